// round 1
// baseline (speedup 1.0000x reference)
#include <cuda_runtime.h>
#include <math.h>

#define NTOK 8192
#define SEQ 2048

// ---------------- scratch (static device globals; no allocation) ----------------
__device__ float g_qkv_buf[NTOK * 768];
__device__ float t_qkv_buf[NTOK * 768];
__device__ float g_attn_buf[NTOK * 256];
__device__ float t_attn_buf[NTOK * 256];
__device__ float comb_buf[NTOK * 512];
__device__ float fush_buf[NTOK * 512];
__device__ float xfused_buf[NTOK * 256];
__device__ float h1_buf[NTOK * 256];
__device__ float ffnh_buf[NTOK * 512];
__device__ float xffn_buf[NTOK * 256];

// ---------------- SGEMM: C[M,N] = A[M,K] @ W[N,K]^T + bias (opt. SiLU) ----------
// BM=BN=128, BK=16, 256 threads, 8x8 per thread. M,N multiples of 128, K of 16.
// C has row stride ldc (allows writing into a slice of the concat buffer).
template <bool SILU>
__global__ void __launch_bounds__(256)
sgemm_kernel(const float* __restrict__ A, const float* __restrict__ W,
             const float* __restrict__ bias, float* __restrict__ C,
             int K, int ldc)
{
    __shared__ float As[16][128];
    __shared__ float Bs[16][128];
    const int tid = threadIdx.x;
    const int bm = blockIdx.y * 128;
    const int bn = blockIdx.x * 128;
    const int tx = (tid & 15) * 8;
    const int ty = (tid >> 4) * 8;

    const int lr = tid >> 2;        // 0..63
    const int lc = (tid & 3) * 4;   // 0,4,8,12

    float acc[8][8];
#pragma unroll
    for (int i = 0; i < 8; i++)
#pragma unroll
        for (int j = 0; j < 8; j++) acc[i][j] = 0.f;

    for (int k0 = 0; k0 < K; k0 += 16) {
#pragma unroll
        for (int r = 0; r < 2; r++) {
            const int m = lr + r * 64;
            float4 av = *reinterpret_cast<const float4*>(A + (size_t)(bm + m) * K + k0 + lc);
            As[lc + 0][m] = av.x; As[lc + 1][m] = av.y;
            As[lc + 2][m] = av.z; As[lc + 3][m] = av.w;
            float4 wv = *reinterpret_cast<const float4*>(W + (size_t)(bn + m) * K + k0 + lc);
            Bs[lc + 0][m] = wv.x; Bs[lc + 1][m] = wv.y;
            Bs[lc + 2][m] = wv.z; Bs[lc + 3][m] = wv.w;
        }
        __syncthreads();
#pragma unroll
        for (int k = 0; k < 16; k++) {
            float a[8], b[8];
#pragma unroll
            for (int i = 0; i < 8; i++) a[i] = As[k][ty + i];
#pragma unroll
            for (int j = 0; j < 8; j++) b[j] = Bs[k][tx + j];
#pragma unroll
            for (int i = 0; i < 8; i++)
#pragma unroll
                for (int j = 0; j < 8; j++) acc[i][j] += a[i] * b[j];
        }
        __syncthreads();
    }

#pragma unroll
    for (int i = 0; i < 8; i++) {
        const int row = bm + ty + i;
#pragma unroll
        for (int j4 = 0; j4 < 8; j4 += 4) {
            float4 v4;
            float* pv = &v4.x;
#pragma unroll
            for (int j = 0; j < 4; j++) {
                float v = acc[i][j4 + j] + bias[bn + tx + j4 + j];
                if (SILU) v = v / (1.f + __expf(-v));
                pv[j] = v;
            }
            *reinterpret_cast<float4*>(C + (size_t)row * ldc + bn + tx + j4) = v4;
        }
    }
}

// ---------------- global attention: 8 heads, hd=32, full softmax ----------------
// qkv layout per token: [q(256) | k(256) | v(256)]; head h = cols h*32..h*32+31.
// grid (S/128, H, B), 128 threads, 1 query per thread, online softmax over
// 32-key smem tiles (scores processed in chunks of 16 to bound registers).
__global__ void __launch_bounds__(128)
global_attn_kernel(const float* __restrict__ qkv, float* __restrict__ out)
{
    __shared__ float ks[32][32];
    __shared__ float vs[32][32];
    const int tid = threadIdx.x;
    const int qi = blockIdx.x * 128 + tid;
    const int h = blockIdx.y;
    const int b = blockIdx.z;

    const float scale = 0.17677669529663687f;  // 1/sqrt(32)
    float q[32];
    const float* qp = qkv + (size_t)(b * SEQ + qi) * 768 + h * 32;
#pragma unroll
    for (int d = 0; d < 32; d += 4) {
        float4 t = *reinterpret_cast<const float4*>(qp + d);
        q[d] = t.x * scale; q[d + 1] = t.y * scale;
        q[d + 2] = t.z * scale; q[d + 3] = t.w * scale;
    }

    float m = -1e30f, l = 0.f;
    float acc[32];
#pragma unroll
    for (int d = 0; d < 32; d++) acc[d] = 0.f;

    const int r0 = tid >> 3;        // 0..15
    const int c0 = (tid & 7) * 4;   // 0..28

    for (int kt = 0; kt < SEQ; kt += 32) {
#pragma unroll
        for (int r = 0; r < 2; r++) {
            const int row = r0 + r * 16;
            const float* kp = qkv + (size_t)(b * SEQ + kt + row) * 768 + 256 + h * 32 + c0;
            *reinterpret_cast<float4*>(&ks[row][c0]) = *reinterpret_cast<const float4*>(kp);
            *reinterpret_cast<float4*>(&vs[row][c0]) = *reinterpret_cast<const float4*>(kp + 256);
        }
        __syncthreads();

#pragma unroll
        for (int c = 0; c < 2; c++) {
            float s[16];
#pragma unroll
            for (int j = 0; j < 16; j++) {
                const int jj = c * 16 + j;
                float sum = 0.f;
#pragma unroll
                for (int d = 0; d < 32; d++) sum += q[d] * ks[jj][d];
                s[j] = sum;
            }
            float tmax = s[0];
#pragma unroll
            for (int j = 1; j < 16; j++) tmax = fmaxf(tmax, s[j]);
            const float m_new = fmaxf(m, tmax);
            const float corr = __expf(m - m_new);
            l *= corr;
#pragma unroll
            for (int d = 0; d < 32; d++) acc[d] *= corr;
#pragma unroll
            for (int j = 0; j < 16; j++) {
                const int jj = c * 16 + j;
                const float p = __expf(s[j] - m_new);
                l += p;
#pragma unroll
                for (int d = 0; d < 32; d++) acc[d] += p * vs[jj][d];
            }
            m = m_new;
        }
        __syncthreads();
    }

    const float inv = 1.f / l;
    float* op = out + (size_t)(b * SEQ + qi) * 256 + h * 32;
#pragma unroll
    for (int d = 0; d < 32; d += 4) {
        float4 t;
        t.x = acc[d] * inv; t.y = acc[d + 1] * inv;
        t.z = acc[d + 2] * inv; t.w = acc[d + 3] * inv;
        *reinterpret_cast<float4*>(op + d) = t;
    }
}

// ---------------- local attention: 4 heads, hd=64, window 5 --------------------
// one block per token, one warp per head; lane covers dims (lane, lane+32).
__global__ void __launch_bounds__(128)
local_attn_kernel(const float* __restrict__ qkv, float* __restrict__ out)
{
    const int n = blockIdx.x;
    const int b = n / SEQ;
    const int s = n % SEQ;
    const int h = threadIdx.x >> 5;
    const int lane = threadIdx.x & 31;

    const size_t qb = (size_t)n * 768 + h * 64;
    const float q0 = qkv[qb + lane];
    const float q1 = qkv[qb + 32 + lane];

    float sc[5];
#pragma unroll
    for (int wo = 0; wo < 5; wo++) {
        const int j = s + wo - 2;
        if (j >= 0 && j < SEQ) {
            const size_t kb = (size_t)(b * SEQ + j) * 768 + 256 + h * 64;
            float part = q0 * qkv[kb + lane] + q1 * qkv[kb + 32 + lane];
#pragma unroll
            for (int o = 16; o > 0; o >>= 1) part += __shfl_xor_sync(0xffffffffu, part, o);
            sc[wo] = part * 0.125f;  // 1/sqrt(64)
        } else {
            sc[wo] = -1e30f;
        }
    }
    float mx = sc[0];
#pragma unroll
    for (int wo = 1; wo < 5; wo++) mx = fmaxf(mx, sc[wo]);
    float p[5], lsum = 0.f;
#pragma unroll
    for (int wo = 0; wo < 5; wo++) {
        p[wo] = (sc[wo] > -1e29f) ? __expf(sc[wo] - mx) : 0.f;
        lsum += p[wo];
    }
    float o0 = 0.f, o1 = 0.f;
#pragma unroll
    for (int wo = 0; wo < 5; wo++) {
        const int j = s + wo - 2;
        if (j >= 0 && j < SEQ) {
            const size_t vb = (size_t)(b * SEQ + j) * 768 + 512 + h * 64;
            o0 += p[wo] * qkv[vb + lane];
            o1 += p[wo] * qkv[vb + 32 + lane];
        }
    }
    const float inv = 1.f / lsum;
    out[(size_t)n * 256 + h * 64 + lane] = o0 * inv;
    out[(size_t)n * 256 + h * 64 + 32 + lane] = o1 * inv;
}

// ---------------- residual add + LayerNorm --------------------------------------
__global__ void __launch_bounds__(256)
add_ln_kernel(const float* __restrict__ x, const float* __restrict__ dx,
              const float* __restrict__ g, const float* __restrict__ bb,
              float* __restrict__ out)
{
    const int n = blockIdx.x;
    const int d = threadIdx.x;
    const float v = x[(size_t)n * 256 + d] + dx[(size_t)n * 256 + d];
    float s1 = v, s2 = v * v;
#pragma unroll
    for (int o = 16; o > 0; o >>= 1) {
        s1 += __shfl_xor_sync(0xffffffffu, s1, o);
        s2 += __shfl_xor_sync(0xffffffffu, s2, o);
    }
    __shared__ float r1[8], r2[8];
    const int wid = d >> 5, lane = d & 31;
    if (lane == 0) { r1[wid] = s1; r2[wid] = s2; }
    __syncthreads();
    if (wid == 0) {
        float a = (lane < 8) ? r1[lane] : 0.f;
        float c = (lane < 8) ? r2[lane] : 0.f;
#pragma unroll
        for (int o = 4; o > 0; o >>= 1) {
            a += __shfl_xor_sync(0xffffffffu, a, o);
            c += __shfl_xor_sync(0xffffffffu, c, o);
        }
        if (lane == 0) { r1[0] = a; r2[0] = c; }
    }
    __syncthreads();
    const float mu = r1[0] * (1.f / 256.f);
    const float var = r2[0] * (1.f / 256.f) - mu * mu;
    out[(size_t)n * 256 + d] = (v - mu) * rsqrtf(var + 1e-5f) * g[d] + bb[d];
}

// ---------------- launch ---------------------------------------------------------
extern "C" void kernel_launch(void* const* d_in, const int* in_sizes, int n_in,
                              void* d_out, int out_size)
{
    const float* x      = (const float*)d_in[0];
    const float* g_in_w = (const float*)d_in[1];
    const float* g_in_b = (const float*)d_in[2];
    const float* g_out_w= (const float*)d_in[3];
    const float* g_out_b= (const float*)d_in[4];
    const float* t_in_w = (const float*)d_in[5];
    const float* t_in_b = (const float*)d_in[6];
    const float* t_out_w= (const float*)d_in[7];
    const float* t_out_b= (const float*)d_in[8];
    const float* fus_w1 = (const float*)d_in[9];
    const float* fus_b1 = (const float*)d_in[10];
    const float* fus_w2 = (const float*)d_in[11];
    const float* fus_b2 = (const float*)d_in[12];
    const float* ffn_w1 = (const float*)d_in[13];
    const float* ffn_b1 = (const float*)d_in[14];
    const float* ffn_w2 = (const float*)d_in[15];
    const float* ffn_b2 = (const float*)d_in[16];
    const float* gn_g   = (const float*)d_in[17];
    const float* gn_b   = (const float*)d_in[18];
    const float* fn_g   = (const float*)d_in[19];
    const float* fn_b   = (const float*)d_in[20];

    float *gqkv, *tqkv, *gat, *tat, *comb, *fush, *xfu, *h1, *ffh, *xff;
    cudaGetSymbolAddress((void**)&gqkv, g_qkv_buf);
    cudaGetSymbolAddress((void**)&tqkv, t_qkv_buf);
    cudaGetSymbolAddress((void**)&gat,  g_attn_buf);
    cudaGetSymbolAddress((void**)&tat,  t_attn_buf);
    cudaGetSymbolAddress((void**)&comb, comb_buf);
    cudaGetSymbolAddress((void**)&fush, fush_buf);
    cudaGetSymbolAddress((void**)&xfu,  xfused_buf);
    cudaGetSymbolAddress((void**)&h1,   h1_buf);
    cudaGetSymbolAddress((void**)&ffh,  ffnh_buf);
    cudaGetSymbolAddress((void**)&xff,  xffn_buf);

    // QKV projections for both branches
    sgemm_kernel<false><<<dim3(6, 64), 256>>>(x, g_in_w, g_in_b, gqkv, 256, 768);
    sgemm_kernel<false><<<dim3(6, 64), 256>>>(x, t_in_w, t_in_b, tqkv, 256, 768);

    // attention
    global_attn_kernel<<<dim3(16, 8, 4), 128>>>(gqkv, gat);
    local_attn_kernel<<<NTOK, 128>>>(tqkv, tat);

    // output projections, written directly into concat buffer [global | local]
    sgemm_kernel<false><<<dim3(2, 64), 256>>>(gat, g_out_w, g_out_b, comb,       256, 512);
    sgemm_kernel<false><<<dim3(2, 64), 256>>>(tat, t_out_w, t_out_b, comb + 256, 256, 512);

    // fusion MLP
    sgemm_kernel<true ><<<dim3(4, 64), 256>>>(comb, fus_w1, fus_b1, fush, 512, 512);
    sgemm_kernel<false><<<dim3(2, 64), 256>>>(fush, fus_w2, fus_b2, xfu,  512, 256);

    // residual + LN
    add_ln_kernel<<<NTOK, 256>>>(x, xfu, gn_g, gn_b, h1);

    // FFN
    sgemm_kernel<true ><<<dim3(4, 64), 256>>>(h1,  ffn_w1, ffn_b1, ffh, 256, 512);
    sgemm_kernel<false><<<dim3(2, 64), 256>>>(ffh, ffn_w2, ffn_b2, xff, 512, 256);

    // final residual + LN -> output
    add_ln_kernel<<<NTOK, 256>>>(h1, xff, fn_g, fn_b, (float*)d_out);
}

// round 4
// speedup vs baseline: 1.3375x; 1.3375x over previous
#include <cuda_runtime.h>
#include <math.h>

#define NTOK 8192
#define SEQ 2048

// ---------------- scratch (static device globals; no allocation) ----------------
__device__ float g_qkv_buf[NTOK * 768];
__device__ float t_qkv_buf[NTOK * 768];
__device__ float g_attn_buf[NTOK * 256];
__device__ float t_attn_buf[NTOK * 256];
__device__ float comb_buf[NTOK * 512];
__device__ float fush_buf[NTOK * 512];
__device__ float xfused_buf[NTOK * 256];
__device__ float h1_buf[NTOK * 256];
__device__ float ffnh_buf[NTOK * 512];
__device__ float xffn_buf[NTOK * 256];

// ---------------- tf32 helpers ---------------------------------------------------
__device__ __forceinline__ unsigned f2tf32(float x) {
    unsigned r;
    asm("cvt.rna.tf32.f32 %0, %1;" : "=r"(r) : "f"(x));
    return r;
}

__device__ __forceinline__ void mma_tf32(float* d, const unsigned* a, const unsigned* b,
                                         const float* c) {
    asm("mma.sync.aligned.m16n8k8.row.col.f32.tf32.tf32.f32 "
        "{%0,%1,%2,%3},{%4,%5,%6,%7},{%8,%9},{%10,%11,%12,%13};"
        : "=f"(d[0]), "=f"(d[1]), "=f"(d[2]), "=f"(d[3])
        : "r"(a[0]), "r"(a[1]), "r"(a[2]), "r"(a[3]),
          "r"(b[0]), "r"(b[1]),
          "f"(c[0]), "f"(c[1]), "f"(c[2]), "f"(c[3]));
}

// ---------------- TF32 tensor-core GEMM: C[M,N] = A[M,K] @ W[N,K]^T + bias -------
// BM=BN=128, BK=32, 256 threads (8 warps), warp tile 32x64 via m16n8k8 tf32 mma.
// M,N multiples of 128; K multiple of 32. C row stride ldc (concat slicing).
#define SMS 36  // smem row stride (floats); 32+4 keeps float4 alignment, kills conflicts
template <bool SILU>
__global__ void __launch_bounds__(256)
tgemm_kernel(const float* __restrict__ A, const float* __restrict__ W,
             const float* __restrict__ bias, float* __restrict__ C,
             int K, int ldc)
{
    __shared__ unsigned As[128 * SMS];
    __shared__ unsigned Bs[128 * SMS];

    const int tid = threadIdx.x;
    const int bm = blockIdx.y * 128;
    const int bn = blockIdx.x * 128;

    const int warp = tid >> 5;
    const int lane = tid & 31;
    const int wm = (warp & 3) * 32;   // warp m offset within block tile
    const int wn = (warp >> 2) * 64;  // warp n offset within block tile
    const int g = lane >> 2;          // group id (row within fragment)
    const int t = lane & 3;           // thread in group (col/k within fragment)

    // loader mapping: each thread loads 16 floats of A and 16 of B per BK tile
    const int lrow = tid >> 1;            // 0..127
    const int lcol = (tid & 1) * 16;      // 0 or 16

    float acc[2][8][4];
#pragma unroll
    for (int mt = 0; mt < 2; mt++)
#pragma unroll
        for (int nt = 0; nt < 8; nt++)
#pragma unroll
            for (int r = 0; r < 4; r++) acc[mt][nt][r] = 0.f;

    for (int k0 = 0; k0 < K; k0 += 32) {
        // load A[128x32] and W[128x32] tiles, converting to tf32
#pragma unroll
        for (int i = 0; i < 4; i++) {
            const int c = lcol + i * 4;
            float4 av = *reinterpret_cast<const float4*>(A + (size_t)(bm + lrow) * K + k0 + c);
            unsigned* as = &As[lrow * SMS + c];
            as[0] = f2tf32(av.x); as[1] = f2tf32(av.y);
            as[2] = f2tf32(av.z); as[3] = f2tf32(av.w);
            float4 wv = *reinterpret_cast<const float4*>(W + (size_t)(bn + lrow) * K + k0 + c);
            unsigned* bs = &Bs[lrow * SMS + c];
            bs[0] = f2tf32(wv.x); bs[1] = f2tf32(wv.y);
            bs[2] = f2tf32(wv.z); bs[3] = f2tf32(wv.w);
        }
        __syncthreads();

#pragma unroll
        for (int ks = 0; ks < 4; ks++) {
            const int kk = ks * 8;
            unsigned af[2][4];
#pragma unroll
            for (int mt = 0; mt < 2; mt++) {
                const int r0 = wm + mt * 16 + g;
                af[mt][0] = As[(r0    ) * SMS + kk + t];
                af[mt][1] = As[(r0 + 8) * SMS + kk + t];
                af[mt][2] = As[(r0    ) * SMS + kk + t + 4];
                af[mt][3] = As[(r0 + 8) * SMS + kk + t + 4];
            }
            unsigned bf[8][2];
#pragma unroll
            for (int nt = 0; nt < 8; nt++) {
                const int n0 = wn + nt * 8 + g;
                bf[nt][0] = Bs[n0 * SMS + kk + t];
                bf[nt][1] = Bs[n0 * SMS + kk + t + 4];
            }
#pragma unroll
            for (int mt = 0; mt < 2; mt++)
#pragma unroll
                for (int nt = 0; nt < 8; nt++)
                    mma_tf32(acc[mt][nt], af[mt], bf[nt], acc[mt][nt]);
        }
        __syncthreads();
    }

    // epilogue: bias (+SiLU), float2 stores
#pragma unroll
    for (int mt = 0; mt < 2; mt++) {
#pragma unroll
        for (int nt = 0; nt < 8; nt++) {
            const int col = bn + wn + nt * 8 + 2 * t;
            const float b0 = bias[col], b1 = bias[col + 1];
#pragma unroll
            for (int h = 0; h < 2; h++) {
                const int row = bm + wm + mt * 16 + g + h * 8;
                float v0 = acc[mt][nt][2 * h] + b0;
                float v1 = acc[mt][nt][2 * h + 1] + b1;
                if (SILU) {
                    v0 = v0 / (1.f + __expf(-v0));
                    v1 = v1 / (1.f + __expf(-v1));
                }
                float2 o; o.x = v0; o.y = v1;
                *reinterpret_cast<float2*>(C + (size_t)row * ldc + col) = o;
            }
        }
    }
}

// ---------------- global attention: 8 heads, hd=32, full softmax ----------------
__global__ void __launch_bounds__(128)
global_attn_kernel(const float* __restrict__ qkv, float* __restrict__ out)
{
    __shared__ float ks[32][32];
    __shared__ float vs[32][32];
    const int tid = threadIdx.x;
    const int qi = blockIdx.x * 128 + tid;
    const int h = blockIdx.y;
    const int b = blockIdx.z;

    const float scale = 0.17677669529663687f;  // 1/sqrt(32)
    float q[32];
    const float* qp = qkv + (size_t)(b * SEQ + qi) * 768 + h * 32;
#pragma unroll
    for (int d = 0; d < 32; d += 4) {
        float4 t = *reinterpret_cast<const float4*>(qp + d);
        q[d] = t.x * scale; q[d + 1] = t.y * scale;
        q[d + 2] = t.z * scale; q[d + 3] = t.w * scale;
    }

    float m = -1e30f, l = 0.f;
    float acc[32];
#pragma unroll
    for (int d = 0; d < 32; d++) acc[d] = 0.f;

    const int r0 = tid >> 3;
    const int c0 = (tid & 7) * 4;

    for (int kt = 0; kt < SEQ; kt += 32) {
#pragma unroll
        for (int r = 0; r < 2; r++) {
            const int row = r0 + r * 16;
            const float* kp = qkv + (size_t)(b * SEQ + kt + row) * 768 + 256 + h * 32 + c0;
            *reinterpret_cast<float4*>(&ks[row][c0]) = *reinterpret_cast<const float4*>(kp);
            *reinterpret_cast<float4*>(&vs[row][c0]) = *reinterpret_cast<const float4*>(kp + 256);
        }
        __syncthreads();

#pragma unroll
        for (int c = 0; c < 2; c++) {
            float s[16];
#pragma unroll
            for (int j = 0; j < 16; j++) {
                const int jj = c * 16 + j;
                float sum = 0.f;
#pragma unroll
                for (int d = 0; d < 32; d++) sum += q[d] * ks[jj][d];
                s[j] = sum;
            }
            float tmax = s[0];
#pragma unroll
            for (int j = 1; j < 16; j++) tmax = fmaxf(tmax, s[j]);
            const float m_new = fmaxf(m, tmax);
            const float corr = __expf(m - m_new);
            l *= corr;
#pragma unroll
            for (int d = 0; d < 32; d++) acc[d] *= corr;
#pragma unroll
            for (int j = 0; j < 16; j++) {
                const int jj = c * 16 + j;
                const float p = __expf(s[j] - m_new);
                l += p;
#pragma unroll
                for (int d = 0; d < 32; d++) acc[d] += p * vs[jj][d];
            }
            m = m_new;
        }
        __syncthreads();
    }

    const float inv = 1.f / l;
    float* op = out + (size_t)(b * SEQ + qi) * 256 + h * 32;
#pragma unroll
    for (int d = 0; d < 32; d += 4) {
        float4 t;
        t.x = acc[d] * inv; t.y = acc[d + 1] * inv;
        t.z = acc[d + 2] * inv; t.w = acc[d + 3] * inv;
        *reinterpret_cast<float4*>(op + d) = t;
    }
}

// ---------------- local attention: 4 heads, hd=64, window 5 --------------------
__global__ void __launch_bounds__(128)
local_attn_kernel(const float* __restrict__ qkv, float* __restrict__ out)
{
    const int n = blockIdx.x;
    const int b = n / SEQ;
    const int s = n % SEQ;
    const int h = threadIdx.x >> 5;
    const int lane = threadIdx.x & 31;

    const size_t qb = (size_t)n * 768 + h * 64;
    const float q0 = qkv[qb + lane];
    const float q1 = qkv[qb + 32 + lane];

    float sc[5];
#pragma unroll
    for (int wo = 0; wo < 5; wo++) {
        const int j = s + wo - 2;
        if (j >= 0 && j < SEQ) {
            const size_t kb = (size_t)(b * SEQ + j) * 768 + 256 + h * 64;
            float part = q0 * qkv[kb + lane] + q1 * qkv[kb + 32 + lane];
#pragma unroll
            for (int o = 16; o > 0; o >>= 1) part += __shfl_xor_sync(0xffffffffu, part, o);
            sc[wo] = part * 0.125f;
        } else {
            sc[wo] = -1e30f;
        }
    }
    float mx = sc[0];
#pragma unroll
    for (int wo = 1; wo < 5; wo++) mx = fmaxf(mx, sc[wo]);
    float p[5], lsum = 0.f;
#pragma unroll
    for (int wo = 0; wo < 5; wo++) {
        p[wo] = (sc[wo] > -1e29f) ? __expf(sc[wo] - mx) : 0.f;
        lsum += p[wo];
    }
    float o0 = 0.f, o1 = 0.f;
#pragma unroll
    for (int wo = 0; wo < 5; wo++) {
        const int j = s + wo - 2;
        if (j >= 0 && j < SEQ) {
            const size_t vb = (size_t)(b * SEQ + j) * 768 + 512 + h * 64;
            o0 += p[wo] * qkv[vb + lane];
            o1 += p[wo] * qkv[vb + 32 + lane];
        }
    }
    const float inv = 1.f / lsum;
    out[(size_t)n * 256 + h * 64 + lane] = o0 * inv;
    out[(size_t)n * 256 + h * 64 + 32 + lane] = o1 * inv;
}

// ---------------- residual add + LayerNorm --------------------------------------
__global__ void __launch_bounds__(256)
add_ln_kernel(const float* __restrict__ x, const float* __restrict__ dx,
              const float* __restrict__ g, const float* __restrict__ bb,
              float* __restrict__ out)
{
    const int n = blockIdx.x;
    const int d = threadIdx.x;
    const float v = x[(size_t)n * 256 + d] + dx[(size_t)n * 256 + d];
    float s1 = v, s2 = v * v;
#pragma unroll
    for (int o = 16; o > 0; o >>= 1) {
        s1 += __shfl_xor_sync(0xffffffffu, s1, o);
        s2 += __shfl_xor_sync(0xffffffffu, s2, o);
    }
    __shared__ float r1[8], r2[8];
    const int wid = d >> 5, lane = d & 31;
    if (lane == 0) { r1[wid] = s1; r2[wid] = s2; }
    __syncthreads();
    if (wid == 0) {
        float a = (lane < 8) ? r1[lane] : 0.f;
        float c = (lane < 8) ? r2[lane] : 0.f;
#pragma unroll
        for (int o = 4; o > 0; o >>= 1) {
            a += __shfl_xor_sync(0xffffffffu, a, o);
            c += __shfl_xor_sync(0xffffffffu, c, o);
        }
        if (lane == 0) { r1[0] = a; r2[0] = c; }
    }
    __syncthreads();
    const float mu = r1[0] * (1.f / 256.f);
    const float var = r2[0] * (1.f / 256.f) - mu * mu;
    out[(size_t)n * 256 + d] = (v - mu) * rsqrtf(var + 1e-5f) * g[d] + bb[d];
}

// ---------------- launch ---------------------------------------------------------
extern "C" void kernel_launch(void* const* d_in, const int* in_sizes, int n_in,
                              void* d_out, int out_size)
{
    const float* x      = (const float*)d_in[0];
    const float* g_in_w = (const float*)d_in[1];
    const float* g_in_b = (const float*)d_in[2];
    const float* g_out_w= (const float*)d_in[3];
    const float* g_out_b= (const float*)d_in[4];
    const float* t_in_w = (const float*)d_in[5];
    const float* t_in_b = (const float*)d_in[6];
    const float* t_out_w= (const float*)d_in[7];
    const float* t_out_b= (const float*)d_in[8];
    const float* fus_w1 = (const float*)d_in[9];
    const float* fus_b1 = (const float*)d_in[10];
    const float* fus_w2 = (const float*)d_in[11];
    const float* fus_b2 = (const float*)d_in[12];
    const float* ffn_w1 = (const float*)d_in[13];
    const float* ffn_b1 = (const float*)d_in[14];
    const float* ffn_w2 = (const float*)d_in[15];
    const float* ffn_b2 = (const float*)d_in[16];
    const float* gn_g   = (const float*)d_in[17];
    const float* gn_b   = (const float*)d_in[18];
    const float* fn_g   = (const float*)d_in[19];
    const float* fn_b   = (const float*)d_in[20];

    float *gqkv, *tqkv, *gat, *tat, *comb, *fush, *xfu, *h1, *ffh, *xff;
    cudaGetSymbolAddress((void**)&gqkv, g_qkv_buf);
    cudaGetSymbolAddress((void**)&tqkv, t_qkv_buf);
    cudaGetSymbolAddress((void**)&gat,  g_attn_buf);
    cudaGetSymbolAddress((void**)&tat,  t_attn_buf);
    cudaGetSymbolAddress((void**)&comb, comb_buf);
    cudaGetSymbolAddress((void**)&fush, fush_buf);
    cudaGetSymbolAddress((void**)&xfu,  xfused_buf);
    cudaGetSymbolAddress((void**)&h1,   h1_buf);
    cudaGetSymbolAddress((void**)&ffh,  ffnh_buf);
    cudaGetSymbolAddress((void**)&xff,  xffn_buf);

    // QKV projections for both branches (tf32 tensor cores)
    tgemm_kernel<false><<<dim3(6, 64), 256>>>(x, g_in_w, g_in_b, gqkv, 256, 768);
    tgemm_kernel<false><<<dim3(6, 64), 256>>>(x, t_in_w, t_in_b, tqkv, 256, 768);

    // attention
    global_attn_kernel<<<dim3(16, 8, 4), 128>>>(gqkv, gat);
    local_attn_kernel<<<NTOK, 128>>>(tqkv, tat);

    // output projections, written directly into concat buffer [global | local]
    tgemm_kernel<false><<<dim3(2, 64), 256>>>(gat, g_out_w, g_out_b, comb,       256, 512);
    tgemm_kernel<false><<<dim3(2, 64), 256>>>(tat, t_out_w, t_out_b, comb + 256, 256, 512);

    // fusion MLP
    tgemm_kernel<true ><<<dim3(4, 64), 256>>>(comb, fus_w1, fus_b1, fush, 512, 512);
    tgemm_kernel<false><<<dim3(2, 64), 256>>>(fush, fus_w2, fus_b2, xfu,  512, 256);

    // residual + LN
    add_ln_kernel<<<NTOK, 256>>>(x, xfu, gn_g, gn_b, h1);

    // FFN
    tgemm_kernel<true ><<<dim3(4, 64), 256>>>(h1,  ffn_w1, ffn_b1, ffh, 256, 512);
    tgemm_kernel<false><<<dim3(2, 64), 256>>>(ffh, ffn_w2, ffn_b2, xff, 512, 256);

    // final residual + LN -> output
    add_ln_kernel<<<NTOK, 256>>>(h1, xff, fn_g, fn_b, (float*)d_out);
}

// round 8
// speedup vs baseline: 2.6484x; 1.9800x over previous
#include <cuda_runtime.h>
#include <math.h>

#define NTOK 8192
#define SEQ 2048

// ---------------- scratch (static device globals; no allocation) ----------------
__device__ float g_qkv_buf[NTOK * 768];
__device__ float t_qkv_buf[NTOK * 768];
__device__ float g_attn_buf[NTOK * 256];
__device__ float t_attn_buf[NTOK * 256];
__device__ float comb_buf[NTOK * 512];
__device__ float fush_buf[NTOK * 512];
__device__ float xfused_buf[NTOK * 256];
__device__ float h1_buf[NTOK * 256];
__device__ float ffnh_buf[NTOK * 512];
__device__ float xffn_buf[NTOK * 256];

// ---------------- tf32 helpers ---------------------------------------------------
__device__ __forceinline__ unsigned f2tf32(float x) {
    unsigned r;
    asm("cvt.rna.tf32.f32 %0, %1;" : "=r"(r) : "f"(x));
    return r;
}

__device__ __forceinline__ void mma_tf32(float* d, const unsigned* a, const unsigned* b,
                                         const float* c) {
    asm("mma.sync.aligned.m16n8k8.row.col.f32.tf32.tf32.f32 "
        "{%0,%1,%2,%3},{%4,%5,%6,%7},{%8,%9},{%10,%11,%12,%13};"
        : "=f"(d[0]), "=f"(d[1]), "=f"(d[2]), "=f"(d[3])
        : "r"(a[0]), "r"(a[1]), "r"(a[2]), "r"(a[3]),
          "r"(b[0]), "r"(b[1]),
          "f"(c[0]), "f"(c[1]), "f"(c[2]), "f"(c[3]));
}

// ---------------- TF32 tensor-core GEMM: C[M,N] = A[M,K] @ W[N,K]^T + bias -------
#define SMS 36
template <bool SILU>
__global__ void __launch_bounds__(256)
tgemm_kernel(const float* __restrict__ A, const float* __restrict__ W,
             const float* __restrict__ bias, float* __restrict__ C,
             int K, int ldc)
{
    __shared__ unsigned As[128 * SMS];
    __shared__ unsigned Bs[128 * SMS];

    const int tid = threadIdx.x;
    const int bm = blockIdx.y * 128;
    const int bn = blockIdx.x * 128;

    const int warp = tid >> 5;
    const int lane = tid & 31;
    const int wm = (warp & 3) * 32;
    const int wn = (warp >> 2) * 64;
    const int g = lane >> 2;
    const int t = lane & 3;

    const int lrow = tid >> 1;
    const int lcol = (tid & 1) * 16;

    float acc[2][8][4];
#pragma unroll
    for (int mt = 0; mt < 2; mt++)
#pragma unroll
        for (int nt = 0; nt < 8; nt++)
#pragma unroll
            for (int r = 0; r < 4; r++) acc[mt][nt][r] = 0.f;

    for (int k0 = 0; k0 < K; k0 += 32) {
#pragma unroll
        for (int i = 0; i < 4; i++) {
            const int c = lcol + i * 4;
            float4 av = *reinterpret_cast<const float4*>(A + (size_t)(bm + lrow) * K + k0 + c);
            unsigned* as = &As[lrow * SMS + c];
            as[0] = f2tf32(av.x); as[1] = f2tf32(av.y);
            as[2] = f2tf32(av.z); as[3] = f2tf32(av.w);
            float4 wv = *reinterpret_cast<const float4*>(W + (size_t)(bn + lrow) * K + k0 + c);
            unsigned* bs = &Bs[lrow * SMS + c];
            bs[0] = f2tf32(wv.x); bs[1] = f2tf32(wv.y);
            bs[2] = f2tf32(wv.z); bs[3] = f2tf32(wv.w);
        }
        __syncthreads();

#pragma unroll
        for (int ks = 0; ks < 4; ks++) {
            const int kk = ks * 8;
            unsigned af[2][4];
#pragma unroll
            for (int mt = 0; mt < 2; mt++) {
                const int r0 = wm + mt * 16 + g;
                af[mt][0] = As[(r0    ) * SMS + kk + t];
                af[mt][1] = As[(r0 + 8) * SMS + kk + t];
                af[mt][2] = As[(r0    ) * SMS + kk + t + 4];
                af[mt][3] = As[(r0 + 8) * SMS + kk + t + 4];
            }
            unsigned bf[8][2];
#pragma unroll
            for (int nt = 0; nt < 8; nt++) {
                const int n0 = wn + nt * 8 + g;
                bf[nt][0] = Bs[n0 * SMS + kk + t];
                bf[nt][1] = Bs[n0 * SMS + kk + t + 4];
            }
#pragma unroll
            for (int mt = 0; mt < 2; mt++)
#pragma unroll
                for (int nt = 0; nt < 8; nt++)
                    mma_tf32(acc[mt][nt], af[mt], bf[nt], acc[mt][nt]);
        }
        __syncthreads();
    }

#pragma unroll
    for (int mt = 0; mt < 2; mt++) {
#pragma unroll
        for (int nt = 0; nt < 8; nt++) {
            const int col = bn + wn + nt * 8 + 2 * t;
            const float b0 = bias[col], b1 = bias[col + 1];
#pragma unroll
            for (int h = 0; h < 2; h++) {
                const int row = bm + wm + mt * 16 + g + h * 8;
                float v0 = acc[mt][nt][2 * h] + b0;
                float v1 = acc[mt][nt][2 * h + 1] + b1;
                if (SILU) {
                    v0 = v0 / (1.f + __expf(-v0));
                    v1 = v1 / (1.f + __expf(-v1));
                }
                float2 o; o.x = v0; o.y = v1;
                *reinterpret_cast<float2*>(C + (size_t)row * ldc + col) = o;
            }
        }
    }
}

// ---------------- flash global attention (tf32 mma): 8 heads, hd=32 -------------
// One block = one (b,h) x 64 queries. 4 warps x 16 query rows. 64-key tiles.
// S = Q@K^T via m16n8k8 (Q persistent A-frags, K smem stride 36 -> conflict-free).
// Online softmax on the mma accumulator layout (quad shfl over t bits).
// P (64x64!) staged via smem stride 68 as A operand of P@V; V smem stride 40 so
// the B-frag read Vs[k][n] hits bank 8t+g (conflict-free).
#define KS_STRIDE 36
#define VS_STRIDE 40
#define PS_STRIDE 68
__global__ void __launch_bounds__(128)
flash_global_attn(const float* __restrict__ qkv, float* __restrict__ out)
{
    __shared__ unsigned Ks[64 * KS_STRIDE];
    __shared__ unsigned Vs[64 * VS_STRIDE];
    __shared__ unsigned Ps[64 * PS_STRIDE];

    const int tid = threadIdx.x;
    const int warp = tid >> 5;
    const int lane = tid & 31;
    const int g = lane >> 2;
    const int t = lane & 3;
    const int h = blockIdx.y;
    const int b = blockIdx.z;
    const int q0 = blockIdx.x * 64;
    const int wq = warp * 16;

    // Q fragments (pre-scaled)
    const float scale = 0.17677669529663687f;  // 1/sqrt(32)
    unsigned qf[4][4];
    {
        const float* base = qkv + (size_t)(b * SEQ) * 768 + h * 32;
        const int r0 = q0 + wq + g;
#pragma unroll
        for (int ks = 0; ks < 4; ks++) {
            const int c = ks * 8 + t;
            qf[ks][0] = f2tf32(base[(size_t)(r0    ) * 768 + c    ] * scale);
            qf[ks][1] = f2tf32(base[(size_t)(r0 + 8) * 768 + c    ] * scale);
            qf[ks][2] = f2tf32(base[(size_t)(r0    ) * 768 + c + 4] * scale);
            qf[ks][3] = f2tf32(base[(size_t)(r0 + 8) * 768 + c + 4] * scale);
        }
    }

    float o[4][4];
#pragma unroll
    for (int nt = 0; nt < 4; nt++)
#pragma unroll
        for (int r = 0; r < 4; r++) o[nt][r] = 0.f;
    float m0 = -1e30f, m1 = -1e30f, l0 = 0.f, l1 = 0.f;

    const int lrow = tid >> 1;          // 0..63
    const int lcol = (tid & 1) * 16;    // 0 or 16

    for (int kt = 0; kt < SEQ; kt += 64) {
        __syncthreads();  // protect previous tile's smem reads
        // cooperative load K,V tile (64 x 32 each) as tf32
#pragma unroll
        for (int i = 0; i < 4; i++) {
            const int c = lcol + i * 4;
            const float* kp = qkv + (size_t)(b * SEQ + kt + lrow) * 768 + 256 + h * 32 + c;
            float4 kv = *reinterpret_cast<const float4*>(kp);
            unsigned* ksp = &Ks[lrow * KS_STRIDE + c];
            ksp[0] = f2tf32(kv.x); ksp[1] = f2tf32(kv.y);
            ksp[2] = f2tf32(kv.z); ksp[3] = f2tf32(kv.w);
            float4 vv = *reinterpret_cast<const float4*>(kp + 256);
            unsigned* vsp = &Vs[lrow * VS_STRIDE + c];
            vsp[0] = f2tf32(vv.x); vsp[1] = f2tf32(vv.y);
            vsp[2] = f2tf32(vv.z); vsp[3] = f2tf32(vv.w);
        }
        __syncthreads();

        // S = Q @ K^T  (per warp: 16 x 64)
        float s[8][4];
#pragma unroll
        for (int nt = 0; nt < 8; nt++)
#pragma unroll
            for (int r = 0; r < 4; r++) s[nt][r] = 0.f;
#pragma unroll
        for (int ks = 0; ks < 4; ks++) {
            const int kk = ks * 8;
#pragma unroll
            for (int nt = 0; nt < 8; nt++) {
                unsigned bf[2];
                const unsigned* kb = &Ks[(nt * 8 + g) * KS_STRIDE + kk + t];
                bf[0] = kb[0];
                bf[1] = kb[4];
                mma_tf32(s[nt], qf[ks], bf, s[nt]);
            }
        }

        // row maxima (row0 = wq+g, row1 = wq+g+8)
        float r0 = s[0][0], r1 = s[0][2];
#pragma unroll
        for (int nt = 0; nt < 8; nt++) {
            r0 = fmaxf(r0, fmaxf(s[nt][0], s[nt][1]));
            r1 = fmaxf(r1, fmaxf(s[nt][2], s[nt][3]));
        }
        r0 = fmaxf(r0, __shfl_xor_sync(0xffffffffu, r0, 1));
        r0 = fmaxf(r0, __shfl_xor_sync(0xffffffffu, r0, 2));
        r1 = fmaxf(r1, __shfl_xor_sync(0xffffffffu, r1, 1));
        r1 = fmaxf(r1, __shfl_xor_sync(0xffffffffu, r1, 2));

        const float m0n = fmaxf(m0, r0);
        const float m1n = fmaxf(m1, r1);
        const float c0 = __expf(m0 - m0n);
        const float c1 = __expf(m1 - m1n);

        // p = exp(s - m), write to Ps, accumulate row sums
        float sum0 = 0.f, sum1 = 0.f;
#pragma unroll
        for (int nt = 0; nt < 8; nt++) {
            const float p00 = __expf(s[nt][0] - m0n);
            const float p01 = __expf(s[nt][1] - m0n);
            const float p10 = __expf(s[nt][2] - m1n);
            const float p11 = __expf(s[nt][3] - m1n);
            sum0 += p00 + p01;
            sum1 += p10 + p11;
            const int col = nt * 8 + 2 * t;
            unsigned* pr0 = &Ps[(wq + g    ) * PS_STRIDE + col];
            unsigned* pr1 = &Ps[(wq + g + 8) * PS_STRIDE + col];
            pr0[0] = f2tf32(p00); pr0[1] = f2tf32(p01);
            pr1[0] = f2tf32(p10); pr1[1] = f2tf32(p11);
        }
        sum0 += __shfl_xor_sync(0xffffffffu, sum0, 1);
        sum0 += __shfl_xor_sync(0xffffffffu, sum0, 2);
        sum1 += __shfl_xor_sync(0xffffffffu, sum1, 1);
        sum1 += __shfl_xor_sync(0xffffffffu, sum1, 2);
        l0 = l0 * c0 + sum0;
        l1 = l1 * c1 + sum1;
        m0 = m0n; m1 = m1n;

        // rescale O accumulators
#pragma unroll
        for (int nt = 0; nt < 4; nt++) {
            o[nt][0] *= c0; o[nt][1] *= c0;
            o[nt][2] *= c1; o[nt][3] *= c1;
        }
        __syncwarp();  // Ps stores visible to own warp's fragment loads

        // O += P @ V  (per warp: 16 x 32, K=64)
#pragma unroll
        for (int ks = 0; ks < 8; ks++) {
            const int kk = ks * 8;
            unsigned af[4];
            const unsigned* pa0 = &Ps[(wq + g    ) * PS_STRIDE + kk + t];
            const unsigned* pa1 = &Ps[(wq + g + 8) * PS_STRIDE + kk + t];
            af[0] = pa0[0]; af[1] = pa1[0];
            af[2] = pa0[4]; af[3] = pa1[4];
#pragma unroll
            for (int nt = 0; nt < 4; nt++) {
                unsigned bf[2];
                bf[0] = Vs[(kk + t    ) * VS_STRIDE + nt * 8 + g];
                bf[1] = Vs[(kk + t + 4) * VS_STRIDE + nt * 8 + g];
                mma_tf32(o[nt], af, bf, o[nt]);
            }
        }
    }

    const float inv0 = 1.f / l0;
    const float inv1 = 1.f / l1;
    float* op = out + (size_t)(b * SEQ) * 256 + h * 32;
    const int row0 = q0 + wq + g;
#pragma unroll
    for (int nt = 0; nt < 4; nt++) {
        const int col = nt * 8 + 2 * t;
        float2 v0; v0.x = o[nt][0] * inv0; v0.y = o[nt][1] * inv0;
        float2 v1; v1.x = o[nt][2] * inv1; v1.y = o[nt][3] * inv1;
        *reinterpret_cast<float2*>(op + (size_t)(row0    ) * 256 + col) = v0;
        *reinterpret_cast<float2*>(op + (size_t)(row0 + 8) * 256 + col) = v1;
    }
}

// ---------------- local attention: 4 heads, hd=64, window 5 --------------------
__global__ void __launch_bounds__(128)
local_attn_kernel(const float* __restrict__ qkv, float* __restrict__ out)
{
    const int n = blockIdx.x;
    const int b = n / SEQ;
    const int s = n % SEQ;
    const int h = threadIdx.x >> 5;
    const int lane = threadIdx.x & 31;

    const size_t qb = (size_t)n * 768 + h * 64;
    const float q0 = qkv[qb + lane];
    const float q1 = qkv[qb + 32 + lane];

    float sc[5];
#pragma unroll
    for (int wo = 0; wo < 5; wo++) {
        const int j = s + wo - 2;
        if (j >= 0 && j < SEQ) {
            const size_t kb = (size_t)(b * SEQ + j) * 768 + 256 + h * 64;
            float part = q0 * qkv[kb + lane] + q1 * qkv[kb + 32 + lane];
#pragma unroll
            for (int o = 16; o > 0; o >>= 1) part += __shfl_xor_sync(0xffffffffu, part, o);
            sc[wo] = part * 0.125f;
        } else {
            sc[wo] = -1e30f;
        }
    }
    float mx = sc[0];
#pragma unroll
    for (int wo = 1; wo < 5; wo++) mx = fmaxf(mx, sc[wo]);
    float p[5], lsum = 0.f;
#pragma unroll
    for (int wo = 0; wo < 5; wo++) {
        p[wo] = (sc[wo] > -1e29f) ? __expf(sc[wo] - mx) : 0.f;
        lsum += p[wo];
    }
    float o0 = 0.f, o1 = 0.f;
#pragma unroll
    for (int wo = 0; wo < 5; wo++) {
        const int j = s + wo - 2;
        if (j >= 0 && j < SEQ) {
            const size_t vb = (size_t)(b * SEQ + j) * 768 + 512 + h * 64;
            o0 += p[wo] * qkv[vb + lane];
            o1 += p[wo] * qkv[vb + 32 + lane];
        }
    }
    const float inv = 1.f / lsum;
    out[(size_t)n * 256 + h * 64 + lane] = o0 * inv;
    out[(size_t)n * 256 + h * 64 + 32 + lane] = o1 * inv;
}

// ---------------- residual add + LayerNorm --------------------------------------
__global__ void __launch_bounds__(256)
add_ln_kernel(const float* __restrict__ x, const float* __restrict__ dx,
              const float* __restrict__ g, const float* __restrict__ bb,
              float* __restrict__ out)
{
    const int n = blockIdx.x;
    const int d = threadIdx.x;
    const float v = x[(size_t)n * 256 + d] + dx[(size_t)n * 256 + d];
    float s1 = v, s2 = v * v;
#pragma unroll
    for (int o = 16; o > 0; o >>= 1) {
        s1 += __shfl_xor_sync(0xffffffffu, s1, o);
        s2 += __shfl_xor_sync(0xffffffffu, s2, o);
    }
    __shared__ float r1[8], r2[8];
    const int wid = d >> 5, lane = d & 31;
    if (lane == 0) { r1[wid] = s1; r2[wid] = s2; }
    __syncthreads();
    if (wid == 0) {
        float a = (lane < 8) ? r1[lane] : 0.f;
        float c = (lane < 8) ? r2[lane] : 0.f;
#pragma unroll
        for (int o = 4; o > 0; o >>= 1) {
            a += __shfl_xor_sync(0xffffffffu, a, o);
            c += __shfl_xor_sync(0xffffffffu, c, o);
        }
        if (lane == 0) { r1[0] = a; r2[0] = c; }
    }
    __syncthreads();
    const float mu = r1[0] * (1.f / 256.f);
    const float var = r2[0] * (1.f / 256.f) - mu * mu;
    out[(size_t)n * 256 + d] = (v - mu) * rsqrtf(var + 1e-5f) * g[d] + bb[d];
}

// ---------------- launch ---------------------------------------------------------
extern "C" void kernel_launch(void* const* d_in, const int* in_sizes, int n_in,
                              void* d_out, int out_size)
{
    const float* x      = (const float*)d_in[0];
    const float* g_in_w = (const float*)d_in[1];
    const float* g_in_b = (const float*)d_in[2];
    const float* g_out_w= (const float*)d_in[3];
    const float* g_out_b= (const float*)d_in[4];
    const float* t_in_w = (const float*)d_in[5];
    const float* t_in_b = (const float*)d_in[6];
    const float* t_out_w= (const float*)d_in[7];
    const float* t_out_b= (const float*)d_in[8];
    const float* fus_w1 = (const float*)d_in[9];
    const float* fus_b1 = (const float*)d_in[10];
    const float* fus_w2 = (const float*)d_in[11];
    const float* fus_b2 = (const float*)d_in[12];
    const float* ffn_w1 = (const float*)d_in[13];
    const float* ffn_b1 = (const float*)d_in[14];
    const float* ffn_w2 = (const float*)d_in[15];
    const float* ffn_b2 = (const float*)d_in[16];
    const float* gn_g   = (const float*)d_in[17];
    const float* gn_b   = (const float*)d_in[18];
    const float* fn_g   = (const float*)d_in[19];
    const float* fn_b   = (const float*)d_in[20];

    float *gqkv, *tqkv, *gat, *tat, *comb, *fush, *xfu, *h1, *ffh, *xff;
    cudaGetSymbolAddress((void**)&gqkv, g_qkv_buf);
    cudaGetSymbolAddress((void**)&tqkv, t_qkv_buf);
    cudaGetSymbolAddress((void**)&gat,  g_attn_buf);
    cudaGetSymbolAddress((void**)&tat,  t_attn_buf);
    cudaGetSymbolAddress((void**)&comb, comb_buf);
    cudaGetSymbolAddress((void**)&fush, fush_buf);
    cudaGetSymbolAddress((void**)&xfu,  xfused_buf);
    cudaGetSymbolAddress((void**)&h1,   h1_buf);
    cudaGetSymbolAddress((void**)&ffh,  ffnh_buf);
    cudaGetSymbolAddress((void**)&xff,  xffn_buf);

    // QKV projections for both branches (tf32 tensor cores)
    tgemm_kernel<false><<<dim3(6, 64), 256>>>(x, g_in_w, g_in_b, gqkv, 256, 768);
    tgemm_kernel<false><<<dim3(6, 64), 256>>>(x, t_in_w, t_in_b, tqkv, 256, 768);

    // attention
    flash_global_attn<<<dim3(SEQ / 64, 8, 4), 128>>>(gqkv, gat);
    local_attn_kernel<<<NTOK, 128>>>(tqkv, tat);

    // output projections, written directly into concat buffer [global | local]
    tgemm_kernel<false><<<dim3(2, 64), 256>>>(gat, g_out_w, g_out_b, comb,       256, 512);
    tgemm_kernel<false><<<dim3(2, 64), 256>>>(tat, t_out_w, t_out_b, comb + 256, 256, 512);

    // fusion MLP
    tgemm_kernel<true ><<<dim3(4, 64), 256>>>(comb, fus_w1, fus_b1, fush, 512, 512);
    tgemm_kernel<false><<<dim3(2, 64), 256>>>(fush, fus_w2, fus_b2, xfu,  512, 256);

    // residual + LN
    add_ln_kernel<<<NTOK, 256>>>(x, xfu, gn_g, gn_b, h1);

    // FFN
    tgemm_kernel<true ><<<dim3(4, 64), 256>>>(h1,  ffn_w1, ffn_b1, ffh, 256, 512);
    tgemm_kernel<false><<<dim3(2, 64), 256>>>(ffh, ffn_w2, ffn_b2, xff, 512, 256);

    // final residual + LN -> output
    add_ln_kernel<<<NTOK, 256>>>(h1, xff, fn_g, fn_b, (float*)d_out);
}

// round 9
// speedup vs baseline: 2.8282x; 1.0679x over previous
#include <cuda_runtime.h>
#include <math.h>

#define NTOK 8192
#define SEQ 2048

// ---------------- scratch (static device globals; no allocation) ----------------
__device__ float g_qkv_buf[NTOK * 768];
__device__ float t_qkv_buf[NTOK * 768];
__device__ float g_attn_buf[NTOK * 256];
__device__ float t_attn_buf[NTOK * 256];
__device__ float comb_buf[NTOK * 512];
__device__ float fush_buf[NTOK * 512];
__device__ float xfused_buf[NTOK * 256];
__device__ float h1_buf[NTOK * 256];
__device__ float ffnh_buf[NTOK * 512];
__device__ float xffn_buf[NTOK * 256];

// ---------------- helpers ---------------------------------------------------------
__device__ __forceinline__ unsigned f2tf32(float x) {
    unsigned r;
    asm("cvt.rna.tf32.f32 %0, %1;" : "=r"(r) : "f"(x));
    return r;
}

__device__ __forceinline__ void mma_tf32(float* d, const unsigned* a, const unsigned* b,
                                         const float* c) {
    asm("mma.sync.aligned.m16n8k8.row.col.f32.tf32.tf32.f32 "
        "{%0,%1,%2,%3},{%4,%5,%6,%7},{%8,%9},{%10,%11,%12,%13};"
        : "=f"(d[0]), "=f"(d[1]), "=f"(d[2]), "=f"(d[3])
        : "r"(a[0]), "r"(a[1]), "r"(a[2]), "r"(a[3]),
          "r"(b[0]), "r"(b[1]),
          "f"(c[0]), "f"(c[1]), "f"(c[2]), "f"(c[3]));
}

__device__ __forceinline__ void cp_async16(void* smem, const void* gptr) {
    unsigned saddr = (unsigned)__cvta_generic_to_shared(smem);
    asm volatile("cp.async.ca.shared.global [%0], [%1], 16;" :: "r"(saddr), "l"(gptr));
}
#define CP_COMMIT()  asm volatile("cp.async.commit_group;")
#define CP_WAIT0()   asm volatile("cp.async.wait_group 0;")
#define CP_WAIT1()   asm volatile("cp.async.wait_group 1;")

// ---------------- TF32 dual-source pipelined GEMM --------------------------------
// C[M,N] = A[M,K] @ W[N,K]^T + bias (opt SiLU). BM=BN=128, BK=32, 256 threads,
// 8 warps x (32x64) via m16n8k8. Raw fp32 bits fed to tf32 mma (truncation).
// 2-stage cp.async pipeline. Blocks with blockIdx.x < split use source set 1,
// the rest use set 2 (same K, same ldc) -> sibling GEMMs share one launch.
#define SMS 36
#define GTILE (128 * SMS)
#define GSMEM_BYTES (4 * GTILE * 4)   // 2 stages x (A+B) tiles
template <bool SILU>
__global__ void __launch_bounds__(256)
tgemm2_kernel(const float* __restrict__ A1, const float* __restrict__ W1,
              const float* __restrict__ b1, float* __restrict__ C1,
              const float* __restrict__ A2, const float* __restrict__ W2,
              const float* __restrict__ b2, float* __restrict__ C2,
              int split, int K, int ldc)
{
    extern __shared__ unsigned sm[];
    unsigned* As = sm;              // [2][GTILE]
    unsigned* Bs = sm + 2 * GTILE;  // [2][GTILE]

    const int tid = threadIdx.x;
    const int bm = blockIdx.y * 128;

    const float *A, *W, *bias;
    float* C;
    int bn;
    if ((int)blockIdx.x < split) {
        A = A1; W = W1; bias = b1; C = C1; bn = blockIdx.x * 128;
    } else {
        A = A2; W = W2; bias = b2; C = C2; bn = (blockIdx.x - split) * 128;
    }

    const int warp = tid >> 5;
    const int lane = tid & 31;
    const int wm = (warp & 3) * 32;
    const int wn = (warp >> 2) * 64;
    const int g = lane >> 2;
    const int t = lane & 3;

    const int lrow = tid >> 1;        // 0..127
    const int lcol = (tid & 1) * 16;  // 0 or 16

    const float* aptr = A + (size_t)(bm + lrow) * K + lcol;
    const float* wptr = W + (size_t)(bn + lrow) * K + lcol;
    unsigned* asw = &As[lrow * SMS + lcol];
    unsigned* bsw = &Bs[lrow * SMS + lcol];

    float acc[2][8][4];
#pragma unroll
    for (int mt = 0; mt < 2; mt++)
#pragma unroll
        for (int nt = 0; nt < 8; nt++)
#pragma unroll
            for (int r = 0; r < 4; r++) acc[mt][nt][r] = 0.f;

    const int ntiles = K >> 5;

    // prefetch tile 0 into stage 0
#pragma unroll
    for (int i = 0; i < 4; i++) {
        cp_async16(asw + i * 4, aptr + i * 4);
        cp_async16(bsw + i * 4, wptr + i * 4);
    }
    CP_COMMIT();

    for (int kt = 0; kt < ntiles; kt++) {
        // prefetch next tile into the other stage
        if (kt + 1 < ntiles) {
            const int st = (kt + 1) & 1;
            const int k0 = (kt + 1) << 5;
#pragma unroll
            for (int i = 0; i < 4; i++) {
                cp_async16(asw + st * GTILE + i * 4, aptr + k0 + i * 4);
                cp_async16(bsw + st * GTILE + i * 4, wptr + k0 + i * 4);
            }
            CP_COMMIT();
            CP_WAIT1();   // current tile's group done, next may be in flight
        } else {
            CP_WAIT0();
        }
        __syncthreads();

        const unsigned* as = As + (kt & 1) * GTILE;
        const unsigned* bs = Bs + (kt & 1) * GTILE;
#pragma unroll
        for (int ks = 0; ks < 4; ks++) {
            const int kk = ks * 8;
            unsigned af[2][4];
#pragma unroll
            for (int mt = 0; mt < 2; mt++) {
                const int r0 = wm + mt * 16 + g;
                af[mt][0] = as[(r0    ) * SMS + kk + t];
                af[mt][1] = as[(r0 + 8) * SMS + kk + t];
                af[mt][2] = as[(r0    ) * SMS + kk + t + 4];
                af[mt][3] = as[(r0 + 8) * SMS + kk + t + 4];
            }
            unsigned bf[8][2];
#pragma unroll
            for (int nt = 0; nt < 8; nt++) {
                const int n0 = wn + nt * 8 + g;
                bf[nt][0] = bs[n0 * SMS + kk + t];
                bf[nt][1] = bs[n0 * SMS + kk + t + 4];
            }
#pragma unroll
            for (int mt = 0; mt < 2; mt++)
#pragma unroll
                for (int nt = 0; nt < 8; nt++)
                    mma_tf32(acc[mt][nt], af[mt], bf[nt], acc[mt][nt]);
        }
        __syncthreads();
    }

    // epilogue: bias (+SiLU), float2 stores
#pragma unroll
    for (int mt = 0; mt < 2; mt++) {
#pragma unroll
        for (int nt = 0; nt < 8; nt++) {
            const int col = bn + wn + nt * 8 + 2 * t;
            const float b0 = bias[col], bb1 = bias[col + 1];
#pragma unroll
            for (int h = 0; h < 2; h++) {
                const int row = bm + wm + mt * 16 + g + h * 8;
                float v0 = acc[mt][nt][2 * h] + b0;
                float v1 = acc[mt][nt][2 * h + 1] + bb1;
                if (SILU) {
                    v0 = v0 / (1.f + __expf(-v0));
                    v1 = v1 / (1.f + __expf(-v1));
                }
                float2 o; o.x = v0; o.y = v1;
                *reinterpret_cast<float2*>(C + (size_t)row * ldc + col) = o;
            }
        }
    }
}

// ---------------- flash global attention (tf32 mma): 8 heads, hd=32 -------------
// One block = one (b,h) x 64 queries. 4 warps x 16 query rows. 64-key tiles.
// K/V loaded via cp.async as raw fp32 bits (tf32 truncation). P stored raw.
#define KS_STRIDE 36
#define VS_STRIDE 40
#define PS_STRIDE 68
__global__ void __launch_bounds__(128)
flash_global_attn(const float* __restrict__ qkv, float* __restrict__ out)
{
    __shared__ unsigned Ks[64 * KS_STRIDE];
    __shared__ unsigned Vs[64 * VS_STRIDE];
    __shared__ unsigned Ps[64 * PS_STRIDE];

    const int tid = threadIdx.x;
    const int warp = tid >> 5;
    const int lane = tid & 31;
    const int g = lane >> 2;
    const int t = lane & 3;
    const int h = blockIdx.y;
    const int b = blockIdx.z;
    const int q0 = blockIdx.x * 64;
    const int wq = warp * 16;

    // Q fragments (pre-scaled, rna cvt once)
    const float scale = 0.17677669529663687f;  // 1/sqrt(32)
    unsigned qf[4][4];
    {
        const float* base = qkv + (size_t)(b * SEQ) * 768 + h * 32;
        const int r0 = q0 + wq + g;
#pragma unroll
        for (int ks = 0; ks < 4; ks++) {
            const int c = ks * 8 + t;
            qf[ks][0] = f2tf32(base[(size_t)(r0    ) * 768 + c    ] * scale);
            qf[ks][1] = f2tf32(base[(size_t)(r0 + 8) * 768 + c    ] * scale);
            qf[ks][2] = f2tf32(base[(size_t)(r0    ) * 768 + c + 4] * scale);
            qf[ks][3] = f2tf32(base[(size_t)(r0 + 8) * 768 + c + 4] * scale);
        }
    }

    float o[4][4];
#pragma unroll
    for (int nt = 0; nt < 4; nt++)
#pragma unroll
        for (int r = 0; r < 4; r++) o[nt][r] = 0.f;
    float m0 = -1e30f, m1 = -1e30f, l0 = 0.f, l1 = 0.f;

    const int lrow = tid >> 1;          // 0..63
    const int lcol = (tid & 1) * 16;    // 0 or 16

    for (int kt = 0; kt < SEQ; kt += 64) {
        __syncthreads();  // protect previous tile's smem reads
        // cp.async K,V tile (64 x 32 each), raw fp32 bits
#pragma unroll
        for (int i = 0; i < 4; i++) {
            const int c = lcol + i * 4;
            const float* kp = qkv + (size_t)(b * SEQ + kt + lrow) * 768 + 256 + h * 32 + c;
            cp_async16(&Ks[lrow * KS_STRIDE + c], kp);
            cp_async16(&Vs[lrow * VS_STRIDE + c], kp + 256);
        }
        CP_COMMIT();
        CP_WAIT0();
        __syncthreads();

        // S = Q @ K^T  (per warp: 16 x 64)
        float s[8][4];
#pragma unroll
        for (int nt = 0; nt < 8; nt++)
#pragma unroll
            for (int r = 0; r < 4; r++) s[nt][r] = 0.f;
#pragma unroll
        for (int ks = 0; ks < 4; ks++) {
            const int kk = ks * 8;
#pragma unroll
            for (int nt = 0; nt < 8; nt++) {
                unsigned bf[2];
                const unsigned* kb = &Ks[(nt * 8 + g) * KS_STRIDE + kk + t];
                bf[0] = kb[0];
                bf[1] = kb[4];
                mma_tf32(s[nt], qf[ks], bf, s[nt]);
            }
        }

        // row maxima (row0 = wq+g, row1 = wq+g+8)
        float r0 = s[0][0], r1 = s[0][2];
#pragma unroll
        for (int nt = 0; nt < 8; nt++) {
            r0 = fmaxf(r0, fmaxf(s[nt][0], s[nt][1]));
            r1 = fmaxf(r1, fmaxf(s[nt][2], s[nt][3]));
        }
        r0 = fmaxf(r0, __shfl_xor_sync(0xffffffffu, r0, 1));
        r0 = fmaxf(r0, __shfl_xor_sync(0xffffffffu, r0, 2));
        r1 = fmaxf(r1, __shfl_xor_sync(0xffffffffu, r1, 1));
        r1 = fmaxf(r1, __shfl_xor_sync(0xffffffffu, r1, 2));

        const float m0n = fmaxf(m0, r0);
        const float m1n = fmaxf(m1, r1);
        const float c0 = __expf(m0 - m0n);
        const float c1 = __expf(m1 - m1n);

        // p = exp(s - m), write to Ps (raw bits), accumulate row sums
        float sum0 = 0.f, sum1 = 0.f;
#pragma unroll
        for (int nt = 0; nt < 8; nt++) {
            const float p00 = __expf(s[nt][0] - m0n);
            const float p01 = __expf(s[nt][1] - m0n);
            const float p10 = __expf(s[nt][2] - m1n);
            const float p11 = __expf(s[nt][3] - m1n);
            sum0 += p00 + p01;
            sum1 += p10 + p11;
            const int col = nt * 8 + 2 * t;
            unsigned* pr0 = &Ps[(wq + g    ) * PS_STRIDE + col];
            unsigned* pr1 = &Ps[(wq + g + 8) * PS_STRIDE + col];
            pr0[0] = __float_as_uint(p00); pr0[1] = __float_as_uint(p01);
            pr1[0] = __float_as_uint(p10); pr1[1] = __float_as_uint(p11);
        }
        sum0 += __shfl_xor_sync(0xffffffffu, sum0, 1);
        sum0 += __shfl_xor_sync(0xffffffffu, sum0, 2);
        sum1 += __shfl_xor_sync(0xffffffffu, sum1, 1);
        sum1 += __shfl_xor_sync(0xffffffffu, sum1, 2);
        l0 = l0 * c0 + sum0;
        l1 = l1 * c1 + sum1;
        m0 = m0n; m1 = m1n;

        // rescale O accumulators
#pragma unroll
        for (int nt = 0; nt < 4; nt++) {
            o[nt][0] *= c0; o[nt][1] *= c0;
            o[nt][2] *= c1; o[nt][3] *= c1;
        }
        __syncwarp();  // Ps stores visible to own warp's fragment loads

        // O += P @ V  (per warp: 16 x 32, K=64)
#pragma unroll
        for (int ks = 0; ks < 8; ks++) {
            const int kk = ks * 8;
            unsigned af[4];
            const unsigned* pa0 = &Ps[(wq + g    ) * PS_STRIDE + kk + t];
            const unsigned* pa1 = &Ps[(wq + g + 8) * PS_STRIDE + kk + t];
            af[0] = pa0[0]; af[1] = pa1[0];
            af[2] = pa0[4]; af[3] = pa1[4];
#pragma unroll
            for (int nt = 0; nt < 4; nt++) {
                unsigned bf[2];
                bf[0] = Vs[(kk + t    ) * VS_STRIDE + nt * 8 + g];
                bf[1] = Vs[(kk + t + 4) * VS_STRIDE + nt * 8 + g];
                mma_tf32(o[nt], af, bf, o[nt]);
            }
        }
    }

    const float inv0 = 1.f / l0;
    const float inv1 = 1.f / l1;
    float* op = out + (size_t)(b * SEQ) * 256 + h * 32;
    const int row0 = q0 + wq + g;
#pragma unroll
    for (int nt = 0; nt < 4; nt++) {
        const int col = nt * 8 + 2 * t;
        float2 v0; v0.x = o[nt][0] * inv0; v0.y = o[nt][1] * inv0;
        float2 v1; v1.x = o[nt][2] * inv1; v1.y = o[nt][3] * inv1;
        *reinterpret_cast<float2*>(op + (size_t)(row0    ) * 256 + col) = v0;
        *reinterpret_cast<float2*>(op + (size_t)(row0 + 8) * 256 + col) = v1;
    }
}

// ---------------- local attention: 4 heads, hd=64, window 5 --------------------
__global__ void __launch_bounds__(128)
local_attn_kernel(const float* __restrict__ qkv, float* __restrict__ out)
{
    const int n = blockIdx.x;
    const int b = n / SEQ;
    const int s = n % SEQ;
    const int h = threadIdx.x >> 5;
    const int lane = threadIdx.x & 31;

    const size_t qb = (size_t)n * 768 + h * 64;
    const float q0 = qkv[qb + lane];
    const float q1 = qkv[qb + 32 + lane];

    float sc[5];
#pragma unroll
    for (int wo = 0; wo < 5; wo++) {
        const int j = s + wo - 2;
        if (j >= 0 && j < SEQ) {
            const size_t kb = (size_t)(b * SEQ + j) * 768 + 256 + h * 64;
            float part = q0 * qkv[kb + lane] + q1 * qkv[kb + 32 + lane];
#pragma unroll
            for (int o = 16; o > 0; o >>= 1) part += __shfl_xor_sync(0xffffffffu, part, o);
            sc[wo] = part * 0.125f;
        } else {
            sc[wo] = -1e30f;
        }
    }
    float mx = sc[0];
#pragma unroll
    for (int wo = 1; wo < 5; wo++) mx = fmaxf(mx, sc[wo]);
    float p[5], lsum = 0.f;
#pragma unroll
    for (int wo = 0; wo < 5; wo++) {
        p[wo] = (sc[wo] > -1e29f) ? __expf(sc[wo] - mx) : 0.f;
        lsum += p[wo];
    }
    float o0 = 0.f, o1 = 0.f;
#pragma unroll
    for (int wo = 0; wo < 5; wo++) {
        const int j = s + wo - 2;
        if (j >= 0 && j < SEQ) {
            const size_t vb = (size_t)(b * SEQ + j) * 768 + 512 + h * 64;
            o0 += p[wo] * qkv[vb + lane];
            o1 += p[wo] * qkv[vb + 32 + lane];
        }
    }
    const float inv = 1.f / lsum;
    out[(size_t)n * 256 + h * 64 + lane] = o0 * inv;
    out[(size_t)n * 256 + h * 64 + 32 + lane] = o1 * inv;
}

// ---------------- residual add + LayerNorm --------------------------------------
__global__ void __launch_bounds__(256)
add_ln_kernel(const float* __restrict__ x, const float* __restrict__ dx,
              const float* __restrict__ g, const float* __restrict__ bb,
              float* __restrict__ out)
{
    const int n = blockIdx.x;
    const int d = threadIdx.x;
    const float v = x[(size_t)n * 256 + d] + dx[(size_t)n * 256 + d];
    float s1 = v, s2 = v * v;
#pragma unroll
    for (int o = 16; o > 0; o >>= 1) {
        s1 += __shfl_xor_sync(0xffffffffu, s1, o);
        s2 += __shfl_xor_sync(0xffffffffu, s2, o);
    }
    __shared__ float r1[8], r2[8];
    const int wid = d >> 5, lane = d & 31;
    if (lane == 0) { r1[wid] = s1; r2[wid] = s2; }
    __syncthreads();
    if (wid == 0) {
        float a = (lane < 8) ? r1[lane] : 0.f;
        float c = (lane < 8) ? r2[lane] : 0.f;
#pragma unroll
        for (int o = 4; o > 0; o >>= 1) {
            a += __shfl_xor_sync(0xffffffffu, a, o);
            c += __shfl_xor_sync(0xffffffffu, c, o);
        }
        if (lane == 0) { r1[0] = a; r2[0] = c; }
    }
    __syncthreads();
    const float mu = r1[0] * (1.f / 256.f);
    const float var = r2[0] * (1.f / 256.f) - mu * mu;
    out[(size_t)n * 256 + d] = (v - mu) * rsqrtf(var + 1e-5f) * g[d] + bb[d];
}

// ---------------- launch ---------------------------------------------------------
extern "C" void kernel_launch(void* const* d_in, const int* in_sizes, int n_in,
                              void* d_out, int out_size)
{
    const float* x      = (const float*)d_in[0];
    const float* g_in_w = (const float*)d_in[1];
    const float* g_in_b = (const float*)d_in[2];
    const float* g_out_w= (const float*)d_in[3];
    const float* g_out_b= (const float*)d_in[4];
    const float* t_in_w = (const float*)d_in[5];
    const float* t_in_b = (const float*)d_in[6];
    const float* t_out_w= (const float*)d_in[7];
    const float* t_out_b= (const float*)d_in[8];
    const float* fus_w1 = (const float*)d_in[9];
    const float* fus_b1 = (const float*)d_in[10];
    const float* fus_w2 = (const float*)d_in[11];
    const float* fus_b2 = (const float*)d_in[12];
    const float* ffn_w1 = (const float*)d_in[13];
    const float* ffn_b1 = (const float*)d_in[14];
    const float* ffn_w2 = (const float*)d_in[15];
    const float* ffn_b2 = (const float*)d_in[16];
    const float* gn_g   = (const float*)d_in[17];
    const float* gn_b   = (const float*)d_in[18];
    const float* fn_g   = (const float*)d_in[19];
    const float* fn_b   = (const float*)d_in[20];

    float *gqkv, *tqkv, *gat, *tat, *comb, *fush, *xfu, *h1, *ffh, *xff;
    cudaGetSymbolAddress((void**)&gqkv, g_qkv_buf);
    cudaGetSymbolAddress((void**)&tqkv, t_qkv_buf);
    cudaGetSymbolAddress((void**)&gat,  g_attn_buf);
    cudaGetSymbolAddress((void**)&tat,  t_attn_buf);
    cudaGetSymbolAddress((void**)&comb, comb_buf);
    cudaGetSymbolAddress((void**)&fush, fush_buf);
    cudaGetSymbolAddress((void**)&xfu,  xfused_buf);
    cudaGetSymbolAddress((void**)&h1,   h1_buf);
    cudaGetSymbolAddress((void**)&ffh,  ffnh_buf);
    cudaGetSymbolAddress((void**)&xff,  xffn_buf);

    // allow 72KB dynamic smem for the pipelined GEMM (idempotent)
    cudaFuncSetAttribute(tgemm2_kernel<false>,
                         cudaFuncAttributeMaxDynamicSharedMemorySize, GSMEM_BYTES);
    cudaFuncSetAttribute(tgemm2_kernel<true>,
                         cudaFuncAttributeMaxDynamicSharedMemorySize, GSMEM_BYTES);

    // merged QKV projections (set1: global, set2: local)
    tgemm2_kernel<false><<<dim3(12, 64), 256, GSMEM_BYTES>>>(
        x, g_in_w, g_in_b, gqkv,
        x, t_in_w, t_in_b, tqkv, 6, 256, 768);

    // attention
    flash_global_attn<<<dim3(SEQ / 64, 8, 4), 128>>>(gqkv, gat);
    local_attn_kernel<<<NTOK, 128>>>(tqkv, tat);

    // merged output projections -> concat buffer [global | local]
    tgemm2_kernel<false><<<dim3(4, 64), 256, GSMEM_BYTES>>>(
        gat, g_out_w, g_out_b, comb,
        tat, t_out_w, t_out_b, comb + 256, 2, 256, 512);

    // fusion MLP
    tgemm2_kernel<true ><<<dim3(4, 64), 256, GSMEM_BYTES>>>(
        comb, fus_w1, fus_b1, fush,
        comb, fus_w1, fus_b1, fush, 4, 512, 512);
    tgemm2_kernel<false><<<dim3(2, 64), 256, GSMEM_BYTES>>>(
        fush, fus_w2, fus_b2, xfu,
        fush, fus_w2, fus_b2, xfu, 2, 512, 256);

    // residual + LN
    add_ln_kernel<<<NTOK, 256>>>(x, xfu, gn_g, gn_b, h1);

    // FFN
    tgemm2_kernel<true ><<<dim3(4, 64), 256, GSMEM_BYTES>>>(
        h1, ffn_w1, ffn_b1, ffh,
        h1, ffn_w1, ffn_b1, ffh, 4, 256, 512);
    tgemm2_kernel<false><<<dim3(2, 64), 256, GSMEM_BYTES>>>(
        ffh, ffn_w2, ffn_b2, xff,
        ffh, ffn_w2, ffn_b2, xff, 2, 512, 256);

    // final residual + LN -> output
    add_ln_kernel<<<NTOK, 256>>>(h1, xff, fn_g, fn_b, (float*)d_out);
}

// round 10
// speedup vs baseline: 3.0658x; 1.0840x over previous
#include <cuda_runtime.h>
#include <math.h>

#define NTOK 8192
#define SEQ 2048

// ---------------- scratch (static device globals; no allocation) ----------------
__device__ float g_qkv_buf[NTOK * 768];
__device__ float t_qkv_buf[NTOK * 768];
__device__ float g_attn_buf[NTOK * 256];
__device__ float t_attn_buf[NTOK * 256];
__device__ float comb_buf[NTOK * 512];
__device__ float fush_buf[NTOK * 512];
__device__ float xfused_buf[NTOK * 256];
__device__ float h1_buf[NTOK * 256];
__device__ float ffnh_buf[NTOK * 512];
__device__ float xffn_buf[NTOK * 256];

// ---------------- helpers ---------------------------------------------------------
__device__ __forceinline__ unsigned f2tf32(float x) {
    unsigned r;
    asm("cvt.rna.tf32.f32 %0, %1;" : "=r"(r) : "f"(x));
    return r;
}

__device__ __forceinline__ unsigned pack_bf16(float lo, float hi) {
    unsigned r;
    asm("cvt.rn.bf16x2.f32 %0, %1, %2;" : "=r"(r) : "f"(hi), "f"(lo));
    return r;
}

__device__ __forceinline__ void mma_tf32(float* d, const unsigned* a, const unsigned* b,
                                         const float* c) {
    asm("mma.sync.aligned.m16n8k8.row.col.f32.tf32.tf32.f32 "
        "{%0,%1,%2,%3},{%4,%5,%6,%7},{%8,%9},{%10,%11,%12,%13};"
        : "=f"(d[0]), "=f"(d[1]), "=f"(d[2]), "=f"(d[3])
        : "r"(a[0]), "r"(a[1]), "r"(a[2]), "r"(a[3]),
          "r"(b[0]), "r"(b[1]),
          "f"(c[0]), "f"(c[1]), "f"(c[2]), "f"(c[3]));
}

__device__ __forceinline__ void mma_bf16(float* d, const unsigned* a, const unsigned* b,
                                         const float* c) {
    asm("mma.sync.aligned.m16n8k16.row.col.f32.bf16.bf16.f32 "
        "{%0,%1,%2,%3},{%4,%5,%6,%7},{%8,%9},{%10,%11,%12,%13};"
        : "=f"(d[0]), "=f"(d[1]), "=f"(d[2]), "=f"(d[3])
        : "r"(a[0]), "r"(a[1]), "r"(a[2]), "r"(a[3]),
          "r"(b[0]), "r"(b[1]),
          "f"(c[0]), "f"(c[1]), "f"(c[2]), "f"(c[3]));
}

__device__ __forceinline__ void cp_async16(void* smem, const void* gptr) {
    unsigned saddr = (unsigned)__cvta_generic_to_shared(smem);
    asm volatile("cp.async.ca.shared.global [%0], [%1], 16;" :: "r"(saddr), "l"(gptr));
}
#define CP_COMMIT()  asm volatile("cp.async.commit_group;")
#define CP_WAIT0()   asm volatile("cp.async.wait_group 0;")

// ---------------- BF16 dual-source pipelined GEMM --------------------------------
// C[M,N] = A[M,K] @ W[N,K]^T + bias (opt SiLU). BM=BN=128, BK=32, 256 threads,
// 8 warps x (32x64) via m16n8k16 bf16 (fp32->bf16 rn on smem store).
// smem: 2 stages x (A,B) tiles of 128 rows x 16 u32 (bf16x2), row stride 20 u32
// (conflict-free for the g/t fragment pattern). Register-staged double buffer:
// one __syncthreads per K-tile. Dual-source: blockIdx.x < split -> set 1.
#define SMH 20                 // u32 per smem row (16 data + 4 pad)
#define GT (128 * SMH)         // u32 per tile
#define GSMEM_BYTES (4 * GT * 4)   // 2 stages x (A+B) = 40960 B (< 48KB, no opt-in)
template <bool SILU>
__global__ void __launch_bounds__(256, 2)
tgemm2_kernel(const float* __restrict__ A1, const float* __restrict__ W1,
              const float* __restrict__ b1, float* __restrict__ C1,
              const float* __restrict__ A2, const float* __restrict__ W2,
              const float* __restrict__ b2, float* __restrict__ C2,
              int split, int K, int ldc)
{
    extern __shared__ unsigned sm[];
    unsigned* As = sm;              // [2][GT]
    unsigned* Bs = sm + 2 * GT;     // [2][GT]

    const int tid = threadIdx.x;
    const int bm = blockIdx.y * 128;

    const float *A, *W, *bias;
    float* C;
    int bn;
    if ((int)blockIdx.x < split) {
        A = A1; W = W1; bias = b1; C = C1; bn = blockIdx.x * 128;
    } else {
        A = A2; W = W2; bias = b2; C = C2; bn = (blockIdx.x - split) * 128;
    }

    const int warp = tid >> 5;
    const int lane = tid & 31;
    const int wm = (warp & 3) * 32;
    const int wn = (warp >> 2) * 64;
    const int g = lane >> 2;
    const int t = lane & 3;

    const int lrow = tid >> 1;        // 0..127
    const int lhalf = (tid & 1);      // 0/1 -> fp32 cols 0..15 / 16..31

    const float* aptr = A + (size_t)(bm + lrow) * K + lhalf * 16;
    const float* wptr = W + (size_t)(bn + lrow) * K + lhalf * 16;

    float acc[2][8][4];
#pragma unroll
    for (int mt = 0; mt < 2; mt++)
#pragma unroll
        for (int nt = 0; nt < 8; nt++)
#pragma unroll
            for (int r = 0; r < 4; r++) acc[mt][nt][r] = 0.f;

    unsigned ra[8], rb[8];
    // preload tile 0 into registers (16 fp32 -> 8 bf16x2 each for A and B)
#pragma unroll
    for (int i = 0; i < 4; i++) {
        float4 av = *reinterpret_cast<const float4*>(aptr + i * 4);
        ra[2 * i]     = pack_bf16(av.x, av.y);
        ra[2 * i + 1] = pack_bf16(av.z, av.w);
        float4 wv = *reinterpret_cast<const float4*>(wptr + i * 4);
        rb[2 * i]     = pack_bf16(wv.x, wv.y);
        rb[2 * i + 1] = pack_bf16(wv.z, wv.w);
    }

    const int ntiles = K >> 5;
    for (int kt = 0; kt < ntiles; kt++) {
        const int st = kt & 1;
        unsigned* as = As + st * GT;
        unsigned* bs = Bs + st * GT;

        // store staged tile to smem (2 x uint4 each)
        {
            uint4* da = reinterpret_cast<uint4*>(&as[lrow * SMH + lhalf * 8]);
            da[0] = make_uint4(ra[0], ra[1], ra[2], ra[3]);
            da[1] = make_uint4(ra[4], ra[5], ra[6], ra[7]);
            uint4* db = reinterpret_cast<uint4*>(&bs[lrow * SMH + lhalf * 8]);
            db[0] = make_uint4(rb[0], rb[1], rb[2], rb[3]);
            db[1] = make_uint4(rb[4], rb[5], rb[6], rb[7]);
        }
        __syncthreads();

        // prefetch next tile into registers (overlaps with compute below)
        if (kt + 1 < ntiles) {
            const int k0 = (kt + 1) << 5;
#pragma unroll
            for (int i = 0; i < 4; i++) {
                float4 av = *reinterpret_cast<const float4*>(aptr + k0 + i * 4);
                ra[2 * i]     = pack_bf16(av.x, av.y);
                ra[2 * i + 1] = pack_bf16(av.z, av.w);
                float4 wv = *reinterpret_cast<const float4*>(wptr + k0 + i * 4);
                rb[2 * i]     = pack_bf16(wv.x, wv.y);
                rb[2 * i + 1] = pack_bf16(wv.z, wv.w);
            }
        }

        // compute: two k16 steps over this BK=32 tile
#pragma unroll
        for (int s = 0; s < 2; s++) {
            const int kk = s * 8;   // u32 (bf16-pair) offset within row
            unsigned af[2][4];
#pragma unroll
            for (int mt = 0; mt < 2; mt++) {
                const int r0 = wm + mt * 16 + g;
                af[mt][0] = as[(r0    ) * SMH + kk + t];
                af[mt][1] = as[(r0 + 8) * SMH + kk + t];
                af[mt][2] = as[(r0    ) * SMH + kk + t + 4];
                af[mt][3] = as[(r0 + 8) * SMH + kk + t + 4];
            }
            unsigned bf[8][2];
#pragma unroll
            for (int nt = 0; nt < 8; nt++) {
                const int n0 = wn + nt * 8 + g;
                bf[nt][0] = bs[n0 * SMH + kk + t];
                bf[nt][1] = bs[n0 * SMH + kk + t + 4];
            }
#pragma unroll
            for (int mt = 0; mt < 2; mt++)
#pragma unroll
                for (int nt = 0; nt < 8; nt++)
                    mma_bf16(acc[mt][nt], af[mt], bf[nt], acc[mt][nt]);
        }
        // single sync per iteration: next iteration writes the other stage,
        // and per-warp program order already keeps stage reuse 2 syncs apart.
    }

    // epilogue: bias (+SiLU), float2 stores
#pragma unroll
    for (int mt = 0; mt < 2; mt++) {
#pragma unroll
        for (int nt = 0; nt < 8; nt++) {
            const int col = bn + wn + nt * 8 + 2 * t;
            const float b0 = bias[col], bb1 = bias[col + 1];
#pragma unroll
            for (int h = 0; h < 2; h++) {
                const int row = bm + wm + mt * 16 + g + h * 8;
                float v0 = acc[mt][nt][2 * h] + b0;
                float v1 = acc[mt][nt][2 * h + 1] + bb1;
                if (SILU) {
                    v0 = v0 / (1.f + __expf(-v0));
                    v1 = v1 / (1.f + __expf(-v1));
                }
                float2 o; o.x = v0; o.y = v1;
                *reinterpret_cast<float2*>(C + (size_t)row * ldc + col) = o;
            }
        }
    }
}

// ---------------- flash global attention (tf32 mma): 8 heads, hd=32 -------------
// One block = one (b,h) x 64 queries. 4 warps x 16 query rows. 64-key tiles.
// K/V loaded via cp.async as raw fp32 bits (tf32 truncation). P stored raw.
#define KS_STRIDE 36
#define VS_STRIDE 40
#define PS_STRIDE 68
__global__ void __launch_bounds__(128)
flash_global_attn(const float* __restrict__ qkv, float* __restrict__ out)
{
    __shared__ unsigned Ks[64 * KS_STRIDE];
    __shared__ unsigned Vs[64 * VS_STRIDE];
    __shared__ unsigned Ps[64 * PS_STRIDE];

    const int tid = threadIdx.x;
    const int warp = tid >> 5;
    const int lane = tid & 31;
    const int g = lane >> 2;
    const int t = lane & 3;
    const int h = blockIdx.y;
    const int b = blockIdx.z;
    const int q0 = blockIdx.x * 64;
    const int wq = warp * 16;

    // Q fragments (pre-scaled, rna cvt once)
    const float scale = 0.17677669529663687f;  // 1/sqrt(32)
    unsigned qf[4][4];
    {
        const float* base = qkv + (size_t)(b * SEQ) * 768 + h * 32;
        const int r0 = q0 + wq + g;
#pragma unroll
        for (int ks = 0; ks < 4; ks++) {
            const int c = ks * 8 + t;
            qf[ks][0] = f2tf32(base[(size_t)(r0    ) * 768 + c    ] * scale);
            qf[ks][1] = f2tf32(base[(size_t)(r0 + 8) * 768 + c    ] * scale);
            qf[ks][2] = f2tf32(base[(size_t)(r0    ) * 768 + c + 4] * scale);
            qf[ks][3] = f2tf32(base[(size_t)(r0 + 8) * 768 + c + 4] * scale);
        }
    }

    float o[4][4];
#pragma unroll
    for (int nt = 0; nt < 4; nt++)
#pragma unroll
        for (int r = 0; r < 4; r++) o[nt][r] = 0.f;
    float m0 = -1e30f, m1 = -1e30f, l0 = 0.f, l1 = 0.f;

    const int lrow = tid >> 1;          // 0..63
    const int lcol = (tid & 1) * 16;    // 0 or 16

    for (int kt = 0; kt < SEQ; kt += 64) {
        __syncthreads();  // protect previous tile's smem reads
        // cp.async K,V tile (64 x 32 each), raw fp32 bits
#pragma unroll
        for (int i = 0; i < 4; i++) {
            const int c = lcol + i * 4;
            const float* kp = qkv + (size_t)(b * SEQ + kt + lrow) * 768 + 256 + h * 32 + c;
            cp_async16(&Ks[lrow * KS_STRIDE + c], kp);
            cp_async16(&Vs[lrow * VS_STRIDE + c], kp + 256);
        }
        CP_COMMIT();
        CP_WAIT0();
        __syncthreads();

        // S = Q @ K^T  (per warp: 16 x 64)
        float s[8][4];
#pragma unroll
        for (int nt = 0; nt < 8; nt++)
#pragma unroll
            for (int r = 0; r < 4; r++) s[nt][r] = 0.f;
#pragma unroll
        for (int ks = 0; ks < 4; ks++) {
            const int kk = ks * 8;
#pragma unroll
            for (int nt = 0; nt < 8; nt++) {
                unsigned bf[2];
                const unsigned* kb = &Ks[(nt * 8 + g) * KS_STRIDE + kk + t];
                bf[0] = kb[0];
                bf[1] = kb[4];
                mma_tf32(s[nt], qf[ks], bf, s[nt]);
            }
        }

        // row maxima (row0 = wq+g, row1 = wq+g+8)
        float r0 = s[0][0], r1 = s[0][2];
#pragma unroll
        for (int nt = 0; nt < 8; nt++) {
            r0 = fmaxf(r0, fmaxf(s[nt][0], s[nt][1]));
            r1 = fmaxf(r1, fmaxf(s[nt][2], s[nt][3]));
        }
        r0 = fmaxf(r0, __shfl_xor_sync(0xffffffffu, r0, 1));
        r0 = fmaxf(r0, __shfl_xor_sync(0xffffffffu, r0, 2));
        r1 = fmaxf(r1, __shfl_xor_sync(0xffffffffu, r1, 1));
        r1 = fmaxf(r1, __shfl_xor_sync(0xffffffffu, r1, 2));

        const float m0n = fmaxf(m0, r0);
        const float m1n = fmaxf(m1, r1);
        const float c0 = __expf(m0 - m0n);
        const float c1 = __expf(m1 - m1n);

        // p = exp(s - m), write to Ps (raw bits), accumulate row sums
        float sum0 = 0.f, sum1 = 0.f;
#pragma unroll
        for (int nt = 0; nt < 8; nt++) {
            const float p00 = __expf(s[nt][0] - m0n);
            const float p01 = __expf(s[nt][1] - m0n);
            const float p10 = __expf(s[nt][2] - m1n);
            const float p11 = __expf(s[nt][3] - m1n);
            sum0 += p00 + p01;
            sum1 += p10 + p11;
            const int col = nt * 8 + 2 * t;
            unsigned* pr0 = &Ps[(wq + g    ) * PS_STRIDE + col];
            unsigned* pr1 = &Ps[(wq + g + 8) * PS_STRIDE + col];
            pr0[0] = __float_as_uint(p00); pr0[1] = __float_as_uint(p01);
            pr1[0] = __float_as_uint(p10); pr1[1] = __float_as_uint(p11);
        }
        sum0 += __shfl_xor_sync(0xffffffffu, sum0, 1);
        sum0 += __shfl_xor_sync(0xffffffffu, sum0, 2);
        sum1 += __shfl_xor_sync(0xffffffffu, sum1, 1);
        sum1 += __shfl_xor_sync(0xffffffffu, sum1, 2);
        l0 = l0 * c0 + sum0;
        l1 = l1 * c1 + sum1;
        m0 = m0n; m1 = m1n;

        // rescale O accumulators
#pragma unroll
        for (int nt = 0; nt < 4; nt++) {
            o[nt][0] *= c0; o[nt][1] *= c0;
            o[nt][2] *= c1; o[nt][3] *= c1;
        }
        __syncwarp();  // Ps stores visible to own warp's fragment loads

        // O += P @ V  (per warp: 16 x 32, K=64)
#pragma unroll
        for (int ks = 0; ks < 8; ks++) {
            const int kk = ks * 8;
            unsigned af[4];
            const unsigned* pa0 = &Ps[(wq + g    ) * PS_STRIDE + kk + t];
            const unsigned* pa1 = &Ps[(wq + g + 8) * PS_STRIDE + kk + t];
            af[0] = pa0[0]; af[1] = pa1[0];
            af[2] = pa0[4]; af[3] = pa1[4];
#pragma unroll
            for (int nt = 0; nt < 4; nt++) {
                unsigned bf[2];
                bf[0] = Vs[(kk + t    ) * VS_STRIDE + nt * 8 + g];
                bf[1] = Vs[(kk + t + 4) * VS_STRIDE + nt * 8 + g];
                mma_tf32(o[nt], af, bf, o[nt]);
            }
        }
    }

    const float inv0 = 1.f / l0;
    const float inv1 = 1.f / l1;
    float* op = out + (size_t)(b * SEQ) * 256 + h * 32;
    const int row0 = q0 + wq + g;
#pragma unroll
    for (int nt = 0; nt < 4; nt++) {
        const int col = nt * 8 + 2 * t;
        float2 v0; v0.x = o[nt][0] * inv0; v0.y = o[nt][1] * inv0;
        float2 v1; v1.x = o[nt][2] * inv1; v1.y = o[nt][3] * inv1;
        *reinterpret_cast<float2*>(op + (size_t)(row0    ) * 256 + col) = v0;
        *reinterpret_cast<float2*>(op + (size_t)(row0 + 8) * 256 + col) = v1;
    }
}

// ---------------- local attention: 4 heads, hd=64, window 5 --------------------
__global__ void __launch_bounds__(128)
local_attn_kernel(const float* __restrict__ qkv, float* __restrict__ out)
{
    const int n = blockIdx.x;
    const int b = n / SEQ;
    const int s = n % SEQ;
    const int h = threadIdx.x >> 5;
    const int lane = threadIdx.x & 31;

    const size_t qb = (size_t)n * 768 + h * 64;
    const float q0 = qkv[qb + lane];
    const float q1 = qkv[qb + 32 + lane];

    float sc[5];
#pragma unroll
    for (int wo = 0; wo < 5; wo++) {
        const int j = s + wo - 2;
        if (j >= 0 && j < SEQ) {
            const size_t kb = (size_t)(b * SEQ + j) * 768 + 256 + h * 64;
            float part = q0 * qkv[kb + lane] + q1 * qkv[kb + 32 + lane];
#pragma unroll
            for (int o = 16; o > 0; o >>= 1) part += __shfl_xor_sync(0xffffffffu, part, o);
            sc[wo] = part * 0.125f;
        } else {
            sc[wo] = -1e30f;
        }
    }
    float mx = sc[0];
#pragma unroll
    for (int wo = 1; wo < 5; wo++) mx = fmaxf(mx, sc[wo]);
    float p[5], lsum = 0.f;
#pragma unroll
    for (int wo = 0; wo < 5; wo++) {
        p[wo] = (sc[wo] > -1e29f) ? __expf(sc[wo] - mx) : 0.f;
        lsum += p[wo];
    }
    float o0 = 0.f, o1 = 0.f;
#pragma unroll
    for (int wo = 0; wo < 5; wo++) {
        const int j = s + wo - 2;
        if (j >= 0 && j < SEQ) {
            const size_t vb = (size_t)(b * SEQ + j) * 768 + 512 + h * 64;
            o0 += p[wo] * qkv[vb + lane];
            o1 += p[wo] * qkv[vb + 32 + lane];
        }
    }
    const float inv = 1.f / lsum;
    out[(size_t)n * 256 + h * 64 + lane] = o0 * inv;
    out[(size_t)n * 256 + h * 64 + 32 + lane] = o1 * inv;
}

// ---------------- residual add + LayerNorm --------------------------------------
__global__ void __launch_bounds__(256)
add_ln_kernel(const float* __restrict__ x, const float* __restrict__ dx,
              const float* __restrict__ g, const float* __restrict__ bb,
              float* __restrict__ out)
{
    const int n = blockIdx.x;
    const int d = threadIdx.x;
    const float v = x[(size_t)n * 256 + d] + dx[(size_t)n * 256 + d];
    float s1 = v, s2 = v * v;
#pragma unroll
    for (int o = 16; o > 0; o >>= 1) {
        s1 += __shfl_xor_sync(0xffffffffu, s1, o);
        s2 += __shfl_xor_sync(0xffffffffu, s2, o);
    }
    __shared__ float r1[8], r2[8];
    const int wid = d >> 5, lane = d & 31;
    if (lane == 0) { r1[wid] = s1; r2[wid] = s2; }
    __syncthreads();
    if (wid == 0) {
        float a = (lane < 8) ? r1[lane] : 0.f;
        float c = (lane < 8) ? r2[lane] : 0.f;
#pragma unroll
        for (int o = 4; o > 0; o >>= 1) {
            a += __shfl_xor_sync(0xffffffffu, a, o);
            c += __shfl_xor_sync(0xffffffffu, c, o);
        }
        if (lane == 0) { r1[0] = a; r2[0] = c; }
    }
    __syncthreads();
    const float mu = r1[0] * (1.f / 256.f);
    const float var = r2[0] * (1.f / 256.f) - mu * mu;
    out[(size_t)n * 256 + d] = (v - mu) * rsqrtf(var + 1e-5f) * g[d] + bb[d];
}

// ---------------- launch ---------------------------------------------------------
extern "C" void kernel_launch(void* const* d_in, const int* in_sizes, int n_in,
                              void* d_out, int out_size)
{
    const float* x      = (const float*)d_in[0];
    const float* g_in_w = (const float*)d_in[1];
    const float* g_in_b = (const float*)d_in[2];
    const float* g_out_w= (const float*)d_in[3];
    const float* g_out_b= (const float*)d_in[4];
    const float* t_in_w = (const float*)d_in[5];
    const float* t_in_b = (const float*)d_in[6];
    const float* t_out_w= (const float*)d_in[7];
    const float* t_out_b= (const float*)d_in[8];
    const float* fus_w1 = (const float*)d_in[9];
    const float* fus_b1 = (const float*)d_in[10];
    const float* fus_w2 = (const float*)d_in[11];
    const float* fus_b2 = (const float*)d_in[12];
    const float* ffn_w1 = (const float*)d_in[13];
    const float* ffn_b1 = (const float*)d_in[14];
    const float* ffn_w2 = (const float*)d_in[15];
    const float* ffn_b2 = (const float*)d_in[16];
    const float* gn_g   = (const float*)d_in[17];
    const float* gn_b   = (const float*)d_in[18];
    const float* fn_g   = (const float*)d_in[19];
    const float* fn_b   = (const float*)d_in[20];

    float *gqkv, *tqkv, *gat, *tat, *comb, *fush, *xfu, *h1, *ffh, *xff;
    cudaGetSymbolAddress((void**)&gqkv, g_qkv_buf);
    cudaGetSymbolAddress((void**)&tqkv, t_qkv_buf);
    cudaGetSymbolAddress((void**)&gat,  g_attn_buf);
    cudaGetSymbolAddress((void**)&tat,  t_attn_buf);
    cudaGetSymbolAddress((void**)&comb, comb_buf);
    cudaGetSymbolAddress((void**)&fush, fush_buf);
    cudaGetSymbolAddress((void**)&xfu,  xfused_buf);
    cudaGetSymbolAddress((void**)&h1,   h1_buf);
    cudaGetSymbolAddress((void**)&ffh,  ffnh_buf);
    cudaGetSymbolAddress((void**)&xff,  xffn_buf);

    // merged QKV projections (set1: global, set2: local)
    tgemm2_kernel<false><<<dim3(12, 64), 256, GSMEM_BYTES>>>(
        x, g_in_w, g_in_b, gqkv,
        x, t_in_w, t_in_b, tqkv, 6, 256, 768);

    // attention
    flash_global_attn<<<dim3(SEQ / 64, 8, 4), 128>>>(gqkv, gat);
    local_attn_kernel<<<NTOK, 128>>>(tqkv, tat);

    // merged output projections -> concat buffer [global | local]
    tgemm2_kernel<false><<<dim3(4, 64), 256, GSMEM_BYTES>>>(
        gat, g_out_w, g_out_b, comb,
        tat, t_out_w, t_out_b, comb + 256, 2, 256, 512);

    // fusion MLP
    tgemm2_kernel<true ><<<dim3(4, 64), 256, GSMEM_BYTES>>>(
        comb, fus_w1, fus_b1, fush,
        comb, fus_w1, fus_b1, fush, 4, 512, 512);
    tgemm2_kernel<false><<<dim3(2, 64), 256, GSMEM_BYTES>>>(
        fush, fus_w2, fus_b2, xfu,
        fush, fus_w2, fus_b2, xfu, 2, 512, 256);

    // residual + LN
    add_ln_kernel<<<NTOK, 256>>>(x, xfu, gn_g, gn_b, h1);

    // FFN
    tgemm2_kernel<true ><<<dim3(4, 64), 256, GSMEM_BYTES>>>(
        h1, ffn_w1, ffn_b1, ffh,
        h1, ffn_w1, ffn_b1, ffh, 4, 256, 512);
    tgemm2_kernel<false><<<dim3(2, 64), 256, GSMEM_BYTES>>>(
        ffh, ffn_w2, ffn_b2, xff,
        ffh, ffn_w2, ffn_b2, xff, 2, 512, 256);

    // final residual + LN -> output
    add_ln_kernel<<<NTOK, 256>>>(h1, xff, fn_g, fn_b, (float*)d_out);
}

// round 13
// speedup vs baseline: 3.4382x; 1.1215x over previous
#include <cuda_runtime.h>
#include <cuda_bf16.h>
#include <math.h>

#define NTOK 8192
#define SEQ 2048

// ---------------- scratch (static device globals; no allocation) ----------------
__device__ float    g_qkv_buf[NTOK * 768];
__device__ float    t_qkv_buf[NTOK * 768];
__device__ unsigned gat_buf[NTOK * 128];    // bf16x2
__device__ unsigned tat_buf[NTOK * 128];    // bf16x2
__device__ unsigned comb_buf[NTOK * 256];   // bf16x2 (512 bf16/row)
__device__ unsigned fush_buf[NTOK * 256];   // bf16x2
__device__ float    xfused_buf[NTOK * 256];
__device__ float    h1_buf[NTOK * 256];
__device__ unsigned h1b_buf[NTOK * 128];    // bf16x2 copy of h1
__device__ unsigned ffnh_buf[NTOK * 256];   // bf16x2
__device__ float    xffn_buf[NTOK * 256];
__device__ unsigned wbf_buf[589824];        // all weights as bf16x2

// weight offsets (in bf16 elements) inside wbf_buf
#define WOFF_GIN   0
#define WOFF_TIN   196608
#define WOFF_GOUT  393216
#define WOFF_TOUT  458752
#define WOFF_FUS1  524288
#define WOFF_FUS2  786432
#define WOFF_FFN1  917504
#define WOFF_FFN2  1048576
// total elems 1179648 -> 294912 float4 units -> 1152 blocks x 256 thr

// ---------------- helpers ---------------------------------------------------------
__device__ __forceinline__ unsigned f2tf32(float x) {
    unsigned r;
    asm("cvt.rna.tf32.f32 %0, %1;" : "=r"(r) : "f"(x));
    return r;
}
__device__ __forceinline__ unsigned pack_bf16(float lo, float hi) {
    unsigned r;
    asm("cvt.rn.bf16x2.f32 %0, %1, %2;" : "=r"(r) : "f"(hi), "f"(lo));
    return r;
}
__device__ __forceinline__ void mma_tf32(float* d, const unsigned* a, const unsigned* b,
                                         const float* c) {
    asm("mma.sync.aligned.m16n8k8.row.col.f32.tf32.tf32.f32 "
        "{%0,%1,%2,%3},{%4,%5,%6,%7},{%8,%9},{%10,%11,%12,%13};"
        : "=f"(d[0]), "=f"(d[1]), "=f"(d[2]), "=f"(d[3])
        : "r"(a[0]), "r"(a[1]), "r"(a[2]), "r"(a[3]),
          "r"(b[0]), "r"(b[1]),
          "f"(c[0]), "f"(c[1]), "f"(c[2]), "f"(c[3]));
}
__device__ __forceinline__ void mma_bf16(float* d, const unsigned* a, const unsigned* b,
                                         const float* c) {
    asm("mma.sync.aligned.m16n8k16.row.col.f32.bf16.bf16.f32 "
        "{%0,%1,%2,%3},{%4,%5,%6,%7},{%8,%9},{%10,%11,%12,%13};"
        : "=f"(d[0]), "=f"(d[1]), "=f"(d[2]), "=f"(d[3])
        : "r"(a[0]), "r"(a[1]), "r"(a[2]), "r"(a[3]),
          "r"(b[0]), "r"(b[1]),
          "f"(c[0]), "f"(c[1]), "f"(c[2]), "f"(c[3]));
}
__device__ __forceinline__ void cp_async16(void* smem, const void* gptr) {
    unsigned saddr = (unsigned)__cvta_generic_to_shared(smem);
    asm volatile("cp.async.ca.shared.global [%0], [%1], 16;" :: "r"(saddr), "l"(gptr));
}
#define CP_COMMIT()  asm volatile("cp.async.commit_group;")
#define CP_WAIT0()   asm volatile("cp.async.wait_group 0;")
#define CP_WAIT1()   asm volatile("cp.async.wait_group 1;")

// ---------------- weight fp32 -> bf16 conversion ---------------------------------
__global__ void __launch_bounds__(256)
convert_weights_kernel(const float* __restrict__ s0, const float* __restrict__ s1,
                       const float* __restrict__ s2, const float* __restrict__ s3,
                       const float* __restrict__ s4, const float* __restrict__ s5,
                       const float* __restrict__ s6, const float* __restrict__ s7,
                       unsigned* __restrict__ dst)
{
    const int i4 = blockIdx.x * 256 + threadIdx.x;  // float4 unit
    const int e = i4 * 4;                            // element index
    const float* src; int base;
    if      (e < 196608)  { src = s0; base = 0; }
    else if (e < 393216)  { src = s1; base = 196608; }
    else if (e < 458752)  { src = s2; base = 393216; }
    else if (e < 524288)  { src = s3; base = 458752; }
    else if (e < 786432)  { src = s4; base = 524288; }
    else if (e < 917504)  { src = s5; base = 786432; }
    else if (e < 1048576) { src = s6; base = 917504; }
    else                  { src = s7; base = 1048576; }
    float4 v = *reinterpret_cast<const float4*>(src + (e - base));
    uint2 o; o.x = pack_bf16(v.x, v.y); o.y = pack_bf16(v.z, v.w);
    *reinterpret_cast<uint2*>(dst + i4 * 2) = o;
}

// ---------------- BF16 dual-source cp.async GEMM ---------------------------------
// C[M,N] = A[M,K] @ W[N,K]^T + bias (opt SiLU). BM=BN=128, BK=32, 256 threads,
// 8 warps x (32x64) via m16n8k16. W always bf16 (cp.async). A either bf16
// (cp.async) or fp32 (register-stage + cvt; QKV only). C fp32 or bf16.
// 2-stage pipeline with one commit per iteration (invariant: wait_group(1)
// at iter kt guarantees tile kt resident).
#define SMH 20
#define GT (128 * SMH)
#define GSMEM_BYTES (4 * GT * 4)   // 40960 B
template <bool SILU, bool ABF16, bool CBF16>
__global__ void __launch_bounds__(256, 2)
tgemm_kernel(const void* __restrict__ A1_, const __nv_bfloat16* __restrict__ W1,
             const float* __restrict__ b1, void* __restrict__ C1_,
             const void* __restrict__ A2_, const __nv_bfloat16* __restrict__ W2,
             const float* __restrict__ b2, void* __restrict__ C2_,
             int split, int K, int ldc)
{
    extern __shared__ unsigned sm[];
    unsigned* As = sm;
    unsigned* Bs = sm + 2 * GT;

    const int tid = threadIdx.x;
    const int bm = blockIdx.y * 128;

    const void* A_; const __nv_bfloat16* W; const float* bias; void* C_;
    int bn;
    if ((int)blockIdx.x < split) { A_ = A1_; W = W1; bias = b1; C_ = C1_; bn = blockIdx.x * 128; }
    else { A_ = A2_; W = W2; bias = b2; C_ = C2_; bn = (blockIdx.x - split) * 128; }

    const int warp = tid >> 5, lane = tid & 31;
    const int wm = (warp & 3) * 32, wn = (warp >> 2) * 64;
    const int g = lane >> 2, t = lane & 3;
    const int lrow = tid >> 1, lhalf = tid & 1;

    const __nv_bfloat16* wrow = W + (size_t)(bn + lrow) * K + lhalf * 16;
    const __nv_bfloat16* arb = (const __nv_bfloat16*)A_ + (size_t)(bm + lrow) * K + lhalf * 16;
    const float* arf = (const float*)A_ + (size_t)(bm + lrow) * K + lhalf * 16;

    unsigned* asw = &As[lrow * SMH + lhalf * 8];
    unsigned* bsw = &Bs[lrow * SMH + lhalf * 8];

    float acc[2][8][4];
#pragma unroll
    for (int mt = 0; mt < 2; mt++)
#pragma unroll
        for (int nt = 0; nt < 8; nt++)
#pragma unroll
            for (int r = 0; r < 4; r++) acc[mt][nt][r] = 0.f;

    unsigned ra[8];
    const int ntiles = K >> 5;

    // prologue: tiles 0 and 1
    if (ABF16) {
        cp_async16(asw, arb);            cp_async16(asw + 4, arb + 8);
        cp_async16(bsw, wrow);           cp_async16(bsw + 4, wrow + 8);
        CP_COMMIT();
        cp_async16(asw + GT, arb + 32);  cp_async16(asw + GT + 4, arb + 40);
        cp_async16(bsw + GT, wrow + 32); cp_async16(bsw + GT + 4, wrow + 40);
        CP_COMMIT();
    } else {
#pragma unroll
        for (int i = 0; i < 4; i++) {
            float4 av = *reinterpret_cast<const float4*>(arf + i * 4);
            ra[2 * i]     = pack_bf16(av.x, av.y);
            ra[2 * i + 1] = pack_bf16(av.z, av.w);
        }
        cp_async16(bsw, wrow);           cp_async16(bsw + 4, wrow + 8);
        CP_COMMIT();
        cp_async16(bsw + GT, wrow + 32); cp_async16(bsw + GT + 4, wrow + 40);
        CP_COMMIT();
    }

    for (int kt = 0; kt < ntiles; kt++) {
        const int st = kt & 1;
        unsigned* as = As + st * GT;
        unsigned* bs = Bs + st * GT;

        if (!ABF16) {
            // store staged A(kt) to smem (no cp.async ever touches As here)
            uint4* da = reinterpret_cast<uint4*>(asw + st * GT);
            da[0] = make_uint4(ra[0], ra[1], ra[2], ra[3]);
            da[1] = make_uint4(ra[4], ra[5], ra[6], ra[7]);
        }
        CP_WAIT1();        // tile kt's group retired
        __syncthreads();

        if (!ABF16 && kt + 1 < ntiles) {
            const float* p = arf + (kt + 1) * 32;
#pragma unroll
            for (int i = 0; i < 4; i++) {
                float4 av = *reinterpret_cast<const float4*>(p + i * 4);
                ra[2 * i]     = pack_bf16(av.x, av.y);
                ra[2 * i + 1] = pack_bf16(av.z, av.w);
            }
        }

        // compute: two k16 steps over BK=32
#pragma unroll
        for (int s = 0; s < 2; s++) {
            const int kk = s * 8;
            unsigned af[2][4];
#pragma unroll
            for (int mt = 0; mt < 2; mt++) {
                const int r0 = wm + mt * 16 + g;
                af[mt][0] = as[(r0    ) * SMH + kk + t];
                af[mt][1] = as[(r0 + 8) * SMH + kk + t];
                af[mt][2] = as[(r0    ) * SMH + kk + t + 4];
                af[mt][3] = as[(r0 + 8) * SMH + kk + t + 4];
            }
            unsigned bf[8][2];
#pragma unroll
            for (int nt = 0; nt < 8; nt++) {
                const int n0 = wn + nt * 8 + g;
                bf[nt][0] = bs[n0 * SMH + kk + t];
                bf[nt][1] = bs[n0 * SMH + kk + t + 4];
            }
#pragma unroll
            for (int mt = 0; mt < 2; mt++)
#pragma unroll
                for (int nt = 0; nt < 8; nt++)
                    mma_bf16(acc[mt][nt], af[mt], bf[nt], acc[mt][nt]);
        }
        __syncthreads();

        // issue tile kt+2 into the stage just freed; always commit (invariant)
        if (kt + 2 < ntiles) {
            const int off = (kt + 2) * 32;
            if (ABF16) {
                cp_async16(asw + st * GT, arb + off);
                cp_async16(asw + st * GT + 4, arb + off + 8);
            }
            cp_async16(bsw + st * GT, wrow + off);
            cp_async16(bsw + st * GT + 4, wrow + off + 8);
        }
        CP_COMMIT();
    }

    // epilogue: bias (+SiLU)
#pragma unroll
    for (int mt = 0; mt < 2; mt++) {
#pragma unroll
        for (int nt = 0; nt < 8; nt++) {
            const int col = bn + wn + nt * 8 + 2 * t;
            const float b0 = bias[col], bb1 = bias[col + 1];
#pragma unroll
            for (int h = 0; h < 2; h++) {
                const int row = bm + wm + mt * 16 + g + h * 8;
                float v0 = acc[mt][nt][2 * h] + b0;
                float v1 = acc[mt][nt][2 * h + 1] + bb1;
                if (SILU) {
                    v0 = v0 / (1.f + __expf(-v0));
                    v1 = v1 / (1.f + __expf(-v1));
                }
                if (CBF16) {
                    ((unsigned*)C_)[((size_t)row * ldc + col) >> 1] = pack_bf16(v0, v1);
                } else {
                    float2 o; o.x = v0; o.y = v1;
                    *reinterpret_cast<float2*>((float*)C_ + (size_t)row * ldc + col) = o;
                }
            }
        }
    }
}

// ---------------- flash global attention (tf32 mma): 8 heads, hd=32 -------------
// Unchanged internals; output written as bf16x2.
#define KS_STRIDE 36
#define VS_STRIDE 40
#define PS_STRIDE 68
__global__ void __launch_bounds__(128)
flash_global_attn(const float* __restrict__ qkv, unsigned* __restrict__ out)
{
    __shared__ unsigned Ks[64 * KS_STRIDE];
    __shared__ unsigned Vs[64 * VS_STRIDE];
    __shared__ unsigned Ps[64 * PS_STRIDE];

    const int tid = threadIdx.x;
    const int warp = tid >> 5;
    const int lane = tid & 31;
    const int g = lane >> 2;
    const int t = lane & 3;
    const int h = blockIdx.y;
    const int b = blockIdx.z;
    const int q0 = blockIdx.x * 64;
    const int wq = warp * 16;

    const float scale = 0.17677669529663687f;  // 1/sqrt(32)
    unsigned qf[4][4];
    {
        const float* base = qkv + (size_t)(b * SEQ) * 768 + h * 32;
        const int r0 = q0 + wq + g;
#pragma unroll
        for (int ks = 0; ks < 4; ks++) {
            const int c = ks * 8 + t;
            qf[ks][0] = f2tf32(base[(size_t)(r0    ) * 768 + c    ] * scale);
            qf[ks][1] = f2tf32(base[(size_t)(r0 + 8) * 768 + c    ] * scale);
            qf[ks][2] = f2tf32(base[(size_t)(r0    ) * 768 + c + 4] * scale);
            qf[ks][3] = f2tf32(base[(size_t)(r0 + 8) * 768 + c + 4] * scale);
        }
    }

    float o[4][4];
#pragma unroll
    for (int nt = 0; nt < 4; nt++)
#pragma unroll
        for (int r = 0; r < 4; r++) o[nt][r] = 0.f;
    float m0 = -1e30f, m1 = -1e30f, l0 = 0.f, l1 = 0.f;

    const int lrow = tid >> 1;
    const int lcol = (tid & 1) * 16;

    for (int kt = 0; kt < SEQ; kt += 64) {
        __syncthreads();
#pragma unroll
        for (int i = 0; i < 4; i++) {
            const int c = lcol + i * 4;
            const float* kp = qkv + (size_t)(b * SEQ + kt + lrow) * 768 + 256 + h * 32 + c;
            cp_async16(&Ks[lrow * KS_STRIDE + c], kp);
            cp_async16(&Vs[lrow * VS_STRIDE + c], kp + 256);
        }
        CP_COMMIT();
        CP_WAIT0();
        __syncthreads();

        float s[8][4];
#pragma unroll
        for (int nt = 0; nt < 8; nt++)
#pragma unroll
            for (int r = 0; r < 4; r++) s[nt][r] = 0.f;
#pragma unroll
        for (int ks = 0; ks < 4; ks++) {
            const int kk = ks * 8;
#pragma unroll
            for (int nt = 0; nt < 8; nt++) {
                unsigned bf[2];
                const unsigned* kb = &Ks[(nt * 8 + g) * KS_STRIDE + kk + t];
                bf[0] = kb[0];
                bf[1] = kb[4];
                mma_tf32(s[nt], qf[ks], bf, s[nt]);
            }
        }

        float r0 = s[0][0], r1 = s[0][2];
#pragma unroll
        for (int nt = 0; nt < 8; nt++) {
            r0 = fmaxf(r0, fmaxf(s[nt][0], s[nt][1]));
            r1 = fmaxf(r1, fmaxf(s[nt][2], s[nt][3]));
        }
        r0 = fmaxf(r0, __shfl_xor_sync(0xffffffffu, r0, 1));
        r0 = fmaxf(r0, __shfl_xor_sync(0xffffffffu, r0, 2));
        r1 = fmaxf(r1, __shfl_xor_sync(0xffffffffu, r1, 1));
        r1 = fmaxf(r1, __shfl_xor_sync(0xffffffffu, r1, 2));

        const float m0n = fmaxf(m0, r0);
        const float m1n = fmaxf(m1, r1);
        const float c0 = __expf(m0 - m0n);
        const float c1 = __expf(m1 - m1n);

        float sum0 = 0.f, sum1 = 0.f;
#pragma unroll
        for (int nt = 0; nt < 8; nt++) {
            const float p00 = __expf(s[nt][0] - m0n);
            const float p01 = __expf(s[nt][1] - m0n);
            const float p10 = __expf(s[nt][2] - m1n);
            const float p11 = __expf(s[nt][3] - m1n);
            sum0 += p00 + p01;
            sum1 += p10 + p11;
            const int col = nt * 8 + 2 * t;
            unsigned* pr0 = &Ps[(wq + g    ) * PS_STRIDE + col];
            unsigned* pr1 = &Ps[(wq + g + 8) * PS_STRIDE + col];
            pr0[0] = __float_as_uint(p00); pr0[1] = __float_as_uint(p01);
            pr1[0] = __float_as_uint(p10); pr1[1] = __float_as_uint(p11);
        }
        sum0 += __shfl_xor_sync(0xffffffffu, sum0, 1);
        sum0 += __shfl_xor_sync(0xffffffffu, sum0, 2);
        sum1 += __shfl_xor_sync(0xffffffffu, sum1, 1);
        sum1 += __shfl_xor_sync(0xffffffffu, sum1, 2);
        l0 = l0 * c0 + sum0;
        l1 = l1 * c1 + sum1;
        m0 = m0n; m1 = m1n;

#pragma unroll
        for (int nt = 0; nt < 4; nt++) {
            o[nt][0] *= c0; o[nt][1] *= c0;
            o[nt][2] *= c1; o[nt][3] *= c1;
        }
        __syncwarp();

#pragma unroll
        for (int ks = 0; ks < 8; ks++) {
            const int kk = ks * 8;
            unsigned af[4];
            const unsigned* pa0 = &Ps[(wq + g    ) * PS_STRIDE + kk + t];
            const unsigned* pa1 = &Ps[(wq + g + 8) * PS_STRIDE + kk + t];
            af[0] = pa0[0]; af[1] = pa1[0];
            af[2] = pa0[4]; af[3] = pa1[4];
#pragma unroll
            for (int nt = 0; nt < 4; nt++) {
                unsigned bf[2];
                bf[0] = Vs[(kk + t    ) * VS_STRIDE + nt * 8 + g];
                bf[1] = Vs[(kk + t + 4) * VS_STRIDE + nt * 8 + g];
                mma_tf32(o[nt], af, bf, o[nt]);
            }
        }
    }

    const float inv0 = 1.f / l0;
    const float inv1 = 1.f / l1;
    unsigned* op = out + (size_t)(b * SEQ) * 128 + h * 16;
    const int row0 = q0 + wq + g;
#pragma unroll
    for (int nt = 0; nt < 4; nt++) {
        const int cu = nt * 4 + t;
        op[(size_t)(row0    ) * 128 + cu] = pack_bf16(o[nt][0] * inv0, o[nt][1] * inv0);
        op[(size_t)(row0 + 8) * 128 + cu] = pack_bf16(o[nt][2] * inv1, o[nt][3] * inv1);
    }
}

// ---------------- local attention: 4 heads, hd=64, window 5 (bf16 out) ----------
__global__ void __launch_bounds__(128)
local_attn_kernel(const float* __restrict__ qkv, __nv_bfloat16* __restrict__ out)
{
    const int n = blockIdx.x;
    const int b = n / SEQ;
    const int s = n % SEQ;
    const int h = threadIdx.x >> 5;
    const int lane = threadIdx.x & 31;

    const size_t qb = (size_t)n * 768 + h * 64;
    const float q0 = qkv[qb + lane];
    const float q1 = qkv[qb + 32 + lane];

    float sc[5];
#pragma unroll
    for (int wo = 0; wo < 5; wo++) {
        const int j = s + wo - 2;
        if (j >= 0 && j < SEQ) {
            const size_t kb = (size_t)(b * SEQ + j) * 768 + 256 + h * 64;
            float part = q0 * qkv[kb + lane] + q1 * qkv[kb + 32 + lane];
#pragma unroll
            for (int o = 16; o > 0; o >>= 1) part += __shfl_xor_sync(0xffffffffu, part, o);
            sc[wo] = part * 0.125f;
        } else {
            sc[wo] = -1e30f;
        }
    }
    float mx = sc[0];
#pragma unroll
    for (int wo = 1; wo < 5; wo++) mx = fmaxf(mx, sc[wo]);
    float p[5], lsum = 0.f;
#pragma unroll
    for (int wo = 0; wo < 5; wo++) {
        p[wo] = (sc[wo] > -1e29f) ? __expf(sc[wo] - mx) : 0.f;
        lsum += p[wo];
    }
    float o0 = 0.f, o1 = 0.f;
#pragma unroll
    for (int wo = 0; wo < 5; wo++) {
        const int j = s + wo - 2;
        if (j >= 0 && j < SEQ) {
            const size_t vb = (size_t)(b * SEQ + j) * 768 + 512 + h * 64;
            o0 += p[wo] * qkv[vb + lane];
            o1 += p[wo] * qkv[vb + 32 + lane];
        }
    }
    const float inv = 1.f / lsum;
    out[(size_t)n * 256 + h * 64 + lane]      = __float2bfloat16(o0 * inv);
    out[(size_t)n * 256 + h * 64 + 32 + lane] = __float2bfloat16(o1 * inv);
}

// ---------------- residual add + LayerNorm (optional bf16 twin) ------------------
template <bool WB16>
__global__ void __launch_bounds__(256)
add_ln_kernel(const float* __restrict__ x, const float* __restrict__ dx,
              const float* __restrict__ g, const float* __restrict__ bb,
              float* __restrict__ out, unsigned* __restrict__ outb)
{
    const int n = blockIdx.x;
    const int d = threadIdx.x;
    const float v = x[(size_t)n * 256 + d] + dx[(size_t)n * 256 + d];
    float s1 = v, s2 = v * v;
#pragma unroll
    for (int o = 16; o > 0; o >>= 1) {
        s1 += __shfl_xor_sync(0xffffffffu, s1, o);
        s2 += __shfl_xor_sync(0xffffffffu, s2, o);
    }
    __shared__ float r1[8], r2[8];
    const int wid = d >> 5, lane = d & 31;
    if (lane == 0) { r1[wid] = s1; r2[wid] = s2; }
    __syncthreads();
    if (wid == 0) {
        float a = (lane < 8) ? r1[lane] : 0.f;
        float c = (lane < 8) ? r2[lane] : 0.f;
#pragma unroll
        for (int o = 4; o > 0; o >>= 1) {
            a += __shfl_xor_sync(0xffffffffu, a, o);
            c += __shfl_xor_sync(0xffffffffu, c, o);
        }
        if (lane == 0) { r1[0] = a; r2[0] = c; }
    }
    __syncthreads();
    const float mu = r1[0] * (1.f / 256.f);
    const float var = r2[0] * (1.f / 256.f) - mu * mu;
    const float vn = (v - mu) * rsqrtf(var + 1e-5f) * g[d] + bb[d];
    out[(size_t)n * 256 + d] = vn;
    if (WB16) {
        const float hi = __shfl_down_sync(0xffffffffu, vn, 1);
        if ((d & 1) == 0) outb[(size_t)n * 128 + (d >> 1)] = pack_bf16(vn, hi);
    }
}

// ---------------- launch ---------------------------------------------------------
extern "C" void kernel_launch(void* const* d_in, const int* in_sizes, int n_in,
                              void* d_out, int out_size)
{
    const float* x      = (const float*)d_in[0];
    const float* g_in_w = (const float*)d_in[1];
    const float* g_in_b = (const float*)d_in[2];
    const float* g_out_w= (const float*)d_in[3];
    const float* g_out_b= (const float*)d_in[4];
    const float* t_in_w = (const float*)d_in[5];
    const float* t_in_b = (const float*)d_in[6];
    const float* t_out_w= (const float*)d_in[7];
    const float* t_out_b= (const float*)d_in[8];
    const float* fus_w1 = (const float*)d_in[9];
    const float* fus_b1 = (const float*)d_in[10];
    const float* fus_w2 = (const float*)d_in[11];
    const float* fus_b2 = (const float*)d_in[12];
    const float* ffn_w1 = (const float*)d_in[13];
    const float* ffn_b1 = (const float*)d_in[14];
    const float* ffn_w2 = (const float*)d_in[15];
    const float* ffn_b2 = (const float*)d_in[16];
    const float* gn_g   = (const float*)d_in[17];
    const float* gn_b   = (const float*)d_in[18];
    const float* fn_g   = (const float*)d_in[19];
    const float* fn_b   = (const float*)d_in[20];

    float *gqkv, *tqkv, *xfu, *h1, *xff;
    unsigned *gat, *tat, *comb, *fush, *h1b, *ffh, *wbf;
    cudaGetSymbolAddress((void**)&gqkv, g_qkv_buf);
    cudaGetSymbolAddress((void**)&tqkv, t_qkv_buf);
    cudaGetSymbolAddress((void**)&gat,  gat_buf);
    cudaGetSymbolAddress((void**)&tat,  tat_buf);
    cudaGetSymbolAddress((void**)&comb, comb_buf);
    cudaGetSymbolAddress((void**)&fush, fush_buf);
    cudaGetSymbolAddress((void**)&xfu,  xfused_buf);
    cudaGetSymbolAddress((void**)&h1,   h1_buf);
    cudaGetSymbolAddress((void**)&h1b,  h1b_buf);
    cudaGetSymbolAddress((void**)&ffh,  ffnh_buf);
    cudaGetSymbolAddress((void**)&xff,  xffn_buf);
    cudaGetSymbolAddress((void**)&wbf,  wbf_buf);

    const __nv_bfloat16* wb = (const __nv_bfloat16*)wbf;

    // 0) weights fp32 -> bf16 (once per launch; graph-capturable kernel)
    convert_weights_kernel<<<1152, 256>>>(g_in_w, t_in_w, g_out_w, t_out_w,
                                          fus_w1, fus_w2, ffn_w1, ffn_w2, wbf);

    // 1) merged QKV projections (A fp32, C fp32)
    tgemm_kernel<false, false, false><<<dim3(12, 64), 256, GSMEM_BYTES>>>(
        x, wb + WOFF_GIN, g_in_b, gqkv,
        x, wb + WOFF_TIN, t_in_b, tqkv, 6, 256, 768);

    // 2) attention (outputs bf16)
    flash_global_attn<<<dim3(SEQ / 64, 8, 4), 128>>>(gqkv, gat);
    local_attn_kernel<<<NTOK, 128>>>(tqkv, (__nv_bfloat16*)tat);

    // 3) merged output projections -> comb (bf16), [global | local]
    tgemm_kernel<false, true, true><<<dim3(4, 64), 256, GSMEM_BYTES>>>(
        gat, wb + WOFF_GOUT, g_out_b, comb,
        tat, wb + WOFF_TOUT, t_out_b, comb + 128, 2, 256, 512);

    // 4) fusion MLP
    tgemm_kernel<true, true, true><<<dim3(4, 64), 256, GSMEM_BYTES>>>(
        comb, wb + WOFF_FUS1, fus_b1, fush,
        comb, wb + WOFF_FUS1, fus_b1, fush, 4, 512, 512);
    tgemm_kernel<false, true, false><<<dim3(2, 64), 256, GSMEM_BYTES>>>(
        fush, wb + WOFF_FUS2, fus_b2, xfu,
        fush, wb + WOFF_FUS2, fus_b2, xfu, 2, 512, 256);

    // 5) residual + LN (fp32 out + bf16 twin)
    add_ln_kernel<true><<<NTOK, 256>>>(x, xfu, gn_g, gn_b, h1, h1b);

    // 6) FFN
    tgemm_kernel<true, true, true><<<dim3(4, 64), 256, GSMEM_BYTES>>>(
        h1b, wb + WOFF_FFN1, ffn_b1, ffh,
        h1b, wb + WOFF_FFN1, ffn_b1, ffh, 4, 256, 512);
    tgemm_kernel<false, true, false><<<dim3(2, 64), 256, GSMEM_BYTES>>>(
        ffh, wb + WOFF_FFN2, ffn_b2, xff,
        ffh, wb + WOFF_FFN2, ffn_b2, xff, 2, 512, 256);

    // 7) final residual + LN -> output (fp32)
    add_ln_kernel<false><<<NTOK, 256>>>(h1, xff, fn_g, fn_b, (float*)d_out, nullptr);
}

// round 15
// speedup vs baseline: 4.3860x; 1.2757x over previous
#include <cuda_runtime.h>
#include <cuda_bf16.h>
#include <math.h>

#define NTOK 8192
#define SEQ 2048

// ---------------- scratch (static device globals; no allocation) ----------------
__device__ float    g_qkv_buf[NTOK * 768];
__device__ float    t_qkv_buf[NTOK * 768];
__device__ unsigned gat_buf[NTOK * 128];    // bf16x2
__device__ unsigned tat_buf[NTOK * 128];    // bf16x2
__device__ unsigned comb_buf[NTOK * 256];   // bf16x2 (512 bf16/row)
__device__ unsigned fush_buf[NTOK * 256];   // bf16x2
__device__ float    xfused_buf[NTOK * 256];
__device__ float    h1_buf[NTOK * 256];
__device__ unsigned h1b_buf[NTOK * 128];    // bf16x2 copy of h1
__device__ unsigned ffnh_buf[NTOK * 256];   // bf16x2
__device__ float    xffn_buf[NTOK * 256];
__device__ unsigned wbf_buf[589824];        // all weights as bf16x2

// weight offsets (in bf16 elements) inside wbf_buf
#define WOFF_GIN   0
#define WOFF_TIN   196608
#define WOFF_GOUT  393216
#define WOFF_TOUT  458752
#define WOFF_FUS1  524288
#define WOFF_FUS2  786432
#define WOFF_FFN1  917504
#define WOFF_FFN2  1048576

// ---------------- helpers ---------------------------------------------------------
__device__ __forceinline__ unsigned pack_bf16(float lo, float hi) {
    unsigned r;
    asm("cvt.rn.bf16x2.f32 %0, %1, %2;" : "=r"(r) : "f"(hi), "f"(lo));
    return r;
}
__device__ __forceinline__ void mma_bf16(float* d, const unsigned* a, const unsigned* b,
                                         const float* c) {
    asm("mma.sync.aligned.m16n8k16.row.col.f32.bf16.bf16.f32 "
        "{%0,%1,%2,%3},{%4,%5,%6,%7},{%8,%9},{%10,%11,%12,%13};"
        : "=f"(d[0]), "=f"(d[1]), "=f"(d[2]), "=f"(d[3])
        : "r"(a[0]), "r"(a[1]), "r"(a[2]), "r"(a[3]),
          "r"(b[0]), "r"(b[1]),
          "f"(c[0]), "f"(c[1]), "f"(c[2]), "f"(c[3]));
}
__device__ __forceinline__ void ldmatrix_x4_trans(unsigned& r0, unsigned& r1,
                                                  unsigned& r2, unsigned& r3,
                                                  unsigned saddr) {
    asm volatile("ldmatrix.sync.aligned.m8n8.x4.trans.shared.b16 {%0,%1,%2,%3}, [%4];"
                 : "=r"(r0), "=r"(r1), "=r"(r2), "=r"(r3) : "r"(saddr));
}
__device__ __forceinline__ void cp_async16(void* smem, const void* gptr) {
    unsigned saddr = (unsigned)__cvta_generic_to_shared(smem);
    asm volatile("cp.async.ca.shared.global [%0], [%1], 16;" :: "r"(saddr), "l"(gptr));
}
#define CP_COMMIT()  asm volatile("cp.async.commit_group;")
#define CP_WAIT1()   asm volatile("cp.async.wait_group 1;")

// ---------------- weight fp32 -> bf16 conversion ---------------------------------
__global__ void __launch_bounds__(256)
convert_weights_kernel(const float* __restrict__ s0, const float* __restrict__ s1,
                       const float* __restrict__ s2, const float* __restrict__ s3,
                       const float* __restrict__ s4, const float* __restrict__ s5,
                       const float* __restrict__ s6, const float* __restrict__ s7,
                       unsigned* __restrict__ dst)
{
    const int i4 = blockIdx.x * 256 + threadIdx.x;
    const int e = i4 * 4;
    const float* src; int base;
    if      (e < 196608)  { src = s0; base = 0; }
    else if (e < 393216)  { src = s1; base = 196608; }
    else if (e < 458752)  { src = s2; base = 393216; }
    else if (e < 524288)  { src = s3; base = 458752; }
    else if (e < 786432)  { src = s4; base = 524288; }
    else if (e < 917504)  { src = s5; base = 786432; }
    else if (e < 1048576) { src = s6; base = 917504; }
    else                  { src = s7; base = 1048576; }
    float4 v = *reinterpret_cast<const float4*>(src + (e - base));
    uint2 o; o.x = pack_bf16(v.x, v.y); o.y = pack_bf16(v.z, v.w);
    *reinterpret_cast<uint2*>(dst + i4 * 2) = o;
}

// ---------------- BF16 dual-source cp.async GEMM ---------------------------------
#define SMH 20
#define GT (128 * SMH)
#define GSMEM_BYTES (4 * GT * 4)   // 40960 B
template <bool SILU, bool ABF16, bool CBF16>
__global__ void __launch_bounds__(256, 2)
tgemm_kernel(const void* __restrict__ A1_, const __nv_bfloat16* __restrict__ W1,
             const float* __restrict__ b1, void* __restrict__ C1_,
             const void* __restrict__ A2_, const __nv_bfloat16* __restrict__ W2,
             const float* __restrict__ b2, void* __restrict__ C2_,
             int split, int K, int ldc)
{
    extern __shared__ unsigned sm[];
    unsigned* As = sm;
    unsigned* Bs = sm + 2 * GT;

    const int tid = threadIdx.x;
    const int bm = blockIdx.y * 128;

    const void* A_; const __nv_bfloat16* W; const float* bias; void* C_;
    int bn;
    if ((int)blockIdx.x < split) { A_ = A1_; W = W1; bias = b1; C_ = C1_; bn = blockIdx.x * 128; }
    else { A_ = A2_; W = W2; bias = b2; C_ = C2_; bn = (blockIdx.x - split) * 128; }

    const int warp = tid >> 5, lane = tid & 31;
    const int wm = (warp & 3) * 32, wn = (warp >> 2) * 64;
    const int g = lane >> 2, t = lane & 3;
    const int lrow = tid >> 1, lhalf = tid & 1;

    const __nv_bfloat16* wrow = W + (size_t)(bn + lrow) * K + lhalf * 16;
    const __nv_bfloat16* arb = (const __nv_bfloat16*)A_ + (size_t)(bm + lrow) * K + lhalf * 16;
    const float* arf = (const float*)A_ + (size_t)(bm + lrow) * K + lhalf * 16;

    unsigned* asw = &As[lrow * SMH + lhalf * 8];
    unsigned* bsw = &Bs[lrow * SMH + lhalf * 8];

    float acc[2][8][4];
#pragma unroll
    for (int mt = 0; mt < 2; mt++)
#pragma unroll
        for (int nt = 0; nt < 8; nt++)
#pragma unroll
            for (int r = 0; r < 4; r++) acc[mt][nt][r] = 0.f;

    unsigned ra[8];
    const int ntiles = K >> 5;

    // prologue: tiles 0 and 1
    if (ABF16) {
        cp_async16(asw, arb);            cp_async16(asw + 4, arb + 8);
        cp_async16(bsw, wrow);           cp_async16(bsw + 4, wrow + 8);
        CP_COMMIT();
        cp_async16(asw + GT, arb + 32);  cp_async16(asw + GT + 4, arb + 40);
        cp_async16(bsw + GT, wrow + 32); cp_async16(bsw + GT + 4, wrow + 40);
        CP_COMMIT();
    } else {
#pragma unroll
        for (int i = 0; i < 4; i++) {
            float4 av = *reinterpret_cast<const float4*>(arf + i * 4);
            ra[2 * i]     = pack_bf16(av.x, av.y);
            ra[2 * i + 1] = pack_bf16(av.z, av.w);
        }
        cp_async16(bsw, wrow);           cp_async16(bsw + 4, wrow + 8);
        CP_COMMIT();
        cp_async16(bsw + GT, wrow + 32); cp_async16(bsw + GT + 4, wrow + 40);
        CP_COMMIT();
    }

    for (int kt = 0; kt < ntiles; kt++) {
        const int st = kt & 1;
        unsigned* as = As + st * GT;
        unsigned* bs = Bs + st * GT;

        if (!ABF16) {
            uint4* da = reinterpret_cast<uint4*>(asw + st * GT);
            da[0] = make_uint4(ra[0], ra[1], ra[2], ra[3]);
            da[1] = make_uint4(ra[4], ra[5], ra[6], ra[7]);
        }
        CP_WAIT1();
        __syncthreads();

        if (!ABF16 && kt + 1 < ntiles) {
            const float* p = arf + (kt + 1) * 32;
#pragma unroll
            for (int i = 0; i < 4; i++) {
                float4 av = *reinterpret_cast<const float4*>(p + i * 4);
                ra[2 * i]     = pack_bf16(av.x, av.y);
                ra[2 * i + 1] = pack_bf16(av.z, av.w);
            }
        }

#pragma unroll
        for (int s = 0; s < 2; s++) {
            const int kk = s * 8;
            unsigned af[2][4];
#pragma unroll
            for (int mt = 0; mt < 2; mt++) {
                const int r0 = wm + mt * 16 + g;
                af[mt][0] = as[(r0    ) * SMH + kk + t];
                af[mt][1] = as[(r0 + 8) * SMH + kk + t];
                af[mt][2] = as[(r0    ) * SMH + kk + t + 4];
                af[mt][3] = as[(r0 + 8) * SMH + kk + t + 4];
            }
            unsigned bf[8][2];
#pragma unroll
            for (int nt = 0; nt < 8; nt++) {
                const int n0 = wn + nt * 8 + g;
                bf[nt][0] = bs[n0 * SMH + kk + t];
                bf[nt][1] = bs[n0 * SMH + kk + t + 4];
            }
#pragma unroll
            for (int mt = 0; mt < 2; mt++)
#pragma unroll
                for (int nt = 0; nt < 8; nt++)
                    mma_bf16(acc[mt][nt], af[mt], bf[nt], acc[mt][nt]);
        }
        __syncthreads();

        if (kt + 2 < ntiles) {
            const int off = (kt + 2) * 32;
            if (ABF16) {
                cp_async16(asw + st * GT, arb + off);
                cp_async16(asw + st * GT + 4, arb + off + 8);
            }
            cp_async16(bsw + st * GT, wrow + off);
            cp_async16(bsw + st * GT + 4, wrow + off + 8);
        }
        CP_COMMIT();
    }

    // epilogue: bias (+SiLU)
#pragma unroll
    for (int mt = 0; mt < 2; mt++) {
#pragma unroll
        for (int nt = 0; nt < 8; nt++) {
            const int col = bn + wn + nt * 8 + 2 * t;
            const float b0 = bias[col], bb1 = bias[col + 1];
#pragma unroll
            for (int h = 0; h < 2; h++) {
                const int row = bm + wm + mt * 16 + g + h * 8;
                float v0 = acc[mt][nt][2 * h] + b0;
                float v1 = acc[mt][nt][2 * h + 1] + bb1;
                if (SILU) {
                    v0 = v0 / (1.f + __expf(-v0));
                    v1 = v1 / (1.f + __expf(-v1));
                }
                if (CBF16) {
                    ((unsigned*)C_)[((size_t)row * ldc + col) >> 1] = pack_bf16(v0, v1);
                } else {
                    float2 o; o.x = v0; o.y = v1;
                    *reinterpret_cast<float2*>((float*)C_ + (size_t)row * ldc + col) = o;
                }
            }
        }
    }
}

// ---------------- flash global attention (bf16 mma, FA2-style) ------------------
// One block = one (b,h) x 64 queries; 4 warps x 16 query rows; 64-key tiles.
// S = Q@K^T via m16n8k16 bf16 (K smem stride-20 u32 pairs, conflict-free).
// P fragments re-packed directly from S accumulators (no P smem).
// P@V via m16n8k16 bf16: V bf16 [key][dim] smem (row stride 40 bf16 = 80B),
// B fragments via ldmatrix.x4.trans (conflict-free: 20r%32 distinct).
#define KSR 20   // u32 (bf16-pair) stride per K row
#define VSR 40   // bf16 stride per V row
__global__ void __launch_bounds__(128)
flash_global_attn(const float* __restrict__ qkv, unsigned* __restrict__ out)
{
    __shared__ unsigned Ks[64 * KSR];
    __shared__ unsigned short Vs[64 * VSR];

    const int tid = threadIdx.x;
    const int warp = tid >> 5;
    const int lane = tid & 31;
    const int g = lane >> 2;
    const int t = lane & 3;
    const int h = blockIdx.y;
    const int b = blockIdx.z;
    const int q0 = blockIdx.x * 64;
    const int wq = warp * 16;

    // Q fragments (pre-scaled bf16), two k16 steps
    const float scale = 0.17677669529663687f;  // 1/sqrt(32)
    unsigned qf[2][4];
    {
        const float* base = qkv + (size_t)(b * SEQ) * 768 + h * 32;
        const size_t r0 = (size_t)(q0 + wq + g) * 768;
        const size_t r1 = (size_t)(q0 + wq + g + 8) * 768;
#pragma unroll
        for (int ks = 0; ks < 2; ks++) {
            const int c = ks * 16 + 2 * t;
            qf[ks][0] = pack_bf16(base[r0 + c] * scale,     base[r0 + c + 1] * scale);
            qf[ks][1] = pack_bf16(base[r1 + c] * scale,     base[r1 + c + 1] * scale);
            qf[ks][2] = pack_bf16(base[r0 + c + 8] * scale, base[r0 + c + 9] * scale);
            qf[ks][3] = pack_bf16(base[r1 + c + 8] * scale, base[r1 + c + 9] * scale);
        }
    }

    float o[4][4];
#pragma unroll
    for (int nt = 0; nt < 4; nt++)
#pragma unroll
        for (int r = 0; r < 4; r++) o[nt][r] = 0.f;
    float m0 = -1e30f, m1 = -1e30f, l0 = 0.f, l1 = 0.f;

    const int lrow = tid >> 1;          // 0..63
    const int lhalf = tid & 1;          // 0/1 -> fp32 cols 0..15 / 16..31
    const int vkey = lane & 15;         // ldmatrix row key within 16-group
    const int vdimb = (lane >> 4) * 8;  // ldmatrix dim base (0 or 8)

    for (int kt = 0; kt < SEQ; kt += 64) {
        __syncthreads();  // protect previous tile's smem reads
        // load K,V (64 x 32 fp32) -> bf16 smem
        {
            const float* kp = qkv + (size_t)(b * SEQ + kt + lrow) * 768 + 256 + h * 32 + lhalf * 16;
            float4 a0 = *reinterpret_cast<const float4*>(kp);
            float4 a1 = *reinterpret_cast<const float4*>(kp + 4);
            float4 a2 = *reinterpret_cast<const float4*>(kp + 8);
            float4 a3 = *reinterpret_cast<const float4*>(kp + 12);
            uint4* kd = reinterpret_cast<uint4*>(&Ks[lrow * KSR + lhalf * 8]);
            kd[0] = make_uint4(pack_bf16(a0.x, a0.y), pack_bf16(a0.z, a0.w),
                               pack_bf16(a1.x, a1.y), pack_bf16(a1.z, a1.w));
            kd[1] = make_uint4(pack_bf16(a2.x, a2.y), pack_bf16(a2.z, a2.w),
                               pack_bf16(a3.x, a3.y), pack_bf16(a3.z, a3.w));
            const float* vp = kp + 256;
            float4 v0 = *reinterpret_cast<const float4*>(vp);
            float4 v1 = *reinterpret_cast<const float4*>(vp + 4);
            float4 v2 = *reinterpret_cast<const float4*>(vp + 8);
            float4 v3 = *reinterpret_cast<const float4*>(vp + 12);
            uint4* vd = reinterpret_cast<uint4*>(&Vs[lrow * VSR + lhalf * 16]);
            vd[0] = make_uint4(pack_bf16(v0.x, v0.y), pack_bf16(v0.z, v0.w),
                               pack_bf16(v1.x, v1.y), pack_bf16(v1.z, v1.w));
            vd[1] = make_uint4(pack_bf16(v2.x, v2.y), pack_bf16(v2.z, v2.w),
                               pack_bf16(v3.x, v3.y), pack_bf16(v3.z, v3.w));
        }
        __syncthreads();

        // S = Q @ K^T  (per warp: 16 x 64, two k16 steps)
        float s[8][4];
#pragma unroll
        for (int nt = 0; nt < 8; nt++)
#pragma unroll
            for (int r = 0; r < 4; r++) s[nt][r] = 0.f;
#pragma unroll
        for (int ks = 0; ks < 2; ks++) {
            const int kk = ks * 8;
#pragma unroll
            for (int nt = 0; nt < 8; nt++) {
                unsigned bf[2];
                const unsigned* kb = &Ks[(nt * 8 + g) * KSR + kk + t];
                bf[0] = kb[0];
                bf[1] = kb[4];
                mma_bf16(s[nt], qf[ks], bf, s[nt]);
            }
        }

        // online softmax (rows wq+g and wq+g+8)
        float r0 = s[0][0], r1 = s[0][2];
#pragma unroll
        for (int nt = 0; nt < 8; nt++) {
            r0 = fmaxf(r0, fmaxf(s[nt][0], s[nt][1]));
            r1 = fmaxf(r1, fmaxf(s[nt][2], s[nt][3]));
        }
        r0 = fmaxf(r0, __shfl_xor_sync(0xffffffffu, r0, 1));
        r0 = fmaxf(r0, __shfl_xor_sync(0xffffffffu, r0, 2));
        r1 = fmaxf(r1, __shfl_xor_sync(0xffffffffu, r1, 1));
        r1 = fmaxf(r1, __shfl_xor_sync(0xffffffffu, r1, 2));

        const float m0n = fmaxf(m0, r0);
        const float m1n = fmaxf(m1, r1);
        const float c0 = __expf(m0 - m0n);
        const float c1 = __expf(m1 - m1n);

        float sum0 = 0.f, sum1 = 0.f;
#pragma unroll
        for (int nt = 0; nt < 8; nt++) {
            s[nt][0] = __expf(s[nt][0] - m0n);
            s[nt][1] = __expf(s[nt][1] - m0n);
            s[nt][2] = __expf(s[nt][2] - m1n);
            s[nt][3] = __expf(s[nt][3] - m1n);
            sum0 += s[nt][0] + s[nt][1];
            sum1 += s[nt][2] + s[nt][3];
        }
        sum0 += __shfl_xor_sync(0xffffffffu, sum0, 1);
        sum0 += __shfl_xor_sync(0xffffffffu, sum0, 2);
        sum1 += __shfl_xor_sync(0xffffffffu, sum1, 1);
        sum1 += __shfl_xor_sync(0xffffffffu, sum1, 2);
        l0 = l0 * c0 + sum0;
        l1 = l1 * c1 + sum1;
        m0 = m0n; m1 = m1n;

#pragma unroll
        for (int nt = 0; nt < 4; nt++) {
            o[nt][0] *= c0; o[nt][1] *= c0;
            o[nt][2] *= c1; o[nt][3] *= c1;
        }

        // O += P @ V  (per warp: 16 x 32, four k16 steps over keys)
        // P A-fragments come straight from the S accumulators (FA2 trick).
#pragma unroll
        for (int ks = 0; ks < 4; ks++) {
            unsigned af[4];
            af[0] = pack_bf16(s[2 * ks][0],     s[2 * ks][1]);
            af[1] = pack_bf16(s[2 * ks][2],     s[2 * ks][3]);
            af[2] = pack_bf16(s[2 * ks + 1][0], s[2 * ks + 1][1]);
            af[3] = pack_bf16(s[2 * ks + 1][2], s[2 * ks + 1][3]);

            unsigned vaddr = (unsigned)__cvta_generic_to_shared(
                &Vs[(ks * 16 + vkey) * VSR + vdimb]);
            unsigned v0, v1, v2, v3, v4, v5, v6, v7;
            ldmatrix_x4_trans(v0, v1, v2, v3, vaddr);        // dims 0..15
            ldmatrix_x4_trans(v4, v5, v6, v7, vaddr + 32);   // dims 16..31

            unsigned bf[2];
            bf[0] = v0; bf[1] = v1; mma_bf16(o[0], af, bf, o[0]);
            bf[0] = v2; bf[1] = v3; mma_bf16(o[1], af, bf, o[1]);
            bf[0] = v4; bf[1] = v5; mma_bf16(o[2], af, bf, o[2]);
            bf[0] = v6; bf[1] = v7; mma_bf16(o[3], af, bf, o[3]);
        }
    }

    const float inv0 = 1.f / l0;
    const float inv1 = 1.f / l1;
    unsigned* op = out + (size_t)(b * SEQ) * 128 + h * 16;
    const int row0 = q0 + wq + g;
#pragma unroll
    for (int nt = 0; nt < 4; nt++) {
        const int cu = nt * 4 + t;
        op[(size_t)(row0    ) * 128 + cu] = pack_bf16(o[nt][0] * inv0, o[nt][1] * inv0);
        op[(size_t)(row0 + 8) * 128 + cu] = pack_bf16(o[nt][2] * inv1, o[nt][3] * inv1);
    }
}

// ---------------- local attention: 4 heads, hd=64, window 5 (bf16 out) ----------
__global__ void __launch_bounds__(128)
local_attn_kernel(const float* __restrict__ qkv, __nv_bfloat16* __restrict__ out)
{
    const int n = blockIdx.x;
    const int b = n / SEQ;
    const int s = n % SEQ;
    const int h = threadIdx.x >> 5;
    const int lane = threadIdx.x & 31;

    const size_t qb = (size_t)n * 768 + h * 64;
    const float q0 = qkv[qb + lane];
    const float q1 = qkv[qb + 32 + lane];

    float sc[5];
#pragma unroll
    for (int wo = 0; wo < 5; wo++) {
        const int j = s + wo - 2;
        if (j >= 0 && j < SEQ) {
            const size_t kb = (size_t)(b * SEQ + j) * 768 + 256 + h * 64;
            float part = q0 * qkv[kb + lane] + q1 * qkv[kb + 32 + lane];
#pragma unroll
            for (int o = 16; o > 0; o >>= 1) part += __shfl_xor_sync(0xffffffffu, part, o);
            sc[wo] = part * 0.125f;
        } else {
            sc[wo] = -1e30f;
        }
    }
    float mx = sc[0];
#pragma unroll
    for (int wo = 1; wo < 5; wo++) mx = fmaxf(mx, sc[wo]);
    float p[5], lsum = 0.f;
#pragma unroll
    for (int wo = 0; wo < 5; wo++) {
        p[wo] = (sc[wo] > -1e29f) ? __expf(sc[wo] - mx) : 0.f;
        lsum += p[wo];
    }
    float o0 = 0.f, o1 = 0.f;
#pragma unroll
    for (int wo = 0; wo < 5; wo++) {
        const int j = s + wo - 2;
        if (j >= 0 && j < SEQ) {
            const size_t vb = (size_t)(b * SEQ + j) * 768 + 512 + h * 64;
            o0 += p[wo] * qkv[vb + lane];
            o1 += p[wo] * qkv[vb + 32 + lane];
        }
    }
    const float inv = 1.f / lsum;
    out[(size_t)n * 256 + h * 64 + lane]      = __float2bfloat16(o0 * inv);
    out[(size_t)n * 256 + h * 64 + 32 + lane] = __float2bfloat16(o1 * inv);
}

// ---------------- residual add + LayerNorm (optional bf16 twin) ------------------
template <bool WB16>
__global__ void __launch_bounds__(256)
add_ln_kernel(const float* __restrict__ x, const float* __restrict__ dx,
              const float* __restrict__ g, const float* __restrict__ bb,
              float* __restrict__ out, unsigned* __restrict__ outb)
{
    const int n = blockIdx.x;
    const int d = threadIdx.x;
    const float v = x[(size_t)n * 256 + d] + dx[(size_t)n * 256 + d];
    float s1 = v, s2 = v * v;
#pragma unroll
    for (int o = 16; o > 0; o >>= 1) {
        s1 += __shfl_xor_sync(0xffffffffu, s1, o);
        s2 += __shfl_xor_sync(0xffffffffu, s2, o);
    }
    __shared__ float r1[8], r2[8];
    const int wid = d >> 5, lane = d & 31;
    if (lane == 0) { r1[wid] = s1; r2[wid] = s2; }
    __syncthreads();
    if (wid == 0) {
        float a = (lane < 8) ? r1[lane] : 0.f;
        float c = (lane < 8) ? r2[lane] : 0.f;
#pragma unroll
        for (int o = 4; o > 0; o >>= 1) {
            a += __shfl_xor_sync(0xffffffffu, a, o);
            c += __shfl_xor_sync(0xffffffffu, c, o);
        }
        if (lane == 0) { r1[0] = a; r2[0] = c; }
    }
    __syncthreads();
    const float mu = r1[0] * (1.f / 256.f);
    const float var = r2[0] * (1.f / 256.f) - mu * mu;
    const float vn = (v - mu) * rsqrtf(var + 1e-5f) * g[d] + bb[d];
    out[(size_t)n * 256 + d] = vn;
    if (WB16) {
        const float hi = __shfl_down_sync(0xffffffffu, vn, 1);
        if ((d & 1) == 0) outb[(size_t)n * 128 + (d >> 1)] = pack_bf16(vn, hi);
    }
}

// ---------------- launch ---------------------------------------------------------
extern "C" void kernel_launch(void* const* d_in, const int* in_sizes, int n_in,
                              void* d_out, int out_size)
{
    const float* x      = (const float*)d_in[0];
    const float* g_in_w = (const float*)d_in[1];
    const float* g_in_b = (const float*)d_in[2];
    const float* g_out_w= (const float*)d_in[3];
    const float* g_out_b= (const float*)d_in[4];
    const float* t_in_w = (const float*)d_in[5];
    const float* t_in_b = (const float*)d_in[6];
    const float* t_out_w= (const float*)d_in[7];
    const float* t_out_b= (const float*)d_in[8];
    const float* fus_w1 = (const float*)d_in[9];
    const float* fus_b1 = (const float*)d_in[10];
    const float* fus_w2 = (const float*)d_in[11];
    const float* fus_b2 = (const float*)d_in[12];
    const float* ffn_w1 = (const float*)d_in[13];
    const float* ffn_b1 = (const float*)d_in[14];
    const float* ffn_w2 = (const float*)d_in[15];
    const float* ffn_b2 = (const float*)d_in[16];
    const float* gn_g   = (const float*)d_in[17];
    const float* gn_b   = (const float*)d_in[18];
    const float* fn_g   = (const float*)d_in[19];
    const float* fn_b   = (const float*)d_in[20];

    float *gqkv, *tqkv, *xfu, *h1, *xff;
    unsigned *gat, *tat, *comb, *fush, *h1b, *ffh, *wbf;
    cudaGetSymbolAddress((void**)&gqkv, g_qkv_buf);
    cudaGetSymbolAddress((void**)&tqkv, t_qkv_buf);
    cudaGetSymbolAddress((void**)&gat,  gat_buf);
    cudaGetSymbolAddress((void**)&tat,  tat_buf);
    cudaGetSymbolAddress((void**)&comb, comb_buf);
    cudaGetSymbolAddress((void**)&fush, fush_buf);
    cudaGetSymbolAddress((void**)&xfu,  xfused_buf);
    cudaGetSymbolAddress((void**)&h1,   h1_buf);
    cudaGetSymbolAddress((void**)&h1b,  h1b_buf);
    cudaGetSymbolAddress((void**)&ffh,  ffnh_buf);
    cudaGetSymbolAddress((void**)&xff,  xffn_buf);
    cudaGetSymbolAddress((void**)&wbf,  wbf_buf);

    const __nv_bfloat16* wb = (const __nv_bfloat16*)wbf;

    // 0) weights fp32 -> bf16 (once per launch; graph-capturable kernel)
    convert_weights_kernel<<<1152, 256>>>(g_in_w, t_in_w, g_out_w, t_out_w,
                                          fus_w1, fus_w2, ffn_w1, ffn_w2, wbf);

    // 1) merged QKV projections (A fp32, C fp32)
    tgemm_kernel<false, false, false><<<dim3(12, 64), 256, GSMEM_BYTES>>>(
        x, wb + WOFF_GIN, g_in_b, gqkv,
        x, wb + WOFF_TIN, t_in_b, tqkv, 6, 256, 768);

    // 2) attention (outputs bf16)
    flash_global_attn<<<dim3(SEQ / 64, 8, 4), 128>>>(gqkv, gat);
    local_attn_kernel<<<NTOK, 128>>>(tqkv, (__nv_bfloat16*)tat);

    // 3) merged output projections -> comb (bf16), [global | local]
    tgemm_kernel<false, true, true><<<dim3(4, 64), 256, GSMEM_BYTES>>>(
        gat, wb + WOFF_GOUT, g_out_b, comb,
        tat, wb + WOFF_TOUT, t_out_b, comb + 128, 2, 256, 512);

    // 4) fusion MLP
    tgemm_kernel<true, true, true><<<dim3(4, 64), 256, GSMEM_BYTES>>>(
        comb, wb + WOFF_FUS1, fus_b1, fush,
        comb, wb + WOFF_FUS1, fus_b1, fush, 4, 512, 512);
    tgemm_kernel<false, true, false><<<dim3(2, 64), 256, GSMEM_BYTES>>>(
        fush, wb + WOFF_FUS2, fus_b2, xfu,
        fush, wb + WOFF_FUS2, fus_b2, xfu, 2, 512, 256);

    // 5) residual + LN (fp32 out + bf16 twin)
    add_ln_kernel<true><<<NTOK, 256>>>(x, xfu, gn_g, gn_b, h1, h1b);

    // 6) FFN
    tgemm_kernel<true, true, true><<<dim3(4, 64), 256, GSMEM_BYTES>>>(
        h1b, wb + WOFF_FFN1, ffn_b1, ffh,
        h1b, wb + WOFF_FFN1, ffn_b1, ffh, 4, 256, 512);
    tgemm_kernel<false, true, false><<<dim3(2, 64), 256, GSMEM_BYTES>>>(
        ffh, wb + WOFF_FFN2, ffn_b2, xff,
        ffh, wb + WOFF_FFN2, ffn_b2, xff, 2, 512, 256);

    // 7) final residual + LN -> output (fp32)
    add_ln_kernel<false><<<NTOK, 256>>>(h1, xff, fn_g, fn_b, (float*)d_out, nullptr);
}

// round 16
// speedup vs baseline: 4.9296x; 1.1240x over previous
#include <cuda_runtime.h>
#include <cuda_bf16.h>
#include <math.h>

#define NTOK 8192
#define SEQ 2048

// ---------------- scratch (static device globals; no allocation) ----------------
__device__ unsigned g_qkv_buf[NTOK * 384];  // bf16x2 (768 bf16/row)
__device__ unsigned t_qkv_buf[NTOK * 384];  // bf16x2
__device__ unsigned gat_buf[NTOK * 128];    // bf16x2
__device__ unsigned tat_buf[NTOK * 128];    // bf16x2
__device__ unsigned comb_buf[NTOK * 256];   // bf16x2 (512 bf16/row)
__device__ unsigned fush_buf[NTOK * 256];   // bf16x2
__device__ float    xfused_buf[NTOK * 256];
__device__ float    h1_buf[NTOK * 256];
__device__ unsigned h1b_buf[NTOK * 128];    // bf16x2 copy of h1
__device__ unsigned ffnh_buf[NTOK * 256];   // bf16x2
__device__ float    xffn_buf[NTOK * 256];
__device__ unsigned wbf_buf[589824];        // all weights as bf16x2

// weight offsets (in bf16 elements) inside wbf_buf
#define WOFF_GIN   0
#define WOFF_TIN   196608
#define WOFF_GOUT  393216
#define WOFF_TOUT  458752
#define WOFF_FUS1  524288
#define WOFF_FUS2  786432
#define WOFF_FFN1  917504
#define WOFF_FFN2  1048576

// ---------------- helpers ---------------------------------------------------------
__device__ __forceinline__ unsigned pack_bf16(float lo, float hi) {
    unsigned r;
    asm("cvt.rn.bf16x2.f32 %0, %1, %2;" : "=r"(r) : "f"(hi), "f"(lo));
    return r;
}
__device__ __forceinline__ void mma_bf16(float* d, const unsigned* a, const unsigned* b,
                                         const float* c) {
    asm("mma.sync.aligned.m16n8k16.row.col.f32.bf16.bf16.f32 "
        "{%0,%1,%2,%3},{%4,%5,%6,%7},{%8,%9},{%10,%11,%12,%13};"
        : "=f"(d[0]), "=f"(d[1]), "=f"(d[2]), "=f"(d[3])
        : "r"(a[0]), "r"(a[1]), "r"(a[2]), "r"(a[3]),
          "r"(b[0]), "r"(b[1]),
          "f"(c[0]), "f"(c[1]), "f"(c[2]), "f"(c[3]));
}
__device__ __forceinline__ void ldmatrix_x4_trans(unsigned& r0, unsigned& r1,
                                                  unsigned& r2, unsigned& r3,
                                                  unsigned saddr) {
    asm volatile("ldmatrix.sync.aligned.m8n8.x4.trans.shared.b16 {%0,%1,%2,%3}, [%4];"
                 : "=r"(r0), "=r"(r1), "=r"(r2), "=r"(r3) : "r"(saddr));
}
__device__ __forceinline__ void cp_async16(void* smem, const void* gptr) {
    unsigned saddr = (unsigned)__cvta_generic_to_shared(smem);
    asm volatile("cp.async.ca.shared.global [%0], [%1], 16;" :: "r"(saddr), "l"(gptr));
}
#define CP_COMMIT()  asm volatile("cp.async.commit_group;")
#define CP_WAIT0()   asm volatile("cp.async.wait_group 0;")
#define CP_WAIT1()   asm volatile("cp.async.wait_group 1;")

// ---------------- weight fp32 -> bf16 conversion ---------------------------------
__global__ void __launch_bounds__(256)
convert_weights_kernel(const float* __restrict__ s0, const float* __restrict__ s1,
                       const float* __restrict__ s2, const float* __restrict__ s3,
                       const float* __restrict__ s4, const float* __restrict__ s5,
                       const float* __restrict__ s6, const float* __restrict__ s7,
                       unsigned* __restrict__ dst)
{
    const int i4 = blockIdx.x * 256 + threadIdx.x;
    const int e = i4 * 4;
    const float* src; int base;
    if      (e < 196608)  { src = s0; base = 0; }
    else if (e < 393216)  { src = s1; base = 196608; }
    else if (e < 458752)  { src = s2; base = 393216; }
    else if (e < 524288)  { src = s3; base = 458752; }
    else if (e < 786432)  { src = s4; base = 524288; }
    else if (e < 917504)  { src = s5; base = 786432; }
    else if (e < 1048576) { src = s6; base = 917504; }
    else                  { src = s7; base = 1048576; }
    float4 v = *reinterpret_cast<const float4*>(src + (e - base));
    uint2 o; o.x = pack_bf16(v.x, v.y); o.y = pack_bf16(v.z, v.w);
    *reinterpret_cast<uint2*>(dst + i4 * 2) = o;
}

// ---------------- BF16 dual-source cp.async GEMM ---------------------------------
#define SMH 20
#define GT (128 * SMH)
#define GSMEM_BYTES (4 * GT * 4)   // 40960 B
template <bool SILU, bool ABF16, bool CBF16>
__global__ void __launch_bounds__(256, 2)
tgemm_kernel(const void* __restrict__ A1_, const __nv_bfloat16* __restrict__ W1,
             const float* __restrict__ b1, void* __restrict__ C1_,
             const void* __restrict__ A2_, const __nv_bfloat16* __restrict__ W2,
             const float* __restrict__ b2, void* __restrict__ C2_,
             int split, int K, int ldc)
{
    extern __shared__ unsigned sm[];
    unsigned* As = sm;
    unsigned* Bs = sm + 2 * GT;

    const int tid = threadIdx.x;
    const int bm = blockIdx.y * 128;

    const void* A_; const __nv_bfloat16* W; const float* bias; void* C_;
    int bn;
    if ((int)blockIdx.x < split) { A_ = A1_; W = W1; bias = b1; C_ = C1_; bn = blockIdx.x * 128; }
    else { A_ = A2_; W = W2; bias = b2; C_ = C2_; bn = (blockIdx.x - split) * 128; }

    const int warp = tid >> 5, lane = tid & 31;
    const int wm = (warp & 3) * 32, wn = (warp >> 2) * 64;
    const int g = lane >> 2, t = lane & 3;
    const int lrow = tid >> 1, lhalf = tid & 1;

    const __nv_bfloat16* wrow = W + (size_t)(bn + lrow) * K + lhalf * 16;
    const __nv_bfloat16* arb = (const __nv_bfloat16*)A_ + (size_t)(bm + lrow) * K + lhalf * 16;
    const float* arf = (const float*)A_ + (size_t)(bm + lrow) * K + lhalf * 16;

    unsigned* asw = &As[lrow * SMH + lhalf * 8];
    unsigned* bsw = &Bs[lrow * SMH + lhalf * 8];

    float acc[2][8][4];
#pragma unroll
    for (int mt = 0; mt < 2; mt++)
#pragma unroll
        for (int nt = 0; nt < 8; nt++)
#pragma unroll
            for (int r = 0; r < 4; r++) acc[mt][nt][r] = 0.f;

    unsigned ra[8];
    const int ntiles = K >> 5;

    // prologue: tiles 0 and 1
    if (ABF16) {
        cp_async16(asw, arb);            cp_async16(asw + 4, arb + 8);
        cp_async16(bsw, wrow);           cp_async16(bsw + 4, wrow + 8);
        CP_COMMIT();
        cp_async16(asw + GT, arb + 32);  cp_async16(asw + GT + 4, arb + 40);
        cp_async16(bsw + GT, wrow + 32); cp_async16(bsw + GT + 4, wrow + 40);
        CP_COMMIT();
    } else {
#pragma unroll
        for (int i = 0; i < 4; i++) {
            float4 av = *reinterpret_cast<const float4*>(arf + i * 4);
            ra[2 * i]     = pack_bf16(av.x, av.y);
            ra[2 * i + 1] = pack_bf16(av.z, av.w);
        }
        cp_async16(bsw, wrow);           cp_async16(bsw + 4, wrow + 8);
        CP_COMMIT();
        cp_async16(bsw + GT, wrow + 32); cp_async16(bsw + GT + 4, wrow + 40);
        CP_COMMIT();
    }

    for (int kt = 0; kt < ntiles; kt++) {
        const int st = kt & 1;
        unsigned* as = As + st * GT;
        unsigned* bs = Bs + st * GT;

        if (!ABF16) {
            uint4* da = reinterpret_cast<uint4*>(asw + st * GT);
            da[0] = make_uint4(ra[0], ra[1], ra[2], ra[3]);
            da[1] = make_uint4(ra[4], ra[5], ra[6], ra[7]);
        }
        CP_WAIT1();
        __syncthreads();

        if (!ABF16 && kt + 1 < ntiles) {
            const float* p = arf + (kt + 1) * 32;
#pragma unroll
            for (int i = 0; i < 4; i++) {
                float4 av = *reinterpret_cast<const float4*>(p + i * 4);
                ra[2 * i]     = pack_bf16(av.x, av.y);
                ra[2 * i + 1] = pack_bf16(av.z, av.w);
            }
        }

#pragma unroll
        for (int s = 0; s < 2; s++) {
            const int kk = s * 8;
            unsigned af[2][4];
#pragma unroll
            for (int mt = 0; mt < 2; mt++) {
                const int r0 = wm + mt * 16 + g;
                af[mt][0] = as[(r0    ) * SMH + kk + t];
                af[mt][1] = as[(r0 + 8) * SMH + kk + t];
                af[mt][2] = as[(r0    ) * SMH + kk + t + 4];
                af[mt][3] = as[(r0 + 8) * SMH + kk + t + 4];
            }
            unsigned bf[8][2];
#pragma unroll
            for (int nt = 0; nt < 8; nt++) {
                const int n0 = wn + nt * 8 + g;
                bf[nt][0] = bs[n0 * SMH + kk + t];
                bf[nt][1] = bs[n0 * SMH + kk + t + 4];
            }
#pragma unroll
            for (int mt = 0; mt < 2; mt++)
#pragma unroll
                for (int nt = 0; nt < 8; nt++)
                    mma_bf16(acc[mt][nt], af[mt], bf[nt], acc[mt][nt]);
        }
        __syncthreads();

        if (kt + 2 < ntiles) {
            const int off = (kt + 2) * 32;
            if (ABF16) {
                cp_async16(asw + st * GT, arb + off);
                cp_async16(asw + st * GT + 4, arb + off + 8);
            }
            cp_async16(bsw + st * GT, wrow + off);
            cp_async16(bsw + st * GT + 4, wrow + off + 8);
        }
        CP_COMMIT();
    }

    // epilogue: bias (+SiLU)
#pragma unroll
    for (int mt = 0; mt < 2; mt++) {
#pragma unroll
        for (int nt = 0; nt < 8; nt++) {
            const int col = bn + wn + nt * 8 + 2 * t;
            const float b0 = bias[col], bb1 = bias[col + 1];
#pragma unroll
            for (int h = 0; h < 2; h++) {
                const int row = bm + wm + mt * 16 + g + h * 8;
                float v0 = acc[mt][nt][2 * h] + b0;
                float v1 = acc[mt][nt][2 * h + 1] + bb1;
                if (SILU) {
                    v0 = v0 / (1.f + __expf(-v0));
                    v1 = v1 / (1.f + __expf(-v1));
                }
                if (CBF16) {
                    ((unsigned*)C_)[((size_t)row * ldc + col) >> 1] = pack_bf16(v0, v1);
                } else {
                    float2 o; o.x = v0; o.y = v1;
                    *reinterpret_cast<float2*>((float*)C_ + (size_t)row * ldc + col) = o;
                }
            }
        }
    }
}

// ---------------- flash global attention (bf16 mma, FA2-style, bf16 qkv) --------
// One block = one (b,h) x 64 queries; 4 warps x 16 query rows; 64-key tiles.
// qkv is bf16 (768/row). K/V tiles loaded by pure cp.async (no cvt).
// S = Q@K^T m16n8k16; P re-packed from S accumulators; P@V via ldmatrix.trans.
#define KSR 20   // u32 (bf16-pair) stride per K row
#define VSR 40   // bf16 stride per V row
__global__ void __launch_bounds__(128)
flash_global_attn(const unsigned* __restrict__ qkv, unsigned* __restrict__ out)
{
    __shared__ unsigned Ks[64 * KSR];
    __shared__ unsigned short Vs[64 * VSR];

    const int tid = threadIdx.x;
    const int warp = tid >> 5;
    const int lane = tid & 31;
    const int g = lane >> 2;
    const int t = lane & 3;
    const int h = blockIdx.y;
    const int b = blockIdx.z;
    const int q0 = blockIdx.x * 64;
    const int wq = warp * 16;

    // Q fragments: load bf16 pairs, unpack, scale, repack
    const float scale = 0.17677669529663687f;  // 1/sqrt(32)
    unsigned qf[2][4];
    {
        const size_t r0 = (size_t)(b * SEQ + q0 + wq + g) * 384 + h * 16;
        const size_t r1 = r0 + 8 * 384;
#pragma unroll
        for (int ks = 0; ks < 2; ks++) {
            const int c = ks * 8 + t;   // u32 index within the 16-u32 head row
            unsigned u00 = qkv[r0 + c],     u10 = qkv[r1 + c];
            unsigned u01 = qkv[r0 + c + 4], u11 = qkv[r1 + c + 4];
            qf[ks][0] = pack_bf16(__uint_as_float(u00 << 16) * scale,
                                  __uint_as_float(u00 & 0xffff0000u) * scale);
            qf[ks][1] = pack_bf16(__uint_as_float(u10 << 16) * scale,
                                  __uint_as_float(u10 & 0xffff0000u) * scale);
            qf[ks][2] = pack_bf16(__uint_as_float(u01 << 16) * scale,
                                  __uint_as_float(u01 & 0xffff0000u) * scale);
            qf[ks][3] = pack_bf16(__uint_as_float(u11 << 16) * scale,
                                  __uint_as_float(u11 & 0xffff0000u) * scale);
        }
    }

    float o[4][4];
#pragma unroll
    for (int nt = 0; nt < 4; nt++)
#pragma unroll
        for (int r = 0; r < 4; r++) o[nt][r] = 0.f;
    float m0 = -1e30f, m1 = -1e30f, l0 = 0.f, l1 = 0.f;

    const int lrow = tid >> 1;          // 0..63
    const int lhalf = tid & 1;          // 0/1 -> u32 cols 0..7 / 8..15
    const int vkey = lane & 15;
    const int vdimb = (lane >> 4) * 8;

    for (int kt = 0; kt < SEQ; kt += 64) {
        __syncthreads();  // protect previous tile's smem reads
        // cp.async K,V tile (64 rows x 16 u32 each), bf16 straight through
        {
            const unsigned* kp = qkv + (size_t)(b * SEQ + kt + lrow) * 384 + 128 + h * 16 + lhalf * 8;
            cp_async16(&Ks[lrow * KSR + lhalf * 8], kp);
            cp_async16(&Ks[lrow * KSR + lhalf * 8 + 4], kp + 4);
            const unsigned* vp = kp + 128;
            unsigned* vd = reinterpret_cast<unsigned*>(&Vs[lrow * VSR + lhalf * 16]);
            cp_async16(vd, vp);
            cp_async16(vd + 4, vp + 4);
        }
        CP_COMMIT();
        CP_WAIT0();
        __syncthreads();

        // S = Q @ K^T  (per warp: 16 x 64, two k16 steps)
        float s[8][4];
#pragma unroll
        for (int nt = 0; nt < 8; nt++)
#pragma unroll
            for (int r = 0; r < 4; r++) s[nt][r] = 0.f;
#pragma unroll
        for (int ks = 0; ks < 2; ks++) {
            const int kk = ks * 8;
#pragma unroll
            for (int nt = 0; nt < 8; nt++) {
                unsigned bf[2];
                const unsigned* kb = &Ks[(nt * 8 + g) * KSR + kk + t];
                bf[0] = kb[0];
                bf[1] = kb[4];
                mma_bf16(s[nt], qf[ks], bf, s[nt]);
            }
        }

        // online softmax (rows wq+g and wq+g+8)
        float r0 = s[0][0], r1 = s[0][2];
#pragma unroll
        for (int nt = 0; nt < 8; nt++) {
            r0 = fmaxf(r0, fmaxf(s[nt][0], s[nt][1]));
            r1 = fmaxf(r1, fmaxf(s[nt][2], s[nt][3]));
        }
        r0 = fmaxf(r0, __shfl_xor_sync(0xffffffffu, r0, 1));
        r0 = fmaxf(r0, __shfl_xor_sync(0xffffffffu, r0, 2));
        r1 = fmaxf(r1, __shfl_xor_sync(0xffffffffu, r1, 1));
        r1 = fmaxf(r1, __shfl_xor_sync(0xffffffffu, r1, 2));

        const float m0n = fmaxf(m0, r0);
        const float m1n = fmaxf(m1, r1);
        const float c0 = __expf(m0 - m0n);
        const float c1 = __expf(m1 - m1n);

        float sum0 = 0.f, sum1 = 0.f;
#pragma unroll
        for (int nt = 0; nt < 8; nt++) {
            s[nt][0] = __expf(s[nt][0] - m0n);
            s[nt][1] = __expf(s[nt][1] - m0n);
            s[nt][2] = __expf(s[nt][2] - m1n);
            s[nt][3] = __expf(s[nt][3] - m1n);
            sum0 += s[nt][0] + s[nt][1];
            sum1 += s[nt][2] + s[nt][3];
        }
        sum0 += __shfl_xor_sync(0xffffffffu, sum0, 1);
        sum0 += __shfl_xor_sync(0xffffffffu, sum0, 2);
        sum1 += __shfl_xor_sync(0xffffffffu, sum1, 1);
        sum1 += __shfl_xor_sync(0xffffffffu, sum1, 2);
        l0 = l0 * c0 + sum0;
        l1 = l1 * c1 + sum1;
        m0 = m0n; m1 = m1n;

#pragma unroll
        for (int nt = 0; nt < 4; nt++) {
            o[nt][0] *= c0; o[nt][1] *= c0;
            o[nt][2] *= c1; o[nt][3] *= c1;
        }

        // O += P @ V  (per warp: 16 x 32, four k16 steps over keys)
#pragma unroll
        for (int ks = 0; ks < 4; ks++) {
            unsigned af[4];
            af[0] = pack_bf16(s[2 * ks][0],     s[2 * ks][1]);
            af[1] = pack_bf16(s[2 * ks][2],     s[2 * ks][3]);
            af[2] = pack_bf16(s[2 * ks + 1][0], s[2 * ks + 1][1]);
            af[3] = pack_bf16(s[2 * ks + 1][2], s[2 * ks + 1][3]);

            unsigned vaddr = (unsigned)__cvta_generic_to_shared(
                &Vs[(ks * 16 + vkey) * VSR + vdimb]);
            unsigned v0, v1, v2, v3, v4, v5, v6, v7;
            ldmatrix_x4_trans(v0, v1, v2, v3, vaddr);        // dims 0..15
            ldmatrix_x4_trans(v4, v5, v6, v7, vaddr + 32);   // dims 16..31

            unsigned bf[2];
            bf[0] = v0; bf[1] = v1; mma_bf16(o[0], af, bf, o[0]);
            bf[0] = v2; bf[1] = v3; mma_bf16(o[1], af, bf, o[1]);
            bf[0] = v4; bf[1] = v5; mma_bf16(o[2], af, bf, o[2]);
            bf[0] = v6; bf[1] = v7; mma_bf16(o[3], af, bf, o[3]);
        }
    }

    const float inv0 = 1.f / l0;
    const float inv1 = 1.f / l1;
    unsigned* op = out + (size_t)(b * SEQ) * 128 + h * 16;
    const int row0 = q0 + wq + g;
#pragma unroll
    for (int nt = 0; nt < 4; nt++) {
        const int cu = nt * 4 + t;
        op[(size_t)(row0    ) * 128 + cu] = pack_bf16(o[nt][0] * inv0, o[nt][1] * inv0);
        op[(size_t)(row0 + 8) * 128 + cu] = pack_bf16(o[nt][2] * inv1, o[nt][3] * inv1);
    }
}

// ---------------- local attention: 4 heads, hd=64, window 5 (bf16 in/out) -------
__global__ void __launch_bounds__(128)
local_attn_kernel(const __nv_bfloat16* __restrict__ qkv, __nv_bfloat16* __restrict__ out)
{
    const int n = blockIdx.x;
    const int b = n / SEQ;
    const int s = n % SEQ;
    const int h = threadIdx.x >> 5;
    const int lane = threadIdx.x & 31;

    const size_t qb = (size_t)n * 768 + h * 64;
    const float q0 = __bfloat162float(qkv[qb + lane]);
    const float q1 = __bfloat162float(qkv[qb + 32 + lane]);

    float sc[5];
#pragma unroll
    for (int wo = 0; wo < 5; wo++) {
        const int j = s + wo - 2;
        if (j >= 0 && j < SEQ) {
            const size_t kb = (size_t)(b * SEQ + j) * 768 + 256 + h * 64;
            float part = q0 * __bfloat162float(qkv[kb + lane])
                       + q1 * __bfloat162float(qkv[kb + 32 + lane]);
#pragma unroll
            for (int o = 16; o > 0; o >>= 1) part += __shfl_xor_sync(0xffffffffu, part, o);
            sc[wo] = part * 0.125f;
        } else {
            sc[wo] = -1e30f;
        }
    }
    float mx = sc[0];
#pragma unroll
    for (int wo = 1; wo < 5; wo++) mx = fmaxf(mx, sc[wo]);
    float p[5], lsum = 0.f;
#pragma unroll
    for (int wo = 0; wo < 5; wo++) {
        p[wo] = (sc[wo] > -1e29f) ? __expf(sc[wo] - mx) : 0.f;
        lsum += p[wo];
    }
    float o0 = 0.f, o1 = 0.f;
#pragma unroll
    for (int wo = 0; wo < 5; wo++) {
        const int j = s + wo - 2;
        if (j >= 0 && j < SEQ) {
            const size_t vb = (size_t)(b * SEQ + j) * 768 + 512 + h * 64;
            o0 += p[wo] * __bfloat162float(qkv[vb + lane]);
            o1 += p[wo] * __bfloat162float(qkv[vb + 32 + lane]);
        }
    }
    const float inv = 1.f / lsum;
    out[(size_t)n * 256 + h * 64 + lane]      = __float2bfloat16(o0 * inv);
    out[(size_t)n * 256 + h * 64 + 32 + lane] = __float2bfloat16(o1 * inv);
}

// ---------------- residual add + LayerNorm (optional bf16 twin) ------------------
template <bool WB16>
__global__ void __launch_bounds__(256)
add_ln_kernel(const float* __restrict__ x, const float* __restrict__ dx,
              const float* __restrict__ g, const float* __restrict__ bb,
              float* __restrict__ out, unsigned* __restrict__ outb)
{
    const int n = blockIdx.x;
    const int d = threadIdx.x;
    const float v = x[(size_t)n * 256 + d] + dx[(size_t)n * 256 + d];
    float s1 = v, s2 = v * v;
#pragma unroll
    for (int o = 16; o > 0; o >>= 1) {
        s1 += __shfl_xor_sync(0xffffffffu, s1, o);
        s2 += __shfl_xor_sync(0xffffffffu, s2, o);
    }
    __shared__ float r1[8], r2[8];
    const int wid = d >> 5, lane = d & 31;
    if (lane == 0) { r1[wid] = s1; r2[wid] = s2; }
    __syncthreads();
    if (wid == 0) {
        float a = (lane < 8) ? r1[lane] : 0.f;
        float c = (lane < 8) ? r2[lane] : 0.f;
#pragma unroll
        for (int o = 4; o > 0; o >>= 1) {
            a += __shfl_xor_sync(0xffffffffu, a, o);
            c += __shfl_xor_sync(0xffffffffu, c, o);
        }
        if (lane == 0) { r1[0] = a; r2[0] = c; }
    }
    __syncthreads();
    const float mu = r1[0] * (1.f / 256.f);
    const float var = r2[0] * (1.f / 256.f) - mu * mu;
    const float vn = (v - mu) * rsqrtf(var + 1e-5f) * g[d] + bb[d];
    out[(size_t)n * 256 + d] = vn;
    if (WB16) {
        const float hi = __shfl_down_sync(0xffffffffu, vn, 1);
        if ((d & 1) == 0) outb[(size_t)n * 128 + (d >> 1)] = pack_bf16(vn, hi);
    }
}

// ---------------- launch ---------------------------------------------------------
extern "C" void kernel_launch(void* const* d_in, const int* in_sizes, int n_in,
                              void* d_out, int out_size)
{
    const float* x      = (const float*)d_in[0];
    const float* g_in_w = (const float*)d_in[1];
    const float* g_in_b = (const float*)d_in[2];
    const float* g_out_w= (const float*)d_in[3];
    const float* g_out_b= (const float*)d_in[4];
    const float* t_in_w = (const float*)d_in[5];
    const float* t_in_b = (const float*)d_in[6];
    const float* t_out_w= (const float*)d_in[7];
    const float* t_out_b= (const float*)d_in[8];
    const float* fus_w1 = (const float*)d_in[9];
    const float* fus_b1 = (const float*)d_in[10];
    const float* fus_w2 = (const float*)d_in[11];
    const float* fus_b2 = (const float*)d_in[12];
    const float* ffn_w1 = (const float*)d_in[13];
    const float* ffn_b1 = (const float*)d_in[14];
    const float* ffn_w2 = (const float*)d_in[15];
    const float* ffn_b2 = (const float*)d_in[16];
    const float* gn_g   = (const float*)d_in[17];
    const float* gn_b   = (const float*)d_in[18];
    const float* fn_g   = (const float*)d_in[19];
    const float* fn_b   = (const float*)d_in[20];

    float *xfu, *h1, *xff;
    unsigned *gqkv, *tqkv, *gat, *tat, *comb, *fush, *h1b, *ffh, *wbf;
    cudaGetSymbolAddress((void**)&gqkv, g_qkv_buf);
    cudaGetSymbolAddress((void**)&tqkv, t_qkv_buf);
    cudaGetSymbolAddress((void**)&gat,  gat_buf);
    cudaGetSymbolAddress((void**)&tat,  tat_buf);
    cudaGetSymbolAddress((void**)&comb, comb_buf);
    cudaGetSymbolAddress((void**)&fush, fush_buf);
    cudaGetSymbolAddress((void**)&xfu,  xfused_buf);
    cudaGetSymbolAddress((void**)&h1,   h1_buf);
    cudaGetSymbolAddress((void**)&h1b,  h1b_buf);
    cudaGetSymbolAddress((void**)&ffh,  ffnh_buf);
    cudaGetSymbolAddress((void**)&xff,  xffn_buf);
    cudaGetSymbolAddress((void**)&wbf,  wbf_buf);

    const __nv_bfloat16* wb = (const __nv_bfloat16*)wbf;

    // 0) weights fp32 -> bf16 (once per launch; graph-capturable kernel)
    convert_weights_kernel<<<1152, 256>>>(g_in_w, t_in_w, g_out_w, t_out_w,
                                          fus_w1, fus_w2, ffn_w1, ffn_w2, wbf);

    // 1) merged QKV projections (A fp32, C bf16)
    tgemm_kernel<false, false, true><<<dim3(12, 64), 256, GSMEM_BYTES>>>(
        x, wb + WOFF_GIN, g_in_b, gqkv,
        x, wb + WOFF_TIN, t_in_b, tqkv, 6, 256, 768);

    // 2) attention (bf16 in, bf16 out)
    flash_global_attn<<<dim3(SEQ / 64, 8, 4), 128>>>(gqkv, gat);
    local_attn_kernel<<<NTOK, 128>>>((const __nv_bfloat16*)tqkv, (__nv_bfloat16*)tat);

    // 3) merged output projections -> comb (bf16), [global | local]
    tgemm_kernel<false, true, true><<<dim3(4, 64), 256, GSMEM_BYTES>>>(
        gat, wb + WOFF_GOUT, g_out_b, comb,
        tat, wb + WOFF_TOUT, t_out_b, comb + 128, 2, 256, 512);

    // 4) fusion MLP
    tgemm_kernel<true, true, true><<<dim3(4, 64), 256, GSMEM_BYTES>>>(
        comb, wb + WOFF_FUS1, fus_b1, fush,
        comb, wb + WOFF_FUS1, fus_b1, fush, 4, 512, 512);
    tgemm_kernel<false, true, false><<<dim3(2, 64), 256, GSMEM_BYTES>>>(
        fush, wb + WOFF_FUS2, fus_b2, xfu,
        fush, wb + WOFF_FUS2, fus_b2, xfu, 2, 512, 256);

    // 5) residual + LN (fp32 out + bf16 twin)
    add_ln_kernel<true><<<NTOK, 256>>>(x, xfu, gn_g, gn_b, h1, h1b);

    // 6) FFN
    tgemm_kernel<true, true, true><<<dim3(4, 64), 256, GSMEM_BYTES>>>(
        h1b, wb + WOFF_FFN1, ffn_b1, ffh,
        h1b, wb + WOFF_FFN1, ffn_b1, ffh, 4, 256, 512);
    tgemm_kernel<false, true, false><<<dim3(2, 64), 256, GSMEM_BYTES>>>(
        ffh, wb + WOFF_FFN2, ffn_b2, xff,
        ffh, wb + WOFF_FFN2, ffn_b2, xff, 2, 512, 256);

    // 7) final residual + LN -> output (fp32)
    add_ln_kernel<false><<<NTOK, 256>>>(h1, xff, fn_g, fn_b, (float*)d_out, nullptr);
}

// round 17
// speedup vs baseline: 5.0426x; 1.0229x over previous
#include <cuda_runtime.h>
#include <cuda_bf16.h>
#include <math.h>

#define NTOK 8192
#define SEQ 2048

// ---------------- scratch (static device globals; no allocation) ----------------
__device__ unsigned xb_buf[NTOK * 128];     // x as bf16x2 (256 bf16/row)
__device__ unsigned g_qkv_buf[NTOK * 384];  // bf16x2 (768 bf16/row)
__device__ unsigned t_qkv_buf[NTOK * 384];  // bf16x2
__device__ unsigned gat_buf[NTOK * 128];    // bf16x2
__device__ unsigned tat_buf[NTOK * 128];    // bf16x2
__device__ unsigned comb_buf[NTOK * 256];   // bf16x2 (512 bf16/row)
__device__ unsigned fush_buf[NTOK * 256];   // bf16x2
__device__ float    xfused_buf[NTOK * 256];
__device__ float    h1_buf[NTOK * 256];
__device__ unsigned h1b_buf[NTOK * 128];    // bf16x2 copy of h1
__device__ unsigned ffnh_buf[NTOK * 256];   // bf16x2
__device__ float    xffn_buf[NTOK * 256];
__device__ unsigned wbf_buf[589824];        // all weights as bf16x2

// weight offsets (in bf16 elements) inside wbf_buf
#define WOFF_GIN   0
#define WOFF_TIN   196608
#define WOFF_GOUT  393216
#define WOFF_TOUT  458752
#define WOFF_FUS1  524288
#define WOFF_FUS2  786432
#define WOFF_FFN1  917504
#define WOFF_FFN2  1048576
#define W_F4_UNITS 294912   // weight float4 units
#define X_F4_UNITS 524288   // x float4 units (8192*256/4)

// ---------------- helpers ---------------------------------------------------------
__device__ __forceinline__ unsigned pack_bf16(float lo, float hi) {
    unsigned r;
    asm("cvt.rn.bf16x2.f32 %0, %1, %2;" : "=r"(r) : "f"(hi), "f"(lo));
    return r;
}
__device__ __forceinline__ void mma_bf16(float* d, const unsigned* a, const unsigned* b,
                                         const float* c) {
    asm("mma.sync.aligned.m16n8k16.row.col.f32.bf16.bf16.f32 "
        "{%0,%1,%2,%3},{%4,%5,%6,%7},{%8,%9},{%10,%11,%12,%13};"
        : "=f"(d[0]), "=f"(d[1]), "=f"(d[2]), "=f"(d[3])
        : "r"(a[0]), "r"(a[1]), "r"(a[2]), "r"(a[3]),
          "r"(b[0]), "r"(b[1]),
          "f"(c[0]), "f"(c[1]), "f"(c[2]), "f"(c[3]));
}
__device__ __forceinline__ void ldmatrix_x4_trans(unsigned& r0, unsigned& r1,
                                                  unsigned& r2, unsigned& r3,
                                                  unsigned saddr) {
    asm volatile("ldmatrix.sync.aligned.m8n8.x4.trans.shared.b16 {%0,%1,%2,%3}, [%4];"
                 : "=r"(r0), "=r"(r1), "=r"(r2), "=r"(r3) : "r"(saddr));
}
__device__ __forceinline__ void cp_async16(void* smem, const void* gptr) {
    unsigned saddr = (unsigned)__cvta_generic_to_shared(smem);
    asm volatile("cp.async.ca.shared.global [%0], [%1], 16;" :: "r"(saddr), "l"(gptr));
}
#define CP_COMMIT()  asm volatile("cp.async.commit_group;")
#define CP_WAIT0()   asm volatile("cp.async.wait_group 0;")

// ---------------- fp32 -> bf16 conversion (weights + x) ---------------------------
__global__ void __launch_bounds__(256)
convert_weights_kernel(const float* __restrict__ s0, const float* __restrict__ s1,
                       const float* __restrict__ s2, const float* __restrict__ s3,
                       const float* __restrict__ s4, const float* __restrict__ s5,
                       const float* __restrict__ s6, const float* __restrict__ s7,
                       const float* __restrict__ sx,
                       unsigned* __restrict__ dst, unsigned* __restrict__ dstx)
{
    const int i4 = blockIdx.x * 256 + threadIdx.x;
    if (i4 >= W_F4_UNITS) {
        const int xi4 = i4 - W_F4_UNITS;
        if (xi4 < X_F4_UNITS) {
            float4 v = *reinterpret_cast<const float4*>(sx + xi4 * 4);
            uint2 o; o.x = pack_bf16(v.x, v.y); o.y = pack_bf16(v.z, v.w);
            *reinterpret_cast<uint2*>(dstx + xi4 * 2) = o;
        }
        return;
    }
    const int e = i4 * 4;
    const float* src; int base;
    if      (e < 196608)  { src = s0; base = 0; }
    else if (e < 393216)  { src = s1; base = 196608; }
    else if (e < 458752)  { src = s2; base = 393216; }
    else if (e < 524288)  { src = s3; base = 458752; }
    else if (e < 786432)  { src = s4; base = 524288; }
    else if (e < 917504)  { src = s5; base = 786432; }
    else if (e < 1048576) { src = s6; base = 917504; }
    else                  { src = s7; base = 1048576; }
    float4 v = *reinterpret_cast<const float4*>(src + (e - base));
    uint2 o; o.x = pack_bf16(v.x, v.y); o.y = pack_bf16(v.z, v.w);
    *reinterpret_cast<uint2*>(dst + i4 * 2) = o;
}

// ---------------- BF16 dual-source cp.async GEMM (single-sync pipeline) ----------
// C[M,N] = A[M,K] @ W[N,K]^T + bias (opt SiLU). A,W bf16 via cp.async.
// BM=BN=128, BK=32, 256 threads, 8 warps x (32x64) m16n8k16.
// Loop: wait0(tile kt arrived) -> sync(publish + free other stage) ->
//       issue kt+1 -> commit -> compute kt.  ONE barrier per K-tile.
#define SMH 20
#define GT (128 * SMH)
#define GSMEM_BYTES (4 * GT * 4)   // 40960 B
template <bool SILU, bool CBF16>
__global__ void __launch_bounds__(256, 2)
tgemm_kernel(const __nv_bfloat16* __restrict__ A1, const __nv_bfloat16* __restrict__ W1,
             const float* __restrict__ b1, void* __restrict__ C1_,
             const __nv_bfloat16* __restrict__ A2, const __nv_bfloat16* __restrict__ W2,
             const float* __restrict__ b2, void* __restrict__ C2_,
             int split, int K, int ldc)
{
    extern __shared__ unsigned sm[];
    unsigned* As = sm;
    unsigned* Bs = sm + 2 * GT;

    const int tid = threadIdx.x;
    const int bm = blockIdx.y * 128;

    const __nv_bfloat16 *A, *W; const float* bias; void* C_;
    int bn;
    if ((int)blockIdx.x < split) { A = A1; W = W1; bias = b1; C_ = C1_; bn = blockIdx.x * 128; }
    else { A = A2; W = W2; bias = b2; C_ = C2_; bn = (blockIdx.x - split) * 128; }

    const int warp = tid >> 5, lane = tid & 31;
    const int wm = (warp & 3) * 32, wn = (warp >> 2) * 64;
    const int g = lane >> 2, t = lane & 3;
    const int lrow = tid >> 1, lhalf = tid & 1;

    const __nv_bfloat16* wrow = W + (size_t)(bn + lrow) * K + lhalf * 16;
    const __nv_bfloat16* arow = A + (size_t)(bm + lrow) * K + lhalf * 16;

    unsigned* asw = &As[lrow * SMH + lhalf * 8];
    unsigned* bsw = &Bs[lrow * SMH + lhalf * 8];

    float acc[2][8][4];
#pragma unroll
    for (int mt = 0; mt < 2; mt++)
#pragma unroll
        for (int nt = 0; nt < 8; nt++)
#pragma unroll
            for (int r = 0; r < 4; r++) acc[mt][nt][r] = 0.f;

    const int ntiles = K >> 5;

    // prologue: issue tile 0 into stage 0
    cp_async16(asw, arow);  cp_async16(asw + 4, arow + 8);
    cp_async16(bsw, wrow);  cp_async16(bsw + 4, wrow + 8);
    CP_COMMIT();

    for (int kt = 0; kt < ntiles; kt++) {
        const int st = kt & 1;
        CP_WAIT0();        // tile kt arrived (only group possibly pending)
        __syncthreads();   // publish tile kt; all warps done reading other stage

        if (kt + 1 < ntiles) {
            const int off = (kt + 1) * 32;
            const int so = ((kt + 1) & 1) * GT;
            cp_async16(asw + so, arow + off);
            cp_async16(asw + so + 4, arow + off + 8);
            cp_async16(bsw + so, wrow + off);
            cp_async16(bsw + so + 4, wrow + off + 8);
        }
        CP_COMMIT();

        const unsigned* as = As + st * GT;
        const unsigned* bs = Bs + st * GT;
#pragma unroll
        for (int s = 0; s < 2; s++) {
            const int kk = s * 8;
            unsigned af[2][4];
#pragma unroll
            for (int mt = 0; mt < 2; mt++) {
                const int r0 = wm + mt * 16 + g;
                af[mt][0] = as[(r0    ) * SMH + kk + t];
                af[mt][1] = as[(r0 + 8) * SMH + kk + t];
                af[mt][2] = as[(r0    ) * SMH + kk + t + 4];
                af[mt][3] = as[(r0 + 8) * SMH + kk + t + 4];
            }
            unsigned bf[8][2];
#pragma unroll
            for (int nt = 0; nt < 8; nt++) {
                const int n0 = wn + nt * 8 + g;
                bf[nt][0] = bs[n0 * SMH + kk + t];
                bf[nt][1] = bs[n0 * SMH + kk + t + 4];
            }
#pragma unroll
            for (int mt = 0; mt < 2; mt++)
#pragma unroll
                for (int nt = 0; nt < 8; nt++)
                    mma_bf16(acc[mt][nt], af[mt], bf[nt], acc[mt][nt]);
        }
    }

    // epilogue: bias (+SiLU)
#pragma unroll
    for (int mt = 0; mt < 2; mt++) {
#pragma unroll
        for (int nt = 0; nt < 8; nt++) {
            const int col = bn + wn + nt * 8 + 2 * t;
            const float b0 = bias[col], bb1 = bias[col + 1];
#pragma unroll
            for (int h = 0; h < 2; h++) {
                const int row = bm + wm + mt * 16 + g + h * 8;
                float v0 = acc[mt][nt][2 * h] + b0;
                float v1 = acc[mt][nt][2 * h + 1] + bb1;
                if (SILU) {
                    v0 = v0 / (1.f + __expf(-v0));
                    v1 = v1 / (1.f + __expf(-v1));
                }
                if (CBF16) {
                    ((unsigned*)C_)[((size_t)row * ldc + col) >> 1] = pack_bf16(v0, v1);
                } else {
                    float2 o; o.x = v0; o.y = v1;
                    *reinterpret_cast<float2*>((float*)C_ + (size_t)row * ldc + col) = o;
                }
            }
        }
    }
}

// ---------------- combined attention: flash global (blocks 0..1023) + local -----
// flash: one block = (b,h) x 64 queries, 4 warps x 16 rows, 64-key tiles.
// local: blocks 1024..9215, one block per token, warp per head (hd=64, W=5).
#define KSR 20   // u32 (bf16-pair) stride per K row
#define VSR 40   // bf16 stride per V row
#define FLASH_BLOCKS 1024
__global__ void __launch_bounds__(128)
attn_kernel(const unsigned* __restrict__ gqkv, unsigned* __restrict__ gat,
            const __nv_bfloat16* __restrict__ tqkv, __nv_bfloat16* __restrict__ tat)
{
    __shared__ unsigned Ks[64 * KSR];
    __shared__ unsigned short Vs[64 * VSR];

    const int tid = threadIdx.x;
    const int lane = tid & 31;

    if (blockIdx.x < FLASH_BLOCKS) {
        // ---------------- flash global attention ----------------
        const int bx = blockIdx.x;
        const int qt = bx & 31;
        const int h = (bx >> 5) & 7;
        const int b = bx >> 8;
        const int warp = tid >> 5;
        const int g = lane >> 2;
        const int t = lane & 3;
        const int q0 = qt * 64;
        const int wq = warp * 16;

        const float scale = 0.17677669529663687f;  // 1/sqrt(32)
        unsigned qf[2][4];
        {
            const size_t r0 = (size_t)(b * SEQ + q0 + wq + g) * 384 + h * 16;
            const size_t r1 = r0 + 8 * 384;
#pragma unroll
            for (int ks = 0; ks < 2; ks++) {
                const int c = ks * 8 + t;
                unsigned u00 = gqkv[r0 + c],     u10 = gqkv[r1 + c];
                unsigned u01 = gqkv[r0 + c + 4], u11 = gqkv[r1 + c + 4];
                qf[ks][0] = pack_bf16(__uint_as_float(u00 << 16) * scale,
                                      __uint_as_float(u00 & 0xffff0000u) * scale);
                qf[ks][1] = pack_bf16(__uint_as_float(u10 << 16) * scale,
                                      __uint_as_float(u10 & 0xffff0000u) * scale);
                qf[ks][2] = pack_bf16(__uint_as_float(u01 << 16) * scale,
                                      __uint_as_float(u01 & 0xffff0000u) * scale);
                qf[ks][3] = pack_bf16(__uint_as_float(u11 << 16) * scale,
                                      __uint_as_float(u11 & 0xffff0000u) * scale);
            }
        }

        float o[4][4];
#pragma unroll
        for (int nt = 0; nt < 4; nt++)
#pragma unroll
            for (int r = 0; r < 4; r++) o[nt][r] = 0.f;
        float m0 = -1e30f, m1 = -1e30f, l0 = 0.f, l1 = 0.f;

        const int lrow = tid >> 1;
        const int lhalf = tid & 1;
        const int vkey = lane & 15;
        const int vdimb = (lane >> 4) * 8;

        for (int kt = 0; kt < SEQ; kt += 64) {
            __syncthreads();
            {
                const unsigned* kp = gqkv + (size_t)(b * SEQ + kt + lrow) * 384 + 128 + h * 16 + lhalf * 8;
                cp_async16(&Ks[lrow * KSR + lhalf * 8], kp);
                cp_async16(&Ks[lrow * KSR + lhalf * 8 + 4], kp + 4);
                const unsigned* vp = kp + 128;
                unsigned* vd = reinterpret_cast<unsigned*>(&Vs[lrow * VSR + lhalf * 16]);
                cp_async16(vd, vp);
                cp_async16(vd + 4, vp + 4);
            }
            CP_COMMIT();
            CP_WAIT0();
            __syncthreads();

            float s[8][4];
#pragma unroll
            for (int nt = 0; nt < 8; nt++)
#pragma unroll
                for (int r = 0; r < 4; r++) s[nt][r] = 0.f;
#pragma unroll
            for (int ks = 0; ks < 2; ks++) {
                const int kk = ks * 8;
#pragma unroll
                for (int nt = 0; nt < 8; nt++) {
                    unsigned bf[2];
                    const unsigned* kb = &Ks[(nt * 8 + g) * KSR + kk + t];
                    bf[0] = kb[0];
                    bf[1] = kb[4];
                    mma_bf16(s[nt], qf[ks], bf, s[nt]);
                }
            }

            float r0 = s[0][0], r1 = s[0][2];
#pragma unroll
            for (int nt = 0; nt < 8; nt++) {
                r0 = fmaxf(r0, fmaxf(s[nt][0], s[nt][1]));
                r1 = fmaxf(r1, fmaxf(s[nt][2], s[nt][3]));
            }
            r0 = fmaxf(r0, __shfl_xor_sync(0xffffffffu, r0, 1));
            r0 = fmaxf(r0, __shfl_xor_sync(0xffffffffu, r0, 2));
            r1 = fmaxf(r1, __shfl_xor_sync(0xffffffffu, r1, 1));
            r1 = fmaxf(r1, __shfl_xor_sync(0xffffffffu, r1, 2));

            const float m0n = fmaxf(m0, r0);
            const float m1n = fmaxf(m1, r1);
            const float c0 = __expf(m0 - m0n);
            const float c1 = __expf(m1 - m1n);

            float sum0 = 0.f, sum1 = 0.f;
#pragma unroll
            for (int nt = 0; nt < 8; nt++) {
                s[nt][0] = __expf(s[nt][0] - m0n);
                s[nt][1] = __expf(s[nt][1] - m0n);
                s[nt][2] = __expf(s[nt][2] - m1n);
                s[nt][3] = __expf(s[nt][3] - m1n);
                sum0 += s[nt][0] + s[nt][1];
                sum1 += s[nt][2] + s[nt][3];
            }
            sum0 += __shfl_xor_sync(0xffffffffu, sum0, 1);
            sum0 += __shfl_xor_sync(0xffffffffu, sum0, 2);
            sum1 += __shfl_xor_sync(0xffffffffu, sum1, 1);
            sum1 += __shfl_xor_sync(0xffffffffu, sum1, 2);
            l0 = l0 * c0 + sum0;
            l1 = l1 * c1 + sum1;
            m0 = m0n; m1 = m1n;

#pragma unroll
            for (int nt = 0; nt < 4; nt++) {
                o[nt][0] *= c0; o[nt][1] *= c0;
                o[nt][2] *= c1; o[nt][3] *= c1;
            }

#pragma unroll
            for (int ks = 0; ks < 4; ks++) {
                unsigned af[4];
                af[0] = pack_bf16(s[2 * ks][0],     s[2 * ks][1]);
                af[1] = pack_bf16(s[2 * ks][2],     s[2 * ks][3]);
                af[2] = pack_bf16(s[2 * ks + 1][0], s[2 * ks + 1][1]);
                af[3] = pack_bf16(s[2 * ks + 1][2], s[2 * ks + 1][3]);

                unsigned vaddr = (unsigned)__cvta_generic_to_shared(
                    &Vs[(ks * 16 + vkey) * VSR + vdimb]);
                unsigned v0, v1, v2, v3, v4, v5, v6, v7;
                ldmatrix_x4_trans(v0, v1, v2, v3, vaddr);
                ldmatrix_x4_trans(v4, v5, v6, v7, vaddr + 32);

                unsigned bf[2];
                bf[0] = v0; bf[1] = v1; mma_bf16(o[0], af, bf, o[0]);
                bf[0] = v2; bf[1] = v3; mma_bf16(o[1], af, bf, o[1]);
                bf[0] = v4; bf[1] = v5; mma_bf16(o[2], af, bf, o[2]);
                bf[0] = v6; bf[1] = v7; mma_bf16(o[3], af, bf, o[3]);
            }
        }

        const float inv0 = 1.f / l0;
        const float inv1 = 1.f / l1;
        unsigned* op = gat + (size_t)(b * SEQ) * 128 + h * 16;
        const int row0 = q0 + wq + g;
#pragma unroll
        for (int nt = 0; nt < 4; nt++) {
            const int cu = nt * 4 + t;
            op[(size_t)(row0    ) * 128 + cu] = pack_bf16(o[nt][0] * inv0, o[nt][1] * inv0);
            op[(size_t)(row0 + 8) * 128 + cu] = pack_bf16(o[nt][2] * inv1, o[nt][3] * inv1);
        }
    } else {
        // ---------------- local attention ----------------
        const int n = blockIdx.x - FLASH_BLOCKS;
        const int b = n / SEQ;
        const int s = n % SEQ;
        const int h = tid >> 5;

        const size_t qb = (size_t)n * 768 + h * 64;
        const float q0 = __bfloat162float(tqkv[qb + lane]);
        const float q1 = __bfloat162float(tqkv[qb + 32 + lane]);

        float sc[5];
#pragma unroll
        for (int wo = 0; wo < 5; wo++) {
            const int j = s + wo - 2;
            if (j >= 0 && j < SEQ) {
                const size_t kb = (size_t)(b * SEQ + j) * 768 + 256 + h * 64;
                float part = q0 * __bfloat162float(tqkv[kb + lane])
                           + q1 * __bfloat162float(tqkv[kb + 32 + lane]);
#pragma unroll
                for (int o = 16; o > 0; o >>= 1) part += __shfl_xor_sync(0xffffffffu, part, o);
                sc[wo] = part * 0.125f;
            } else {
                sc[wo] = -1e30f;
            }
        }
        float mx = sc[0];
#pragma unroll
        for (int wo = 1; wo < 5; wo++) mx = fmaxf(mx, sc[wo]);
        float p[5], lsum = 0.f;
#pragma unroll
        for (int wo = 0; wo < 5; wo++) {
            p[wo] = (sc[wo] > -1e29f) ? __expf(sc[wo] - mx) : 0.f;
            lsum += p[wo];
        }
        float o0 = 0.f, o1 = 0.f;
#pragma unroll
        for (int wo = 0; wo < 5; wo++) {
            const int j = s + wo - 2;
            if (j >= 0 && j < SEQ) {
                const size_t vb = (size_t)(b * SEQ + j) * 768 + 512 + h * 64;
                o0 += p[wo] * __bfloat162float(tqkv[vb + lane]);
                o1 += p[wo] * __bfloat162float(tqkv[vb + 32 + lane]);
            }
        }
        const float inv = 1.f / lsum;
        tat[(size_t)n * 256 + h * 64 + lane]      = __float2bfloat16(o0 * inv);
        tat[(size_t)n * 256 + h * 64 + 32 + lane] = __float2bfloat16(o1 * inv);
    }
}

// ---------------- residual add + LayerNorm (optional bf16 twin) ------------------
template <bool WB16>
__global__ void __launch_bounds__(256)
add_ln_kernel(const float* __restrict__ x, const float* __restrict__ dx,
              const float* __restrict__ g, const float* __restrict__ bb,
              float* __restrict__ out, unsigned* __restrict__ outb)
{
    const int n = blockIdx.x;
    const int d = threadIdx.x;
    const float v = x[(size_t)n * 256 + d] + dx[(size_t)n * 256 + d];
    float s1 = v, s2 = v * v;
#pragma unroll
    for (int o = 16; o > 0; o >>= 1) {
        s1 += __shfl_xor_sync(0xffffffffu, s1, o);
        s2 += __shfl_xor_sync(0xffffffffu, s2, o);
    }
    __shared__ float r1[8], r2[8];
    const int wid = d >> 5, lane = d & 31;
    if (lane == 0) { r1[wid] = s1; r2[wid] = s2; }
    __syncthreads();
    if (wid == 0) {
        float a = (lane < 8) ? r1[lane] : 0.f;
        float c = (lane < 8) ? r2[lane] : 0.f;
#pragma unroll
        for (int o = 4; o > 0; o >>= 1) {
            a += __shfl_xor_sync(0xffffffffu, a, o);
            c += __shfl_xor_sync(0xffffffffu, c, o);
        }
        if (lane == 0) { r1[0] = a; r2[0] = c; }
    }
    __syncthreads();
    const float mu = r1[0] * (1.f / 256.f);
    const float var = r2[0] * (1.f / 256.f) - mu * mu;
    const float vn = (v - mu) * rsqrtf(var + 1e-5f) * g[d] + bb[d];
    out[(size_t)n * 256 + d] = vn;
    if (WB16) {
        const float hi = __shfl_down_sync(0xffffffffu, vn, 1);
        if ((d & 1) == 0) outb[(size_t)n * 128 + (d >> 1)] = pack_bf16(vn, hi);
    }
}

// ---------------- launch ---------------------------------------------------------
extern "C" void kernel_launch(void* const* d_in, const int* in_sizes, int n_in,
                              void* d_out, int out_size)
{
    const float* x      = (const float*)d_in[0];
    const float* g_in_w = (const float*)d_in[1];
    const float* g_in_b = (const float*)d_in[2];
    const float* g_out_w= (const float*)d_in[3];
    const float* g_out_b= (const float*)d_in[4];
    const float* t_in_w = (const float*)d_in[5];
    const float* t_in_b = (const float*)d_in[6];
    const float* t_out_w= (const float*)d_in[7];
    const float* t_out_b= (const float*)d_in[8];
    const float* fus_w1 = (const float*)d_in[9];
    const float* fus_b1 = (const float*)d_in[10];
    const float* fus_w2 = (const float*)d_in[11];
    const float* fus_b2 = (const float*)d_in[12];
    const float* ffn_w1 = (const float*)d_in[13];
    const float* ffn_b1 = (const float*)d_in[14];
    const float* ffn_w2 = (const float*)d_in[15];
    const float* ffn_b2 = (const float*)d_in[16];
    const float* gn_g   = (const float*)d_in[17];
    const float* gn_b   = (const float*)d_in[18];
    const float* fn_g   = (const float*)d_in[19];
    const float* fn_b   = (const float*)d_in[20];

    float *xfu, *h1, *xff;
    unsigned *xb, *gqkv, *tqkv, *gat, *tat, *comb, *fush, *h1b, *ffh, *wbf;
    cudaGetSymbolAddress((void**)&xb,   xb_buf);
    cudaGetSymbolAddress((void**)&gqkv, g_qkv_buf);
    cudaGetSymbolAddress((void**)&tqkv, t_qkv_buf);
    cudaGetSymbolAddress((void**)&gat,  gat_buf);
    cudaGetSymbolAddress((void**)&tat,  tat_buf);
    cudaGetSymbolAddress((void**)&comb, comb_buf);
    cudaGetSymbolAddress((void**)&fush, fush_buf);
    cudaGetSymbolAddress((void**)&xfu,  xfused_buf);
    cudaGetSymbolAddress((void**)&h1,   h1_buf);
    cudaGetSymbolAddress((void**)&h1b,  h1b_buf);
    cudaGetSymbolAddress((void**)&ffh,  ffnh_buf);
    cudaGetSymbolAddress((void**)&xff,  xffn_buf);
    cudaGetSymbolAddress((void**)&wbf,  wbf_buf);

    const __nv_bfloat16* wb = (const __nv_bfloat16*)wbf;
    const __nv_bfloat16* xbb = (const __nv_bfloat16*)xb;

    // 0) weights + x fp32 -> bf16
    convert_weights_kernel<<<3200, 256>>>(g_in_w, t_in_w, g_out_w, t_out_w,
                                          fus_w1, fus_w2, ffn_w1, ffn_w2, x,
                                          wbf, xb);

    // 1) merged QKV projections (bf16 in, bf16 out)
    tgemm_kernel<false, true><<<dim3(12, 64), 256, GSMEM_BYTES>>>(
        xbb, wb + WOFF_GIN, g_in_b, gqkv,
        xbb, wb + WOFF_TIN, t_in_b, tqkv, 6, 256, 768);

    // 2) combined attention (flash global + local in one launch)
    attn_kernel<<<FLASH_BLOCKS + NTOK, 128>>>(gqkv, gat, (const __nv_bfloat16*)tqkv,
                                              (__nv_bfloat16*)tat);

    // 3) merged output projections -> comb (bf16), [global | local]
    tgemm_kernel<false, true><<<dim3(4, 64), 256, GSMEM_BYTES>>>(
        (const __nv_bfloat16*)gat, wb + WOFF_GOUT, g_out_b, comb,
        (const __nv_bfloat16*)tat, wb + WOFF_TOUT, t_out_b, comb + 128, 2, 256, 512);

    // 4) fusion MLP
    tgemm_kernel<true, true><<<dim3(4, 64), 256, GSMEM_BYTES>>>(
        (const __nv_bfloat16*)comb, wb + WOFF_FUS1, fus_b1, fush,
        (const __nv_bfloat16*)comb, wb + WOFF_FUS1, fus_b1, fush, 4, 512, 512);
    tgemm_kernel<false, false><<<dim3(2, 64), 256, GSMEM_BYTES>>>(
        (const __nv_bfloat16*)fush, wb + WOFF_FUS2, fus_b2, xfu,
        (const __nv_bfloat16*)fush, wb + WOFF_FUS2, fus_b2, xfu, 2, 512, 256);

    // 5) residual + LN (fp32 out + bf16 twin)
    add_ln_kernel<true><<<NTOK, 256>>>(x, xfu, gn_g, gn_b, h1, h1b);

    // 6) FFN
    tgemm_kernel<true, true><<<dim3(4, 64), 256, GSMEM_BYTES>>>(
        (const __nv_bfloat16*)h1b, wb + WOFF_FFN1, ffn_b1, ffh,
        (const __nv_bfloat16*)h1b, wb + WOFF_FFN1, ffn_b1, ffh, 4, 256, 512);
    tgemm_kernel<false, false><<<dim3(2, 64), 256, GSMEM_BYTES>>>(
        (const __nv_bfloat16*)ffh, wb + WOFF_FFN2, ffn_b2, xff,
        (const __nv_bfloat16*)ffh, wb + WOFF_FFN2, ffn_b2, xff, 2, 512, 256);

    // 7) final residual + LN -> output (fp32)
    add_ln_kernel<false><<<NTOK, 256>>>(h1, xff, fn_g, fn_b, (float*)d_out, nullptr);
}